// round 5
// baseline (speedup 1.0000x reference)
#include <cuda_runtime.h>
#include <cuda_bf16.h>
#include <math.h>

#define NB 148
#define NT 512
#define KY 32000
typedef __nv_bfloat16 bf;

// ---------------- device scratch ----------------
__device__ __align__(128) bf g_xh[4096*512], g_xl[4096*512];
__device__ __align__(128) bf g_Wph[512*1024], g_Wpl[512*1024];
__device__ __align__(128) bf g_Uph[512*512], g_Upl[512*512];
__device__ __align__(128) bf g_Wihh[3072*512], g_Wihl[3072*512];
__device__ __align__(128) bf g_Whhh[3072*1024], g_Whhl[3072*1024];
__device__ __align__(128) bf g_Uoph[1024*1024], g_Uopl[1024*1024];
__device__ __align__(128) bf g_Voph[1024*512], g_Vopl[1024*512];
__device__ __align__(128) bf g_Coph[1024*512], g_Copl[1024*512];
__device__ __align__(128) bf g_Woph[(size_t)KY*512], g_Wopl[(size_t)KY*512];
__device__ __align__(128) bf g_Eyph[(size_t)512*KY], g_Eypl[(size_t)512*KY];
__device__ __align__(128) bf g_sh[2][64*1024], g_sl[2][64*1024];
__device__ __align__(128) bf g_ctxh[64*512], g_ctxl[64*512];
__device__ __align__(128) bf g_yEh[64*512], g_yEl[64*512];
__device__ __align__(128) bf g_tmh[64*512], g_tml[64*512];
__device__ __align__(128) bf g_evh[(size_t)64*KY], g_evl[(size_t)64*KY];
__device__ __align__(128) float g_sf[2][64*1024];
__device__ __align__(128) float g_Uh[4096*512];
__device__ __align__(128) float g_wsbp[2][64*512];
__device__ __align__(128) float g_e[64*64];
__device__ __align__(128) float g_gip[2][64*3072];
__device__ __align__(128) float g_ghp[4][64*3072];
__device__ __align__(128) float g_tp[8][64*1024];
__device__ __align__(128) float g_yep[50][64*512];
__device__ __align__(128) float g_Zt[64*128];
__device__ __align__(128) float g_Zinv[64];

// ---------------- grid barrier ----------------
__device__ unsigned g_cnt = 0;
__device__ volatile unsigned g_gen = 0;

__device__ __forceinline__ void gsync() {
    __syncthreads();
    if (threadIdx.x == 0) {
        unsigned gen = g_gen;
        __threadfence();
        if (atomicAdd(&g_cnt, 1u) == NB - 1u) {
            atomicExch(&g_cnt, 0u);
            __threadfence();
            g_gen = gen + 1u;
        } else {
            while (g_gen == gen) __nanosleep(64);
            __threadfence();
        }
    }
    __syncthreads();
}

__device__ __forceinline__ float tanh_fast(float x) {
    float y; asm("tanh.approx.f32 %0, %1;" : "=f"(y) : "f"(x)); return y;
}

__device__ __forceinline__ void csplit(float x, bf& h, bf& l) {
    h = __float2bfloat16(x);
    l = __float2bfloat16(x - __bfloat162float(h));
}

__device__ __forceinline__ void cpa16(bf* s, const bf* g) {
    unsigned sa = (unsigned)__cvta_generic_to_shared(s);
    asm volatile("cp.async.cg.shared.global [%0], [%1], 16;" :: "r"(sa), "l"(g));
}

#define MMA(d, a0, a1, a2, a3, b0, b1)                                        \
    asm volatile("mma.sync.aligned.m16n8k16.row.col.f32.bf16.bf16.f32 "       \
                 "{%0,%1,%2,%3}, {%4,%5,%6,%7}, {%8,%9}, {%0,%1,%2,%3};"      \
                 : "+f"(d[0]), "+f"(d[1]), "+f"(d[2]), "+f"(d[3])             \
                 : "r"(a0), "r"(a1), "r"(a2), "r"(a3), "r"(b0), "r"(b1))

// ------- core: acc = A[0:64][k0:k0+kc] * B^T (3-term bf16 split) -------
// cp.async 4-stage ring, 32-k stages, padded smem (row stride 40 bf16).
// smem: sA[4][2][64*40] then sB[4][2][NTILE*40]. kc % 32 == 0.
template<int NTILE>
__device__ __noinline__ void mma_core(
    const bf* __restrict__ Ah, const bf* __restrict__ Al, int lda,
    const bf* __restrict__ Bh, const bf* __restrict__ Bl, int ldb,
    int n0, int k0, int kc, bf* __restrict__ sm, float* acc) {
    constexpr int AST = 5120;
    constexpr int BST = NTILE * 80;
    constexpr int NJ  = NTILE / 32;
    bf* sA = sm;
    bf* sB = sm + 4 * AST;
    const int tid = threadIdx.x;
    const int w = tid >> 5, lane = tid & 31;
    const int mr = (w & 3) << 4;
    const int nc = (w >> 2) * (NTILE / 4);
    const int fr = lane >> 2, fc = (lane & 3) << 1;
    const int aoff = (mr + fr) * 40 + fc;
    const int boff = (nc + fr) * 40 + fc;
#pragma unroll
    for (int i = 0; i < NJ * 4; i++) acc[i] = 0.f;

    const int ahl = tid >> 8, ar = (tid & 255) >> 2, ac = tid & 3;
    const bf* Ag = (ahl ? Al : Ah) + (size_t)ar * lda + k0 + ac * 8;
    bf* As0 = sA + ahl * 2560 + ar * 40 + ac * 8;

    const int ns = kc >> 5;
#pragma unroll
    for (int s = 0; s < 3; s++) {
        if (s < ns) {
            cpa16(As0 + s * AST, Ag + s * 32);
            for (int q = tid; q < NTILE * 8; q += NT) {
                int row = q >> 3, hl = (q >> 2) & 1, c = q & 3;
                cpa16(sB + s * BST + hl * NTILE * 40 + row * 40 + c * 8,
                      (hl ? Bl : Bh) + (size_t)(n0 + row) * ldb + k0 + s * 32 + c * 8);
            }
        }
        asm volatile("cp.async.commit_group;" ::: "memory");
    }
    for (int s = 0; s < ns; s++) {
        asm volatile("cp.async.wait_group 2;" ::: "memory");
        __syncthreads();
        const int slot = s & 3;
        const bf* sAb = sA + slot * AST;
        const bf* sBb = sB + slot * BST;
#pragma unroll
        for (int half = 0; half < 2; half++) {
            const int ko = half << 4;
            const bf* pah = sAb + aoff + ko;
            unsigned ah0 = *(const unsigned*)(pah);
            unsigned ah1 = *(const unsigned*)(pah + 320);
            unsigned ah2 = *(const unsigned*)(pah + 8);
            unsigned ah3 = *(const unsigned*)(pah + 328);
            const bf* pal = pah + 2560;
            unsigned al0 = *(const unsigned*)(pal);
            unsigned al1 = *(const unsigned*)(pal + 320);
            unsigned al2 = *(const unsigned*)(pal + 8);
            unsigned al3 = *(const unsigned*)(pal + 328);
            const bf* pbh = sBb + boff + ko;
            const bf* pbl = pbh + NTILE * 40;
#pragma unroll
            for (int j = 0; j < NJ; j++) {
                unsigned bh0 = *(const unsigned*)(pbh + j * 320);
                unsigned bh1 = *(const unsigned*)(pbh + j * 320 + 8);
                unsigned bl0 = *(const unsigned*)(pbl + j * 320);
                unsigned bl1 = *(const unsigned*)(pbl + j * 320 + 8);
                float* d = acc + j * 4;
                MMA(d, ah0, ah1, ah2, ah3, bh0, bh1);
                MMA(d, ah0, ah1, ah2, ah3, bl0, bl1);
                MMA(d, al0, al1, al2, al3, bh0, bh1);
            }
        }
        int sn = s + 3;
        if (sn < ns) {
            int sl2 = sn & 3;
            cpa16(As0 + sl2 * AST, Ag + sn * 32);
            for (int q = tid; q < NTILE * 8; q += NT) {
                int row = q >> 3, hl = (q >> 2) & 1, c = q & 3;
                cpa16(sB + sl2 * BST + hl * NTILE * 40 + row * 40 + c * 8,
                      (hl ? Bl : Bh) + (size_t)(n0 + row) * ldb + k0 + sn * 32 + c * 8);
            }
        }
        asm volatile("cp.async.commit_group;" ::: "memory");
    }
    __syncthreads();
}

template<int NTILE>
__device__ __noinline__ void mma_tile(
    const bf* __restrict__ Ah, const bf* __restrict__ Al, int lda,
    const bf* __restrict__ Bh, const bf* __restrict__ Bl, int ldb,
    float* __restrict__ C, int ldc, int n0, int k0, int kc, bf* sm) {
    float acc[NTILE / 8];
    mma_core<NTILE>(Ah, Al, lda, Bh, Bl, ldb, n0, k0, kc, sm, acc);
    const int tid = threadIdx.x;
    const int w = tid >> 5, lane = tid & 31;
    const int mr = (w & 3) << 4;
    const int nc = (w >> 2) * (NTILE / 4);
    const int fr = lane >> 2, fc = (lane & 3) << 1;
#pragma unroll
    for (int j = 0; j < NTILE / 32; j++) {
        int col = n0 + nc + j * 8 + fc;
        float* c0 = C + (size_t)(mr + fr) * ldc + col;
        *(float2*)c0 = make_float2(acc[j*4], acc[j*4+1]);
        *(float2*)(c0 + (size_t)8 * ldc) = make_float2(acc[j*4+2], acc[j*4+3]);
    }
}

// logits 64x256 tile -> exp into g_evh/evl + deterministic row sums g_Zt
__device__ __noinline__ void mma_tile_exp(
    const bf* __restrict__ Ah, const bf* __restrict__ Al,
    const bf* __restrict__ Bh, const bf* __restrict__ Bl,
    int n0, bf* sm) {
    float acc[32];
    mma_core<256>(Ah, Al, 512, Bh, Bl, 512, n0, 0, 512, sm, acc);
    const int tid = threadIdx.x;
    const int w = tid >> 5, lane = tid & 31;
    const int mr = (w & 3) << 4, nc = (w >> 2) << 6;
    const int fr = lane >> 2, fc = (lane & 3) << 1;
    float rs0 = 0.f, rs1 = 0.f;
#pragma unroll
    for (int j = 0; j < 8; j++) {
#pragma unroll
        for (int q = 0; q < 2; q++) {
            int col = n0 + nc + j * 8 + fc + q;
            float e0 = __expf(acc[j*4+q]);
            float e1 = __expf(acc[j*4+2+q]);
            rs0 += e0; rs1 += e1;
            size_t i0 = (size_t)(mr + fr) * KY + col;
            size_t i1 = i0 + (size_t)8 * KY;
            csplit(e0, g_evh[i0], g_evl[i0]);
            csplit(e1, g_evh[i1], g_evl[i1]);
        }
    }
    rs0 += __shfl_xor_sync(~0u, rs0, 1); rs0 += __shfl_xor_sync(~0u, rs0, 2);
    rs1 += __shfl_xor_sync(~0u, rs1, 1); rs1 += __shfl_xor_sync(~0u, rs1, 2);
    float* srs = (float*)sm;
    if ((lane & 3) == 0) { srs[w * 16 + fr] = rs0; srs[w * 16 + 8 + fr] = rs1; }
    __syncthreads();
    if (tid < 64) {
        int mg = tid >> 4, rr = tid & 15;
        float z = srs[mg * 16 + rr] + srs[(4 + mg) * 16 + rr] +
                  srs[(8 + mg) * 16 + rr] + srs[(12 + mg) * 16 + rr];
        g_Zt[tid * 128 + (n0 >> 8)] = z;
    }
    __syncthreads();
}

// attention energy job j (b = j>>2, 16 rows of e per job)
__device__ void energy_job(int j, const float* __restrict__ bvec,
                           const float* __restrict__ v, float* smf) {
    int b = j >> 2, jg = j & 3;
    int tid = threadIdx.x, lane = tid & 31;
    __syncthreads();
    smf[tid] = g_wsbp[0][b * 512 + tid] + g_wsbp[1][b * 512 + tid] + bvec[tid];
    smf[512 + tid] = v[tid];
    __syncthreads();
    int jr = jg * 16 + (tid >> 5);
    const float* uh = g_Uh + (size_t)(b * 64 + jr) * 512;
    float acc = 0.f;
    for (int c = lane; c < 512; c += 32)
        acc += tanh_fast(smf[c] + uh[c]) * smf[512 + c];
#pragma unroll
    for (int o = 16; o > 0; o >>= 1) acc += __shfl_down_sync(~0u, acc, o);
    if (lane == 0) g_e[b * 64 + jr] = acc;
}

__device__ __forceinline__ float block_sum(float v, float* red) {
#pragma unroll
    for (int o = 16; o > 0; o >>= 1) v += __shfl_down_sync(0xffffffffu, v, o);
    if ((threadIdx.x & 31) == 0) red[threadIdx.x >> 5] = v;
    __syncthreads();
    float r = 0.f;
#pragma unroll
    for (int i = 0; i < 16; i++) r += red[i];
    __syncthreads();
    return r;
}

__device__ void convN(const float* __restrict__ in, size_t n,
                      bf* __restrict__ oh, bf* __restrict__ ol, size_t gth, size_t gs) {
    for (size_t i = gth; i < n; i += gs) csplit(in[i], oh[i], ol[i]);
}

__device__ void ttconv(const float* __restrict__ in, int R, int Cc,
                       bf* __restrict__ oh, bf* __restrict__ ol, float* sm) {
    int ntr = R >> 5, ntc = Cc >> 5;
    int tx = threadIdx.x & 31, ty = threadIdx.x >> 5;
    for (int tile = blockIdx.x; tile < ntr * ntc; tile += NB) {
        int tr = tile / ntc, tc = tile % ntc;
        int r0 = tr << 5, c0 = tc << 5;
        __syncthreads();
        sm[ty * 33 + tx]        = in[(size_t)(r0 + ty) * Cc + c0 + tx];
        sm[(ty + 16) * 33 + tx] = in[(size_t)(r0 + ty + 16) * Cc + c0 + tx];
        __syncthreads();
        size_t o0 = (size_t)(c0 + ty) * R + r0 + tx;
        size_t o1 = (size_t)(c0 + ty + 16) * R + r0 + tx;
        csplit(sm[tx * 33 + ty], oh[o0], ol[o0]);
        csplit(sm[tx * 33 + ty + 16], oh[o1], ol[o1]);
    }
}

__global__ __launch_bounds__(NT, 1) void dec_kernel(
    const float* __restrict__ x,    const float* __restrict__ Ey_t,
    const float* __restrict__ W,    const float* __restrict__ U,
    const float* __restrict__ bvec, const float* __restrict__ v,
    const float* __restrict__ W_ih, const float* __restrict__ W_hh,
    const float* __restrict__ b_ih, const float* __restrict__ b_hh,
    const float* __restrict__ U_o,  const float* __restrict__ V_o,
    const float* __restrict__ C_o,  const float* __restrict__ W_o,
    float* __restrict__ out) {
    extern __shared__ __align__(16) char sraw[];
    bf* smb = (bf*)sraw;
    float* smf = (float*)sraw;
    float* s_red = smf + 1024;
    const int tid = threadIdx.x, bid = blockIdx.x;
    const size_t gth = (size_t)bid * NT + tid, GS = (size_t)NB * NT;
    const bf z0 = __float2bfloat16(0.f);

    // ---- prep wave 0: zeros + weight packing ----
    for (size_t i = gth; i < 64 * 1024; i += GS) {
        g_sf[0][i] = 0.f; g_sh[0][i] = z0; g_sl[0][i] = z0;
    }
    for (size_t i = gth; i < 64 * 512; i += GS) { g_yEh[i] = z0; g_yEl[i] = z0; }
    convN(x, (size_t)4096 * 512, g_xh, g_xl, gth, GS);
    convN(W_ih, (size_t)3072 * 512, g_Wihh, g_Wihl, gth, GS);
    convN(W_hh, (size_t)3072 * 1024, g_Whhh, g_Whhl, gth, GS);
    ttconv(W, 1024, 512, g_Wph, g_Wpl, smf);
    ttconv(U, 512, 512, g_Uph, g_Upl, smf);
    ttconv(U_o, 1024, 1024, g_Uoph, g_Uopl, smf);
    ttconv(V_o, 512, 1024, g_Voph, g_Vopl, smf);
    ttconv(C_o, 512, 1024, g_Coph, g_Copl, smf);
    ttconv(W_o, 512, KY, g_Woph, g_Wopl, smf);
    ttconv(Ey_t, KY, 512, g_Eyph, g_Eypl, smf);
    gsync();

    // ---- prep wave 1: U_h = x @ U (128 jobs) + Wsb(s0) (8 jobs) ----
    for (int j = bid; j < 136; j += NB) {
        if (j < 128) {
            int mt = j >> 1, nt = j & 1;
            mma_tile<256>(g_xh + (size_t)mt * 64 * 512, g_xl + (size_t)mt * 64 * 512, 512,
                          g_Uph, g_Upl, 512,
                          g_Uh + (size_t)mt * 64 * 512, 512, nt * 256, 0, 512, smb);
        } else {
            int q = j - 128, ch = q >> 2, nt = q & 3;
            mma_tile<128>(g_sh[0], g_sl[0], 1024, g_Wph, g_Wpl, 1024,
                          g_wsbp[ch], 512, nt * 128, ch * 512, 512, smb);
        }
    }
    gsync();

    // ---- prep wave 2: energies for t=0 ----
    for (int j = bid; j < 256; j += NB) energy_job(j, bvec, v, smf);
    gsync();

    for (int t = 0; t < 64; t++) {
        const int cur = t & 1, nxt = cur ^ 1;

        // ---- B2: softmax+ctx (bid<64) / yE reduce+scale (bid>=64) ----
        if (bid < 64) {
            int b = bid;
            if (tid < 64) smf[tid] = g_e[b * 64 + tid];
            __syncthreads();
            float mx = -1e30f;
#pragma unroll
            for (int j = 0; j < 64; j++) mx = fmaxf(mx, smf[j]);
            float ex = (tid < 64) ? __expf(smf[tid] - mx) : 0.f;
            __syncthreads();
            if (tid < 64) smf[64 + tid] = ex;
            __syncthreads();
            float Z = 0.f;
#pragma unroll
            for (int j = 0; j < 64; j++) Z += smf[64 + j];
            float inv = 1.f / Z;
            const float* xb = x + (size_t)b * 64 * 512;
            float ca = 0.f;
            for (int j = 0; j < 64; j++) ca += smf[64 + j] * xb[j * 512 + tid];
            csplit(ca * inv, g_ctxh[b * 512 + tid], g_ctxl[b * 512 + tid]);
        } else if (t > 0) {
            for (size_t i = (size_t)(bid - 64) * NT + tid; i < 64 * 512; i += (size_t)84 * NT) {
                int b = (int)(i >> 9);
                float s = 0.f;
#pragma unroll
                for (int p = 0; p < 50; p++) s += g_yep[p][i];
                csplit(s * g_Zinv[b], g_yEh[i], g_yEl[i]);
            }
        }
        gsync();

        // ---- C: gi (48 jobs) + gh (96 jobs) ----
        for (int j = bid; j < 144; j += NB) {
            if (j < 48) {
                int ch = j / 24, nt = j % 24;
                mma_tile<128>(g_ctxh, g_ctxl, 512, g_Wihh, g_Wihl, 512,
                              g_gip[ch], 3072, nt * 128, ch * 256, 256, smb);
            } else {
                int q = j - 48, ch = q / 24, nt = q % 24;
                mma_tile<128>(g_sh[cur], g_sl[cur], 1024, g_Whhh, g_Whhl, 1024,
                              g_ghp[ch], 3072, nt * 128, ch * 256, 256, smb);
            }
        }
        gsync();

        // ---- D: gate combine ----
        for (size_t i = gth; i < 64 * 1024; i += GS) {
            int b = (int)(i >> 10), h = (int)(i & 1023);
            size_t bs = (size_t)b * 3072;
            float gr = b_ih[h], gz = b_ih[1024 + h], gn = b_ih[2048 + h];
            float hr = b_hh[h], hz = b_hh[1024 + h], hn = b_hh[2048 + h];
#pragma unroll
            for (int p = 0; p < 2; p++) {
                gr += g_gip[p][bs + h];
                gz += g_gip[p][bs + 1024 + h];
                gn += g_gip[p][bs + 2048 + h];
            }
#pragma unroll
            for (int p = 0; p < 4; p++) {
                hr += g_ghp[p][bs + h];
                hz += g_ghp[p][bs + 1024 + h];
                hn += g_ghp[p][bs + 2048 + h];
            }
            float r = 1.f / (1.f + __expf(-(gr + hr)));
            float zz = 1.f / (1.f + __expf(-(gz + hz)));
            float n = tanhf(gn + r * hn);
            float sn = (1.f - zz) * n + zz * g_sf[cur][i];
            g_sf[nxt][i] = sn;
            csplit(sn, g_sh[nxt][i], g_sl[nxt][i]);
        }
        gsync();

        // ---- E: t partials (64 jobs) ----
        for (int j = bid; j < 64; j += NB) {
            if (j < 32) {
                int ch = j >> 3, nt = j & 7;
                mma_tile<128>(g_sh[nxt], g_sl[nxt], 1024, g_Uoph, g_Uopl, 1024,
                              g_tp[ch], 1024, nt * 128, ch * 256, 256, smb);
            } else if (j < 48) {
                int q = j - 32, ch = q >> 3, nt = q & 7;
                mma_tile<128>(g_yEh, g_yEl, 512, g_Voph, g_Vopl, 512,
                              g_tp[4 + ch], 1024, nt * 128, ch * 256, 256, smb);
            } else {
                int q = j - 48, ch = q >> 3, nt = q & 7;
                mma_tile<128>(g_ctxh, g_ctxl, 512, g_Coph, g_Copl, 512,
                              g_tp[6 + ch], 1024, nt * 128, ch * 256, 256, smb);
            }
        }
        gsync();

        // ---- F: maxout ----
        for (size_t i = gth; i < 64 * 512; i += GS) {
            int b = (int)(i >> 9), d = (int)(i & 511);
            size_t base = (size_t)b * 1024 + 2 * d;
            float t0 = 0.f, t1 = 0.f;
#pragma unroll
            for (int p = 0; p < 8; p++) { t0 += g_tp[p][base]; t1 += g_tp[p][base + 1]; }
            csplit(fmaxf(t0, t1), g_tmh[i], g_tml[i]);
        }
        gsync();

        // ---- G: logits+exp+Zt (125 jobs, 256-wide) + Wsb t+1 (8 jobs): 1 wave ----
        for (int j = bid; j < 133; j += NB) {
            if (j < 125) {
                mma_tile_exp(g_tmh, g_tml, g_Woph, g_Wopl, j * 256, smb);
            } else {
                int q = j - 125, ch = q >> 2, nt = q & 3;
                mma_tile<128>(g_sh[nxt], g_sl[nxt], 1024, g_Wph, g_Wpl, 1024,
                              g_wsbp[ch], 512, nt * 128, ch * 512, 512, smb);
            }
        }
        gsync();

        // ---- I': yE MMA (blocks 0-99) | scale+Z + next-step energies (100-147) ----
        {
            float* po = out + (size_t)t * 64 * KY;
            if (bid < 100) {
                if (t < 63) {
                    int ch = bid >> 1, nt = bid & 1;
                    mma_tile<256>(g_evh, g_evl, KY, g_Eyph, g_Eypl, KY,
                                  g_yep[ch], 512, nt * 256, ch * 640, 640, smb);
                }
            } else {
                for (int b = bid - 100; b < 64; b += 48) {
                    float z = (tid < 125) ? g_Zt[b * 128 + tid] : 0.f;
                    z = block_sum(z, s_red);
                    float inv = 1.f / z;
                    if (tid == 0) g_Zinv[b] = inv;
                    const bf* eh = g_evh + (size_t)b * KY;
                    const bf* el = g_evl + (size_t)b * KY;
                    float* pb = po + (size_t)b * KY;
                    for (int k = tid; k < KY; k += NT)
                        pb[k] = (__bfloat162float(eh[k]) + __bfloat162float(el[k])) * inv;
                    __syncthreads();
                }
                if (t < 63)
                    for (int j = bid - 100; j < 256; j += 48) energy_job(j, bvec, v, smf);
            }
        }
        gsync();
    }
}

extern "C" void kernel_launch(void* const* d_in, const int* in_sizes, int n_in,
                              void* d_out, int out_size) {
    const float* x    = (const float*)d_in[0];
    const float* Ey_t = (const float*)d_in[1];
    const float* W    = (const float*)d_in[2];
    const float* U    = (const float*)d_in[3];
    const float* bvec = (const float*)d_in[4];
    const float* v    = (const float*)d_in[5];
    const float* W_ih = (const float*)d_in[6];
    const float* W_hh = (const float*)d_in[7];
    const float* b_ih = (const float*)d_in[8];
    const float* b_hh = (const float*)d_in[9];
    const float* U_o  = (const float*)d_in[10];
    const float* V_o  = (const float*)d_in[11];
    const float* C_o  = (const float*)d_in[12];
    const float* W_o  = (const float*)d_in[13];
    float* out = (float*)d_out;

    // 4 stages * (A 10240B + B 40960B) = 204800 B dynamic smem
    cudaFuncSetAttribute(dec_kernel, cudaFuncAttributeMaxDynamicSharedMemorySize, 212992);
    dec_kernel<<<NB, NT, 208896>>>(x, Ey_t, W, U, bvec, v, W_ih, W_hh, b_ih, b_hh,
                                   U_o, V_o, C_o, W_o, out);
}

// round 7
// speedup vs baseline: 1.0515x; 1.0515x over previous
#include <cuda_runtime.h>
#include <cuda_bf16.h>
#include <math.h>

#define NB 148
#define NT 512
#define KY 32000
typedef __nv_bfloat16 bf;

// ---------------- device scratch ----------------
__device__ __align__(128) bf g_xh[4096*512], g_xl[4096*512];
__device__ __align__(128) bf g_Wph[512*1024], g_Wpl[512*1024];
__device__ __align__(128) bf g_Uph[512*512], g_Upl[512*512];
__device__ __align__(128) bf g_Wihh[3072*512], g_Wihl[3072*512];
__device__ __align__(128) bf g_Whhh[3072*1024], g_Whhl[3072*1024];
__device__ __align__(128) bf g_Uoph[1024*1024], g_Uopl[1024*1024];
__device__ __align__(128) bf g_Voph[1024*512], g_Vopl[1024*512];
__device__ __align__(128) bf g_Coph[1024*512], g_Copl[1024*512];
__device__ __align__(128) bf g_Woph[(size_t)KY*512], g_Wopl[(size_t)KY*512];
__device__ __align__(128) bf g_Eyph[(size_t)512*KY], g_Eypl[(size_t)512*KY];
__device__ __align__(128) bf g_sh[2][64*1024], g_sl[2][64*1024];
__device__ __align__(128) bf g_ctxh[64*512], g_ctxl[64*512];
__device__ __align__(128) bf g_yEh[64*512], g_yEl[64*512];
__device__ __align__(128) bf g_tmh[64*512], g_tml[64*512];
__device__ __align__(128) bf g_evh[(size_t)64*KY], g_evl[(size_t)64*KY];
__device__ __align__(128) float g_sf[2][64*1024];
__device__ __align__(128) float g_Uh[4096*512];
__device__ __align__(128) float g_wsbp[2][64*512];
__device__ __align__(128) float g_e[64*64];
__device__ __align__(128) float g_gip[2][64*3072];
__device__ __align__(128) float g_ghp[4][64*3072];
__device__ __align__(128) float g_tp[8][64*1024];
__device__ __align__(128) float g_yep[25][64*512];
__device__ __align__(128) float g_Zt[64*256];
__device__ __align__(128) float g_Zinv[64];

// ---------------- grid barrier ----------------
__device__ unsigned g_cnt = 0;
__device__ volatile unsigned g_gen = 0;

__device__ __forceinline__ void gsync() {
    __syncthreads();
    if (threadIdx.x == 0) {
        unsigned gen = g_gen;
        __threadfence();
        if (atomicAdd(&g_cnt, 1u) == NB - 1u) {
            atomicExch(&g_cnt, 0u);
            __threadfence();
            g_gen = gen + 1u;
        } else {
            while (g_gen == gen) __nanosleep(64);
            __threadfence();
        }
    }
    __syncthreads();
}

__device__ __forceinline__ float tanh_fast(float x) {
    float y; asm("tanh.approx.f32 %0, %1;" : "=f"(y) : "f"(x)); return y;
}

__device__ __forceinline__ void csplit(float x, bf& h, bf& l) {
    h = __float2bfloat16(x);
    l = __float2bfloat16(x - __bfloat162float(h));
}

// named ring barriers: FULL = 1+slot, EMPTY = 5+slot.
// Participants per slot barrier: 2 producer warps (64) + 8 consumer warps (256) = 320.
__device__ __forceinline__ void bar_sync_id(int id) {
    asm volatile("bar.sync %0, 320;" :: "r"(id) : "memory");
}
__device__ __forceinline__ void bar_arrive_id(int id) {
    asm volatile("bar.arrive %0, 320;" :: "r"(id) : "memory");
}

__device__ __forceinline__ void ldsm4(unsigned& r0, unsigned& r1, unsigned& r2,
                                      unsigned& r3, unsigned saddr) {
    asm volatile("ldmatrix.sync.aligned.m8n8.x4.shared.b16 {%0,%1,%2,%3}, [%4];"
                 : "=r"(r0), "=r"(r1), "=r"(r2), "=r"(r3) : "r"(saddr));
}

#define MMA(d, a0, a1, a2, a3, b0, b1)                                        \
    asm volatile("mma.sync.aligned.m16n8k16.row.col.f32.bf16.bf16.f32 "       \
                 "{%0,%1,%2,%3}, {%4,%5,%6,%7}, {%8,%9}, {%0,%1,%2,%3};"      \
                 : "+f"(d[0]), "+f"(d[1]), "+f"(d[2]), "+f"(d[3])             \
                 : "r"(a0), "r"(a1), "r"(a2), "r"(a3), "r"(b0), "r"(b1))

// ---------------- warp-specialized 64x128 MMA core ----------------
// Ring slot layout (bf16 elem offsets, padded row stride 40):
//   A-hi row r: r*40 (r 0..63) | A-lo: +2560 | B-hi row n: +5120 (n 0..127) | B-lo: +10240
// Slot = 15360 elems = 30720 B; ring = 4 slots.
// Warps 8..15 produce (pair per slot), warps 0..7 consume (4m x 2n of 64x128).
__device__ __noinline__ void mma_ws(
    const bf* __restrict__ Ah, const bf* __restrict__ Al, int lda,
    const bf* __restrict__ Bh, const bf* __restrict__ Bl, int ldb,
    int n0, int k0, int kc, bf* __restrict__ ring, int& rbase, float* acc) {
    const int tid = threadIdx.x, wid = tid >> 5, lane = tid & 31;
    const int ns = kc >> 5;
    if (wid >= 8) {
        // ---- producer ----
        const int p = wid - 8;
        const int myslot = p & 3;
        const int phalf = p >> 2;
        const int q = phalf * 32 + lane;    // 0..63
        const int rg = q >> 2;              // row group 0..15
        const int ck = q & 3;               // 16B chunk 0..3
        const int s0 = (myslot - (rbase & 3)) & 3;
        bf* sl = ring + myslot * 15360;
        bf* dA  = sl + rg * 40 + ck * 8;
        bf* dAl = dA + 2560;
        bf* dB  = dA + 5120;
        bf* dBl = dA + 10240;
        for (int s = s0; s < ns; s += 4) {
            bar_sync_id(5 + myslot);
            const int kk = k0 + s * 32 + ck * 8;
            uint4 va[4], vb[4], vc[8], vd[8];
#pragma unroll
            for (int i = 0; i < 4; i++)
                va[i] = *(const uint4*)(Ah + (size_t)(rg + 16 * i) * lda + kk);
#pragma unroll
            for (int i = 0; i < 4; i++)
                vb[i] = *(const uint4*)(Al + (size_t)(rg + 16 * i) * lda + kk);
#pragma unroll
            for (int i = 0; i < 8; i++)
                vc[i] = *(const uint4*)(Bh + (size_t)(n0 + rg + 16 * i) * ldb + kk);
#pragma unroll
            for (int i = 0; i < 8; i++)
                vd[i] = *(const uint4*)(Bl + (size_t)(n0 + rg + 16 * i) * ldb + kk);
#pragma unroll
            for (int i = 0; i < 4; i++) *(uint4*)(dA + i * 640)  = va[i];
#pragma unroll
            for (int i = 0; i < 4; i++) *(uint4*)(dAl + i * 640) = vb[i];
#pragma unroll
            for (int i = 0; i < 8; i++) *(uint4*)(dB + i * 640)  = vc[i];
#pragma unroll
            for (int i = 0; i < 8; i++) *(uint4*)(dBl + i * 640) = vd[i];
            __threadfence_block();
            bar_arrive_id(1 + myslot);
        }
    } else {
        // ---- consumer ----
        const int mr = (wid & 3) << 4;
        const int nb = (wid >> 2) << 6;
#pragma unroll
        for (int i = 0; i < 32; i++) acc[i] = 0.f;
        unsigned base = (unsigned)__cvta_generic_to_shared(ring);
        const int arow = mr + (lane & 7) + ((lane >> 3) & 1) * 8;
        const int akof = (lane >> 4) * 8;
        const unsigned aoff = (unsigned)(arow * 40 + akof) * 2;
        const int brow = nb + (lane & 7) + (lane >> 4) * 8;
        const int bkof = ((lane >> 3) & 1) * 8;
        const unsigned boff = 10240u + (unsigned)(brow * 40 + bkof) * 2;
        for (int s = 0; s < ns; s++) {
            const int slot = (rbase + s) & 3;
            bar_sync_id(1 + slot);
            const unsigned sb = base + slot * 30720;
#pragma unroll
            for (int win = 0; win < 2; win++) {
                const unsigned kw = win * 32;
                unsigned ah[4], al[4];
                ldsm4(ah[0], ah[1], ah[2], ah[3], sb + aoff + kw);
                ldsm4(al[0], al[1], al[2], al[3], sb + 5120 + aoff + kw);
#pragma unroll
                for (int jp = 0; jp < 4; jp++) {
                    unsigned bh[4], bl[4];
                    const unsigned bo = sb + boff + jp * 1280 + kw;
                    ldsm4(bh[0], bh[1], bh[2], bh[3], bo);
                    ldsm4(bl[0], bl[1], bl[2], bl[3], bo + 10240);
                    float* d0 = acc + jp * 8;
                    float* d1 = acc + jp * 8 + 4;
                    MMA(d0, ah[0], ah[1], ah[2], ah[3], bh[0], bh[1]);
                    MMA(d0, ah[0], ah[1], ah[2], ah[3], bl[0], bl[1]);
                    MMA(d0, al[0], al[1], al[2], al[3], bh[0], bh[1]);
                    MMA(d1, ah[0], ah[1], ah[2], ah[3], bh[2], bh[3]);
                    MMA(d1, ah[0], ah[1], ah[2], ah[3], bl[2], bl[3]);
                    MMA(d1, al[0], al[1], al[2], al[3], bh[2], bh[3]);
                }
            }
            bar_arrive_id(5 + slot);
        }
    }
    rbase += ns;
}

__device__ __noinline__ void mma_tile(
    const bf* __restrict__ Ah, const bf* __restrict__ Al, int lda,
    const bf* __restrict__ Bh, const bf* __restrict__ Bl, int ldb,
    float* __restrict__ C, int ldc, int n0, int k0, int kc,
    bf* ring, int& rbase) {
    float acc[32];
    mma_ws(Ah, Al, lda, Bh, Bl, ldb, n0, k0, kc, ring, rbase, acc);
    const int tid = threadIdx.x, wid = tid >> 5, lane = tid & 31;
    if (wid < 8) {
        const int mr = (wid & 3) << 4, nb = (wid >> 2) << 6;
        const int fr = lane >> 2, fc = (lane & 3) << 1;
#pragma unroll
        for (int jp = 0; jp < 4; jp++)
#pragma unroll
            for (int t = 0; t < 2; t++) {
                int col = n0 + nb + jp * 16 + t * 8 + fc;
                int f = jp * 8 + t * 4;
                float* c0 = C + (size_t)(mr + fr) * ldc + col;
                *(float2*)c0 = make_float2(acc[f], acc[f + 1]);
                *(float2*)(c0 + (size_t)8 * ldc) = make_float2(acc[f + 2], acc[f + 3]);
            }
    }
}

// logits tile -> exp into g_evh/evl + deterministic row sums g_Zt
__device__ __noinline__ void mma_tile_exp(
    const bf* __restrict__ Ah, const bf* __restrict__ Al,
    const bf* __restrict__ Bh, const bf* __restrict__ Bl,
    int n0, bf* ring, int& rbase, float* smf) {
    float acc[32];
    mma_ws(Ah, Al, 512, Bh, Bl, 512, n0, 0, 512, ring, rbase, acc);
    const int tid = threadIdx.x, wid = tid >> 5, lane = tid & 31;
    if (wid < 8) {
        const int mr = (wid & 3) << 4, nb = (wid >> 2) << 6;
        const int fr = lane >> 2, fc = (lane & 3) << 1;
        float rs0 = 0.f, rs1 = 0.f;
#pragma unroll
        for (int jp = 0; jp < 4; jp++)
#pragma unroll
            for (int t = 0; t < 2; t++) {
                int f = jp * 8 + t * 4;
#pragma unroll
                for (int q = 0; q < 2; q++) {
                    int col = n0 + nb + jp * 16 + t * 8 + fc + q;
                    float e0 = __expf(acc[f + q]);
                    float e1 = __expf(acc[f + 2 + q]);
                    rs0 += e0; rs1 += e1;
                    size_t i0 = (size_t)(mr + fr) * KY + col;
                    size_t i1 = i0 + (size_t)8 * KY;
                    csplit(e0, g_evh[i0], g_evl[i0]);
                    csplit(e1, g_evh[i1], g_evl[i1]);
                }
            }
        rs0 += __shfl_xor_sync(~0u, rs0, 1); rs0 += __shfl_xor_sync(~0u, rs0, 2);
        rs1 += __shfl_xor_sync(~0u, rs1, 1); rs1 += __shfl_xor_sync(~0u, rs1, 2);
        if ((lane & 3) == 0) { smf[wid * 16 + fr] = rs0; smf[wid * 16 + 8 + fr] = rs1; }
    }
    __syncthreads();
    if (tid < 64) {
        int mb = tid >> 4, rr = tid & 15;
        g_Zt[tid * 256 + (n0 >> 7)] = smf[mb * 16 + rr] + smf[(mb + 4) * 16 + rr];
    }
    __syncthreads();
}

// attention energy job j (b = j>>2, 16 rows of e per job)
__device__ void energy_job(int j, const float* __restrict__ bvec,
                           const float* __restrict__ v, float* smf) {
    int b = j >> 2, jg = j & 3;
    int tid = threadIdx.x, lane = tid & 31;
    __syncthreads();
    smf[tid] = g_wsbp[0][b * 512 + tid] + g_wsbp[1][b * 512 + tid] + bvec[tid];
    smf[512 + tid] = v[tid];
    __syncthreads();
    int jr = jg * 16 + (tid >> 5);
    const float* uh = g_Uh + (size_t)(b * 64 + jr) * 512;
    float acc = 0.f;
    for (int c = lane; c < 512; c += 32)
        acc += tanh_fast(smf[c] + uh[c]) * smf[512 + c];
#pragma unroll
    for (int o = 16; o > 0; o >>= 1) acc += __shfl_down_sync(~0u, acc, o);
    if (lane == 0) g_e[b * 64 + jr] = acc;
}

__device__ __forceinline__ float block_sum(float v, float* red) {
#pragma unroll
    for (int o = 16; o > 0; o >>= 1) v += __shfl_down_sync(0xffffffffu, v, o);
    if ((threadIdx.x & 31) == 0) red[threadIdx.x >> 5] = v;
    __syncthreads();
    float r = 0.f;
#pragma unroll
    for (int i = 0; i < 16; i++) r += red[i];
    __syncthreads();
    return r;
}

__device__ void convN(const float* __restrict__ in, size_t n,
                      bf* __restrict__ oh, bf* __restrict__ ol, size_t gth, size_t gs) {
    for (size_t i = gth; i < n; i += gs) csplit(in[i], oh[i], ol[i]);
}

__device__ void ttconv(const float* __restrict__ in, int R, int Cc,
                       bf* __restrict__ oh, bf* __restrict__ ol, float* sm) {
    int ntr = R >> 5, ntc = Cc >> 5;
    int tx = threadIdx.x & 31, ty = threadIdx.x >> 5;
    for (int tile = blockIdx.x; tile < ntr * ntc; tile += NB) {
        int tr = tile / ntc, tc = tile % ntc;
        int r0 = tr << 5, c0 = tc << 5;
        __syncthreads();
        sm[ty * 33 + tx]        = in[(size_t)(r0 + ty) * Cc + c0 + tx];
        sm[(ty + 16) * 33 + tx] = in[(size_t)(r0 + ty + 16) * Cc + c0 + tx];
        __syncthreads();
        size_t o0 = (size_t)(c0 + ty) * R + r0 + tx;
        size_t o1 = (size_t)(c0 + ty + 16) * R + r0 + tx;
        csplit(sm[tx * 33 + ty], oh[o0], ol[o0]);
        csplit(sm[tx * 33 + ty + 16], oh[o1], ol[o1]);
    }
}

__global__ __launch_bounds__(NT, 1) void dec_kernel(
    const float* __restrict__ x,    const float* __restrict__ Ey_t,
    const float* __restrict__ W,    const float* __restrict__ U,
    const float* __restrict__ bvec, const float* __restrict__ v,
    const float* __restrict__ W_ih, const float* __restrict__ W_hh,
    const float* __restrict__ b_ih, const float* __restrict__ b_hh,
    const float* __restrict__ U_o,  const float* __restrict__ V_o,
    const float* __restrict__ C_o,  const float* __restrict__ W_o,
    float* __restrict__ out) {
    extern __shared__ __align__(16) char sraw[];
    float* smf = (float*)sraw;                 // 8KB scratch
    float* s_red = smf + 1024;
    bf* ring = (bf*)(sraw + 8192);             // 4 x 30720B ring
    const int tid = threadIdx.x, bid = blockIdx.x;
    const int wid = tid >> 5;
    const size_t gth = (size_t)bid * NT + tid, GS = (size_t)NB * NT;
    const bf z0 = __float2bfloat16(0.f);
    int rbase = 0;

    // prime empty credits for the 4 ring slots (consumers arrive)
    if (wid < 8) {
#pragma unroll
        for (int s = 0; s < 4; s++) bar_arrive_id(5 + s);
    }

    // ---- prep wave 0: zeros + weight packing ----
    for (size_t i = gth; i < 64 * 1024; i += GS) {
        g_sf[0][i] = 0.f; g_sh[0][i] = z0; g_sl[0][i] = z0;
    }
    for (size_t i = gth; i < 64 * 512; i += GS) { g_yEh[i] = z0; g_yEl[i] = z0; }
    convN(x, (size_t)4096 * 512, g_xh, g_xl, gth, GS);
    convN(W_ih, (size_t)3072 * 512, g_Wihh, g_Wihl, gth, GS);
    convN(W_hh, (size_t)3072 * 1024, g_Whhh, g_Whhl, gth, GS);
    ttconv(W, 1024, 512, g_Wph, g_Wpl, smf);
    ttconv(U, 512, 512, g_Uph, g_Upl, smf);
    ttconv(U_o, 1024, 1024, g_Uoph, g_Uopl, smf);
    ttconv(V_o, 512, 1024, g_Voph, g_Vopl, smf);
    ttconv(C_o, 512, 1024, g_Coph, g_Copl, smf);
    ttconv(W_o, 512, KY, g_Woph, g_Wopl, smf);
    ttconv(Ey_t, KY, 512, g_Eyph, g_Eypl, smf);
    gsync();

    // ---- prep wave 1: U_h = x @ U (256 jobs) + Wsb(s0) (8 jobs) ----
    for (int j = bid; j < 264; j += NB) {
        if (j < 256) {
            int mt = j >> 2, nt = j & 3;
            mma_tile(g_xh + (size_t)mt * 64 * 512, g_xl + (size_t)mt * 64 * 512, 512,
                     g_Uph, g_Upl, 512,
                     g_Uh + (size_t)mt * 64 * 512, 512, nt * 128, 0, 512, ring, rbase);
        } else {
            int q = j - 256, ch = q >> 2, nt = q & 3;
            mma_tile(g_sh[0], g_sl[0], 1024, g_Wph, g_Wpl, 1024,
                     g_wsbp[ch], 512, nt * 128, ch * 512, 512, ring, rbase);
        }
    }
    gsync();

    // ---- prep wave 2: energies for t=0 ----
    for (int j = bid; j < 256; j += NB) energy_job(j, bvec, v, smf);
    gsync();

    for (int t = 0; t < 64; t++) {
        const int cur = t & 1, nxt = cur ^ 1;

        // ---- B2: softmax+ctx (bid<64) / yE reduce+scale (bid>=64) ----
        if (bid < 64) {
            int b = bid;
            if (tid < 64) smf[tid] = g_e[b * 64 + tid];
            __syncthreads();
            float mx = -1e30f;
#pragma unroll
            for (int j = 0; j < 64; j++) mx = fmaxf(mx, smf[j]);
            float ex = (tid < 64) ? __expf(smf[tid] - mx) : 0.f;
            __syncthreads();
            if (tid < 64) smf[64 + tid] = ex;
            __syncthreads();
            float Z = 0.f;
#pragma unroll
            for (int j = 0; j < 64; j++) Z += smf[64 + j];
            float inv = 1.f / Z;
            const float* xb = x + (size_t)b * 64 * 512;
            float ca = 0.f;
            for (int j = 0; j < 64; j++) ca += smf[64 + j] * xb[j * 512 + tid];
            csplit(ca * inv, g_ctxh[b * 512 + tid], g_ctxl[b * 512 + tid]);
        } else if (t > 0) {
            for (size_t i = (size_t)(bid - 64) * NT + tid; i < 64 * 512; i += (size_t)84 * NT) {
                int b = (int)(i >> 9);
                float s = 0.f;
#pragma unroll
                for (int p = 0; p < 25; p++) s += g_yep[p][i];
                csplit(s * g_Zinv[b], g_yEh[i], g_yEl[i]);
            }
        }
        gsync();

        // ---- C: gi (48 jobs) + gh (96 jobs) ----
        for (int j = bid; j < 144; j += NB) {
            if (j < 48) {
                int ch = j / 24, nt = j % 24;
                mma_tile(g_ctxh, g_ctxl, 512, g_Wihh, g_Wihl, 512,
                         g_gip[ch], 3072, nt * 128, ch * 256, 256, ring, rbase);
            } else {
                int q = j - 48, ch = q / 24, nt = q % 24;
                mma_tile(g_sh[cur], g_sl[cur], 1024, g_Whhh, g_Whhl, 1024,
                         g_ghp[ch], 3072, nt * 128, ch * 256, 256, ring, rbase);
            }
        }
        gsync();

        // ---- D: gate combine ----
        for (size_t i = gth; i < 64 * 1024; i += GS) {
            int b = (int)(i >> 10), h = (int)(i & 1023);
            size_t bs = (size_t)b * 3072;
            float gr = b_ih[h], gz = b_ih[1024 + h], gn = b_ih[2048 + h];
            float hr = b_hh[h], hz = b_hh[1024 + h], hn = b_hh[2048 + h];
#pragma unroll
            for (int p = 0; p < 2; p++) {
                gr += g_gip[p][bs + h];
                gz += g_gip[p][bs + 1024 + h];
                gn += g_gip[p][bs + 2048 + h];
            }
#pragma unroll
            for (int p = 0; p < 4; p++) {
                hr += g_ghp[p][bs + h];
                hz += g_ghp[p][bs + 1024 + h];
                hn += g_ghp[p][bs + 2048 + h];
            }
            float r = 1.f / (1.f + __expf(-(gr + hr)));
            float zz = 1.f / (1.f + __expf(-(gz + hz)));
            float n = tanhf(gn + r * hn);
            float sn = (1.f - zz) * n + zz * g_sf[cur][i];
            g_sf[nxt][i] = sn;
            csplit(sn, g_sh[nxt][i], g_sl[nxt][i]);
        }
        gsync();

        // ---- E: t partials (64 jobs) ----
        for (int j = bid; j < 64; j += NB) {
            if (j < 32) {
                int ch = j >> 3, nt = j & 7;
                mma_tile(g_sh[nxt], g_sl[nxt], 1024, g_Uoph, g_Uopl, 1024,
                         g_tp[ch], 1024, nt * 128, ch * 256, 256, ring, rbase);
            } else if (j < 48) {
                int q = j - 32, ch = q >> 3, nt = q & 7;
                mma_tile(g_yEh, g_yEl, 512, g_Voph, g_Vopl, 512,
                         g_tp[4 + ch], 1024, nt * 128, ch * 256, 256, ring, rbase);
            } else {
                int q = j - 48, ch = q >> 3, nt = q & 7;
                mma_tile(g_ctxh, g_ctxl, 512, g_Coph, g_Copl, 512,
                         g_tp[6 + ch], 1024, nt * 128, ch * 256, 256, ring, rbase);
            }
        }
        gsync();

        // ---- F: maxout ----
        for (size_t i = gth; i < 64 * 512; i += GS) {
            int b = (int)(i >> 9), d = (int)(i & 511);
            size_t base = (size_t)b * 1024 + 2 * d;
            float t0 = 0.f, t1 = 0.f;
#pragma unroll
            for (int p = 0; p < 8; p++) { t0 += g_tp[p][base]; t1 += g_tp[p][base + 1]; }
            csplit(fmaxf(t0, t1), g_tmh[i], g_tml[i]);
        }
        gsync();

        // ---- G: logits+exp+Zt (250 jobs) + Wsb for t+1 (8 jobs) ----
        for (int j = bid; j < 258; j += NB) {
            if (j < 250) {
                mma_tile_exp(g_tmh, g_tml, g_Woph, g_Wopl, j * 128, ring, rbase, smf);
            } else {
                int q = j - 250, ch = q >> 2, nt = q & 3;
                mma_tile(g_sh[nxt], g_sl[nxt], 1024, g_Wph, g_Wpl, 1024,
                         g_wsbp[ch], 512, nt * 128, ch * 512, 512, ring, rbase);
            }
        }
        gsync();

        // ---- I': yE MMA (blocks 0-99) | scale+Z + next-step energies (100-147) ----
        {
            float* po = out + (size_t)t * 64 * KY;
            if (bid < 100) {
                if (t < 63) {
                    int ch = bid >> 2, nt = bid & 3;
                    mma_tile(g_evh, g_evl, KY, g_Eyph, g_Eypl, KY,
                             g_yep[ch], 512, nt * 128, ch * 1280, 1280, ring, rbase);
                }
            } else {
                for (int b = bid - 100; b < 64; b += 48) {
                    float z = (tid < 250) ? g_Zt[b * 256 + tid] : 0.f;
                    z = block_sum(z, s_red);
                    float inv = 1.f / z;
                    if (tid == 0) g_Zinv[b] = inv;
                    const bf* eh = g_evh + (size_t)b * KY;
                    const bf* el = g_evl + (size_t)b * KY;
                    float* pb = po + (size_t)b * KY;
                    for (int k = tid; k < KY; k += NT)
                        pb[k] = (__bfloat162float(eh[k]) + __bfloat162float(el[k])) * inv;
                    __syncthreads();
                }
                if (t < 63)
                    for (int j = bid - 100; j < 256; j += 48) energy_job(j, bvec, v, smf);
            }
        }
        gsync();
    }
}

extern "C" void kernel_launch(void* const* d_in, const int* in_sizes, int n_in,
                              void* d_out, int out_size) {
    const float* x    = (const float*)d_in[0];
    const float* Ey_t = (const float*)d_in[1];
    const float* W    = (const float*)d_in[2];
    const float* U    = (const float*)d_in[3];
    const float* bvec = (const float*)d_in[4];
    const float* v    = (const float*)d_in[5];
    const float* W_ih = (const float*)d_in[6];
    const float* W_hh = (const float*)d_in[7];
    const float* b_ih = (const float*)d_in[8];
    const float* b_hh = (const float*)d_in[9];
    const float* U_o  = (const float*)d_in[10];
    const float* V_o  = (const float*)d_in[11];
    const float* C_o  = (const float*)d_in[12];
    const float* W_o  = (const float*)d_in[13];
    float* out = (float*)d_out;

    // 8KB scratch + 4 ring slots x 30720B = 131072 B dynamic smem
    cudaFuncSetAttribute(dec_kernel, cudaFuncAttributeMaxDynamicSharedMemorySize, 135168);
    dec_kernel<<<NB, NT, 131072>>>(x, Ey_t, W, U, bvec, v, W_ih, W_hh, b_ih, b_hh,
                                   U_o, V_o, C_o, W_o, out);
}

// round 8
// speedup vs baseline: 1.0692x; 1.0169x over previous
#include <cuda_runtime.h>
#include <cuda_bf16.h>
#include <math.h>

#define NB 148
#define NT 512
#define KY 32000
typedef __nv_bfloat16 bf;

// ---------------- device scratch ----------------
__device__ __align__(128) bf g_xh[4096*512], g_xl[4096*512];
__device__ __align__(128) bf g_Wph[512*1024], g_Wpl[512*1024];
__device__ __align__(128) bf g_Uph[512*512], g_Upl[512*512];
__device__ __align__(128) bf g_Wihh[3072*512], g_Wihl[3072*512];
__device__ __align__(128) bf g_Whhh[3072*1024], g_Whhl[3072*1024];
__device__ __align__(128) bf g_Uoph[1024*1024], g_Uopl[1024*1024];
__device__ __align__(128) bf g_Voph[1024*512], g_Vopl[1024*512];
__device__ __align__(128) bf g_Coph[1024*512], g_Copl[1024*512];
__device__ __align__(128) bf g_Woph[(size_t)KY*512], g_Wopl[(size_t)KY*512];
__device__ __align__(128) bf g_Eyph[(size_t)512*KY], g_Eypl[(size_t)512*KY];
__device__ __align__(128) bf g_sh[2][64*1024], g_sl[2][64*1024];
__device__ __align__(128) bf g_ctxh[64*512], g_ctxl[64*512];
__device__ __align__(128) bf g_yEh[64*512], g_yEl[64*512];
__device__ __align__(128) bf g_tmh[64*512], g_tml[64*512];
__device__ __align__(128) bf g_evh[(size_t)64*KY], g_evl[(size_t)64*KY];
__device__ __align__(128) float g_sf[2][64*1024];
__device__ __align__(128) float g_Uh[4096*512];
__device__ __align__(128) float g_wsbp[2][64*512];
__device__ __align__(128) float g_e[64*64];
__device__ __align__(128) float g_gip[2][64*3072];
__device__ __align__(128) float g_ghp[4][64*3072];
__device__ __align__(128) float g_tp[8][64*1024];
__device__ __align__(128) float g_yep[50][64*512];
__device__ __align__(128) float g_Zt[64*128];
__device__ __align__(128) float g_Zinv[64];

// ---------------- grid barrier ----------------
__device__ unsigned g_cnt = 0;
__device__ volatile unsigned g_gen = 0;

__device__ __forceinline__ void gsync() {
    __syncthreads();
    if (threadIdx.x == 0) {
        unsigned gen = g_gen;
        __threadfence();
        if (atomicAdd(&g_cnt, 1u) == NB - 1u) {
            atomicExch(&g_cnt, 0u);
            __threadfence();
            g_gen = gen + 1u;
        } else {
            while (g_gen == gen) __nanosleep(64);
            __threadfence();
        }
    }
    __syncthreads();
}

__device__ __forceinline__ float tanh_fast(float x) {
    float y; asm("tanh.approx.f32 %0, %1;" : "=f"(y) : "f"(x)); return y;
}

__device__ __forceinline__ void csplit(float x, bf& h, bf& l) {
    h = __float2bfloat16(x);
    l = __float2bfloat16(x - __bfloat162float(h));
}

#define MMA(d, a0, a1, a2, a3, b0, b1)                                        \
    asm volatile("mma.sync.aligned.m16n8k16.row.col.f32.bf16.bf16.f32 "       \
                 "{%0,%1,%2,%3}, {%4,%5,%6,%7}, {%8,%9}, {%0,%1,%2,%3};"      \
                 : "+f"(d[0]), "+f"(d[1]), "+f"(d[2]), "+f"(d[3])             \
                 : "r"(a0), "r"(a1), "r"(a2), "r"(a3), "r"(b0), "r"(b1))

// ------- core: acc = A[0:64][k0:k0+kc] * B^T (3-term bf16 split) -------
// Register 1-deep prefetch + double-buffered padded smem.
// NTILE in {128, 256}; KS in {64, 32}; kc % KS == 0.
template<int NTILE, int KS>
__device__ __noinline__ void mma_core(
    const bf* __restrict__ Ah, const bf* __restrict__ Al, int lda,
    const bf* __restrict__ Bh, const bf* __restrict__ Bl, int ldb,
    int n0, int k0, int kc, bf* __restrict__ sm, float* acc) {
    constexpr int STR  = KS + 8;
    constexpr int CPR  = KS / 8;          // 16B chunks per row
    constexpr int APL  = 64 * STR;        // A plane (one of hi/lo)
    constexpr int BPL  = NTILE * STR;
    constexpr int ASTG = 2 * APL;
    constexpr int BSTG = 2 * BPL;
    constexpr int CA   = KS / 32;         // uint4 per thread for A
    constexpr int CB   = (NTILE * KS) / 2048;
    constexpr int NJ   = NTILE / 32;
    constexpr int AHALF = 64 * CPR;
    constexpr int BHALF = NTILE * CPR;
    bf* sA = sm;
    bf* sB = sm + 2 * ASTG;
    const int tid = threadIdx.x;
    const int w = tid >> 5, lane = tid & 31;
    const int mr = (w & 3) << 4;
    const int nc = (w >> 2) * (NTILE / 4);
    const int fr = lane >> 2, fc = (lane & 3) << 1;
    const int aoff = (mr + fr) * STR + fc;
    const int boff = (nc + fr) * STR + fc;
#pragma unroll
    for (int i = 0; i < NJ * 4; i++) acc[i] = 0.f;

    uint4 rga[CA], rgb[CB];
    const int ns = kc / KS;

    // preload stage 0
#pragma unroll
    for (int i = 0; i < CA; i++) {
        int p = tid + i * 512, hl = p / AHALF, q = p % AHALF;
        int row = q / CPR, ck = q % CPR;
        rga[i] = *(const uint4*)((hl ? Al : Ah) + (size_t)row * lda + k0 + ck * 8);
    }
#pragma unroll
    for (int i = 0; i < CB; i++) {
        int p = tid + i * 512, hl = p / BHALF, q = p % BHALF;
        int row = q / CPR, ck = q % CPR;
        rgb[i] = *(const uint4*)((hl ? Bl : Bh) + (size_t)(n0 + row) * ldb + k0 + ck * 8);
    }
#pragma unroll
    for (int i = 0; i < CA; i++) {
        int p = tid + i * 512, hl = p / AHALF, q = p % AHALF;
        int row = q / CPR, ck = q % CPR;
        *(uint4*)(sA + hl * APL + row * STR + ck * 8) = rga[i];
    }
#pragma unroll
    for (int i = 0; i < CB; i++) {
        int p = tid + i * 512, hl = p / BHALF, q = p % BHALF;
        int row = q / CPR, ck = q % CPR;
        *(uint4*)(sB + hl * BPL + row * STR + ck * 8) = rgb[i];
    }
    __syncthreads();

    int st = 0;
    for (int s = 0; s < ns; s++) {
        const bool more = s + 1 < ns;
        if (more) {
            const int kk = k0 + (s + 1) * KS;
#pragma unroll
            for (int i = 0; i < CA; i++) {
                int p = tid + i * 512, hl = p / AHALF, q = p % AHALF;
                int row = q / CPR, ck = q % CPR;
                rga[i] = *(const uint4*)((hl ? Al : Ah) + (size_t)row * lda + kk + ck * 8);
            }
#pragma unroll
            for (int i = 0; i < CB; i++) {
                int p = tid + i * 512, hl = p / BHALF, q = p % BHALF;
                int row = q / CPR, ck = q % CPR;
                rgb[i] = *(const uint4*)((hl ? Bl : Bh) + (size_t)(n0 + row) * ldb + kk + ck * 8);
            }
        }
        const bf* sAs = sA + st * ASTG;
        const bf* sBs = sB + st * BSTG;
#pragma unroll
        for (int win = 0; win < KS / 16; win++) {
            const int ko = win << 4;
            const bf* pah = sAs + aoff + ko;
            unsigned ah0 = *(const unsigned*)(pah);
            unsigned ah1 = *(const unsigned*)(pah + 8 * STR);
            unsigned ah2 = *(const unsigned*)(pah + 8);
            unsigned ah3 = *(const unsigned*)(pah + 8 * STR + 8);
            const bf* pal = pah + APL;
            unsigned al0 = *(const unsigned*)(pal);
            unsigned al1 = *(const unsigned*)(pal + 8 * STR);
            unsigned al2 = *(const unsigned*)(pal + 8);
            unsigned al3 = *(const unsigned*)(pal + 8 * STR + 8);
#pragma unroll
            for (int j = 0; j < NJ; j++) {
                const bf* pbh = sBs + boff + ko + j * 8 * STR;
                unsigned bh0 = *(const unsigned*)(pbh);
                unsigned bh1 = *(const unsigned*)(pbh + 8);
                const bf* pbl = pbh + BPL;
                unsigned bl0 = *(const unsigned*)(pbl);
                unsigned bl1 = *(const unsigned*)(pbl + 8);
                float* d = acc + j * 4;
                MMA(d, ah0, ah1, ah2, ah3, bh0, bh1);
                MMA(d, ah0, ah1, ah2, ah3, bl0, bl1);
                MMA(d, al0, al1, al2, al3, bh0, bh1);
            }
        }
        if (more) {
            const int sn = st ^ 1;
            bf* dA = sA + sn * ASTG;
            bf* dB = sB + sn * BSTG;
#pragma unroll
            for (int i = 0; i < CA; i++) {
                int p = tid + i * 512, hl = p / AHALF, q = p % AHALF;
                int row = q / CPR, ck = q % CPR;
                *(uint4*)(dA + hl * APL + row * STR + ck * 8) = rga[i];
            }
#pragma unroll
            for (int i = 0; i < CB; i++) {
                int p = tid + i * 512, hl = p / BHALF, q = p % BHALF;
                int row = q / CPR, ck = q % CPR;
                *(uint4*)(dB + hl * BPL + row * STR + ck * 8) = rgb[i];
            }
        }
        __syncthreads();
        st ^= 1;
    }
}

template<int NTILE, int KS>
__device__ __noinline__ void mma_tile(
    const bf* __restrict__ Ah, const bf* __restrict__ Al, int lda,
    const bf* __restrict__ Bh, const bf* __restrict__ Bl, int ldb,
    float* __restrict__ C, int ldc, int n0, int k0, int kc, bf* sm) {
    float acc[(NTILE / 32) * 4];
    mma_core<NTILE, KS>(Ah, Al, lda, Bh, Bl, ldb, n0, k0, kc, sm, acc);
    const int tid = threadIdx.x;
    const int w = tid >> 5, lane = tid & 31;
    const int mr = (w & 3) << 4;
    const int nc = (w >> 2) * (NTILE / 4);
    const int fr = lane >> 2, fc = (lane & 3) << 1;
#pragma unroll
    for (int j = 0; j < NTILE / 32; j++) {
        int col = n0 + nc + j * 8 + fc;
        float* c0 = C + (size_t)(mr + fr) * ldc + col;
        *(float2*)c0 = make_float2(acc[j*4], acc[j*4+1]);
        *(float2*)(c0 + (size_t)8 * ldc) = make_float2(acc[j*4+2], acc[j*4+3]);
    }
}

// logits 64x256 tile -> exp into g_evh/evl + deterministic row sums g_Zt
__device__ __noinline__ void mma_tile_exp(
    const bf* __restrict__ Ah, const bf* __restrict__ Al,
    const bf* __restrict__ Bh, const bf* __restrict__ Bl,
    int n0, bf* sm) {
    float acc[32];
    mma_core<256, 32>(Ah, Al, 512, Bh, Bl, 512, n0, 0, 512, sm, acc);
    const int tid = threadIdx.x;
    const int w = tid >> 5, lane = tid & 31;
    const int mr = (w & 3) << 4, nc = (w >> 2) << 6;
    const int fr = lane >> 2, fc = (lane & 3) << 1;
    float rs0 = 0.f, rs1 = 0.f;
#pragma unroll
    for (int j = 0; j < 8; j++) {
#pragma unroll
        for (int q = 0; q < 2; q++) {
            int col = n0 + nc + j * 8 + fc + q;
            float e0 = __expf(acc[j*4+q]);
            float e1 = __expf(acc[j*4+2+q]);
            rs0 += e0; rs1 += e1;
            size_t i0 = (size_t)(mr + fr) * KY + col;
            size_t i1 = i0 + (size_t)8 * KY;
            csplit(e0, g_evh[i0], g_evl[i0]);
            csplit(e1, g_evh[i1], g_evl[i1]);
        }
    }
    rs0 += __shfl_xor_sync(~0u, rs0, 1); rs0 += __shfl_xor_sync(~0u, rs0, 2);
    rs1 += __shfl_xor_sync(~0u, rs1, 1); rs1 += __shfl_xor_sync(~0u, rs1, 2);
    float* srs = (float*)sm;
    if ((lane & 3) == 0) { srs[w * 16 + fr] = rs0; srs[w * 16 + 8 + fr] = rs1; }
    __syncthreads();
    if (tid < 64) {
        int mg = tid >> 4, rr = tid & 15;
        float z = srs[mg * 16 + rr] + srs[(4 + mg) * 16 + rr] +
                  srs[(8 + mg) * 16 + rr] + srs[(12 + mg) * 16 + rr];
        g_Zt[tid * 128 + (n0 >> 8)] = z;
    }
    __syncthreads();
}

// attention energy job j (b = j>>2, 16 rows of e per job)
__device__ void energy_job(int j, const float* __restrict__ bvec,
                           const float* __restrict__ v, float* smf) {
    int b = j >> 2, jg = j & 3;
    int tid = threadIdx.x, lane = tid & 31;
    __syncthreads();
    smf[tid] = g_wsbp[0][b * 512 + tid] + g_wsbp[1][b * 512 + tid] + bvec[tid];
    smf[512 + tid] = v[tid];
    __syncthreads();
    int jr = jg * 16 + (tid >> 5);
    const float* uh = g_Uh + (size_t)(b * 64 + jr) * 512;
    float acc = 0.f;
    for (int c = lane; c < 512; c += 32)
        acc += tanh_fast(smf[c] + uh[c]) * smf[512 + c];
#pragma unroll
    for (int o = 16; o > 0; o >>= 1) acc += __shfl_down_sync(~0u, acc, o);
    if (lane == 0) g_e[b * 64 + jr] = acc;
}

__device__ __forceinline__ float block_sum(float v, float* red) {
#pragma unroll
    for (int o = 16; o > 0; o >>= 1) v += __shfl_down_sync(0xffffffffu, v, o);
    if ((threadIdx.x & 31) == 0) red[threadIdx.x >> 5] = v;
    __syncthreads();
    float r = 0.f;
#pragma unroll
    for (int i = 0; i < 16; i++) r += red[i];
    __syncthreads();
    return r;
}

__device__ void convN(const float* __restrict__ in, size_t n,
                      bf* __restrict__ oh, bf* __restrict__ ol, size_t gth, size_t gs) {
    for (size_t i = gth; i < n; i += gs) csplit(in[i], oh[i], ol[i]);
}

__device__ void ttconv(const float* __restrict__ in, int R, int Cc,
                       bf* __restrict__ oh, bf* __restrict__ ol, float* sm) {
    int ntr = R >> 5, ntc = Cc >> 5;
    int tx = threadIdx.x & 31, ty = threadIdx.x >> 5;
    for (int tile = blockIdx.x; tile < ntr * ntc; tile += NB) {
        int tr = tile / ntc, tc = tile % ntc;
        int r0 = tr << 5, c0 = tc << 5;
        __syncthreads();
        sm[ty * 33 + tx]        = in[(size_t)(r0 + ty) * Cc + c0 + tx];
        sm[(ty + 16) * 33 + tx] = in[(size_t)(r0 + ty + 16) * Cc + c0 + tx];
        __syncthreads();
        size_t o0 = (size_t)(c0 + ty) * R + r0 + tx;
        size_t o1 = (size_t)(c0 + ty + 16) * R + r0 + tx;
        csplit(sm[tx * 33 + ty], oh[o0], ol[o0]);
        csplit(sm[tx * 33 + ty + 16], oh[o1], ol[o1]);
    }
}

__global__ __launch_bounds__(NT, 1) void dec_kernel(
    const float* __restrict__ x,    const float* __restrict__ Ey_t,
    const float* __restrict__ W,    const float* __restrict__ U,
    const float* __restrict__ bvec, const float* __restrict__ v,
    const float* __restrict__ W_ih, const float* __restrict__ W_hh,
    const float* __restrict__ b_ih, const float* __restrict__ b_hh,
    const float* __restrict__ U_o,  const float* __restrict__ V_o,
    const float* __restrict__ C_o,  const float* __restrict__ W_o,
    float* __restrict__ out) {
    extern __shared__ __align__(16) char sraw[];
    bf* smb = (bf*)sraw;
    float* smf = (float*)sraw;
    float* s_red = smf + 1024;
    const int tid = threadIdx.x, bid = blockIdx.x;
    const size_t gth = (size_t)bid * NT + tid, GS = (size_t)NB * NT;
    const bf z0 = __float2bfloat16(0.f);

    // ---- prep wave 0: zeros + weight packing ----
    for (size_t i = gth; i < 64 * 1024; i += GS) {
        g_sf[0][i] = 0.f; g_sh[0][i] = z0; g_sl[0][i] = z0;
    }
    for (size_t i = gth; i < 64 * 512; i += GS) { g_yEh[i] = z0; g_yEl[i] = z0; }
    convN(x, (size_t)4096 * 512, g_xh, g_xl, gth, GS);
    convN(W_ih, (size_t)3072 * 512, g_Wihh, g_Wihl, gth, GS);
    convN(W_hh, (size_t)3072 * 1024, g_Whhh, g_Whhl, gth, GS);
    ttconv(W, 1024, 512, g_Wph, g_Wpl, smf);
    ttconv(U, 512, 512, g_Uph, g_Upl, smf);
    ttconv(U_o, 1024, 1024, g_Uoph, g_Uopl, smf);
    ttconv(V_o, 512, 1024, g_Voph, g_Vopl, smf);
    ttconv(C_o, 512, 1024, g_Coph, g_Copl, smf);
    ttconv(W_o, 512, KY, g_Woph, g_Wopl, smf);
    ttconv(Ey_t, KY, 512, g_Eyph, g_Eypl, smf);
    gsync();

    // ---- prep wave 1: U_h = x @ U (128 jobs, 256-wide) + Wsb(s0) (8 jobs) ----
    for (int j = bid; j < 136; j += NB) {
        if (j < 128) {
            int mt = j >> 1, nt = j & 1;
            mma_tile<256, 32>(g_xh + (size_t)mt * 64 * 512, g_xl + (size_t)mt * 64 * 512, 512,
                              g_Uph, g_Upl, 512,
                              g_Uh + (size_t)mt * 64 * 512, 512, nt * 256, 0, 512, smb);
        } else {
            int q = j - 128, ch = q >> 2, nt = q & 3;
            mma_tile<128, 64>(g_sh[0], g_sl[0], 1024, g_Wph, g_Wpl, 1024,
                              g_wsbp[ch], 512, nt * 128, ch * 512, 512, smb);
        }
    }
    gsync();

    // ---- prep wave 2: energies for t=0 ----
    for (int j = bid; j < 256; j += NB) energy_job(j, bvec, v, smf);
    gsync();

    for (int t = 0; t < 64; t++) {
        const int cur = t & 1, nxt = cur ^ 1;

        // ---- B2: softmax+ctx (bid<64) / yE reduce+scale (bid>=64) ----
        if (bid < 64) {
            int b = bid;
            if (tid < 64) smf[tid] = g_e[b * 64 + tid];
            __syncthreads();
            float mx = -1e30f;
#pragma unroll
            for (int j = 0; j < 64; j++) mx = fmaxf(mx, smf[j]);
            float ex = (tid < 64) ? __expf(smf[tid] - mx) : 0.f;
            __syncthreads();
            if (tid < 64) smf[64 + tid] = ex;
            __syncthreads();
            float Z = 0.f;
#pragma unroll
            for (int j = 0; j < 64; j++) Z += smf[64 + j];
            float inv = 1.f / Z;
            const float* xb = x + (size_t)b * 64 * 512;
            float ca = 0.f;
            for (int j = 0; j < 64; j++) ca += smf[64 + j] * xb[j * 512 + tid];
            csplit(ca * inv, g_ctxh[b * 512 + tid], g_ctxl[b * 512 + tid]);
        } else if (t > 0) {
            for (size_t i = (size_t)(bid - 64) * NT + tid; i < 64 * 512; i += (size_t)84 * NT) {
                int b = (int)(i >> 9);
                float s = 0.f;
#pragma unroll
                for (int p = 0; p < 50; p++) s += g_yep[p][i];
                csplit(s * g_Zinv[b], g_yEh[i], g_yEl[i]);
            }
        }
        gsync();

        // ---- C: gi (48 jobs) + gh (96 jobs) ----
        for (int j = bid; j < 144; j += NB) {
            if (j < 48) {
                int ch = j / 24, nt = j % 24;
                mma_tile<128, 64>(g_ctxh, g_ctxl, 512, g_Wihh, g_Wihl, 512,
                                  g_gip[ch], 3072, nt * 128, ch * 256, 256, smb);
            } else {
                int q = j - 48, ch = q / 24, nt = q % 24;
                mma_tile<128, 64>(g_sh[cur], g_sl[cur], 1024, g_Whhh, g_Whhl, 1024,
                                  g_ghp[ch], 3072, nt * 128, ch * 256, 256, smb);
            }
        }
        gsync();

        // ---- D: gate combine ----
        for (size_t i = gth; i < 64 * 1024; i += GS) {
            int b = (int)(i >> 10), h = (int)(i & 1023);
            size_t bs = (size_t)b * 3072;
            float gr = b_ih[h], gz = b_ih[1024 + h], gn = b_ih[2048 + h];
            float hr = b_hh[h], hz = b_hh[1024 + h], hn = b_hh[2048 + h];
#pragma unroll
            for (int p = 0; p < 2; p++) {
                gr += g_gip[p][bs + h];
                gz += g_gip[p][bs + 1024 + h];
                gn += g_gip[p][bs + 2048 + h];
            }
#pragma unroll
            for (int p = 0; p < 4; p++) {
                hr += g_ghp[p][bs + h];
                hz += g_ghp[p][bs + 1024 + h];
                hn += g_ghp[p][bs + 2048 + h];
            }
            float r = 1.f / (1.f + __expf(-(gr + hr)));
            float zz = 1.f / (1.f + __expf(-(gz + hz)));
            float n = tanhf(gn + r * hn);
            float sn = (1.f - zz) * n + zz * g_sf[cur][i];
            g_sf[nxt][i] = sn;
            csplit(sn, g_sh[nxt][i], g_sl[nxt][i]);
        }
        gsync();

        // ---- E: t partials (64 jobs) ----
        for (int j = bid; j < 64; j += NB) {
            if (j < 32) {
                int ch = j >> 3, nt = j & 7;
                mma_tile<128, 64>(g_sh[nxt], g_sl[nxt], 1024, g_Uoph, g_Uopl, 1024,
                                  g_tp[ch], 1024, nt * 128, ch * 256, 256, smb);
            } else if (j < 48) {
                int q = j - 32, ch = q >> 3, nt = q & 7;
                mma_tile<128, 64>(g_yEh, g_yEl, 512, g_Voph, g_Vopl, 512,
                                  g_tp[4 + ch], 1024, nt * 128, ch * 256, 256, smb);
            } else {
                int q = j - 48, ch = q >> 3, nt = q & 7;
                mma_tile<128, 64>(g_ctxh, g_ctxl, 512, g_Coph, g_Copl, 512,
                                  g_tp[6 + ch], 1024, nt * 128, ch * 256, 256, smb);
            }
        }
        gsync();

        // ---- F: maxout ----
        for (size_t i = gth; i < 64 * 512; i += GS) {
            int b = (int)(i >> 9), d = (int)(i & 511);
            size_t base = (size_t)b * 1024 + 2 * d;
            float t0 = 0.f, t1 = 0.f;
#pragma unroll
            for (int p = 0; p < 8; p++) { t0 += g_tp[p][base]; t1 += g_tp[p][base + 1]; }
            csplit(fmaxf(t0, t1), g_tmh[i], g_tml[i]);
        }
        gsync();

        // ---- G: logits+exp+Zt (125 jobs, 256-wide) + Wsb t+1 (8 jobs): 1 wave ----
        for (int j = bid; j < 133; j += NB) {
            if (j < 125) {
                mma_tile_exp(g_tmh, g_tml, g_Woph, g_Wopl, j * 256, smb);
            } else {
                int q = j - 125, ch = q >> 2, nt = q & 3;
                mma_tile<128, 64>(g_sh[nxt], g_sl[nxt], 1024, g_Wph, g_Wpl, 1024,
                                  g_wsbp[ch], 512, nt * 128, ch * 512, 512, smb);
            }
        }
        gsync();

        // ---- I': yE MMA (blocks 0-99) | scale+Z + next-step energies (100-147) ----
        {
            float* po = out + (size_t)t * 64 * KY;
            if (bid < 100) {
                if (t < 63) {
                    int ch = bid >> 1, nt = bid & 1;
                    mma_tile<256, 32>(g_evh, g_evl, KY, g_Eyph, g_Eypl, KY,
                                      g_yep[ch], 512, nt * 256, ch * 640, 640, smb);
                }
            } else {
                for (int b = bid - 100; b < 64; b += 48) {
                    float z = (tid < 125) ? g_Zt[b * 128 + tid] : 0.f;
                    z = block_sum(z, s_red);
                    float inv = 1.f / z;
                    if (tid == 0) g_Zinv[b] = inv;
                    const bf* eh = g_evh + (size_t)b * KY;
                    const bf* el = g_evl + (size_t)b * KY;
                    float* pb = po + (size_t)b * KY;
                    for (int k = tid; k < KY; k += NT)
                        pb[k] = (__bfloat162float(eh[k]) + __bfloat162float(el[k])) * inv;
                    __syncthreads();
                }
                if (t < 63)
                    for (int j = bid - 100; j < 256; j += 48) energy_job(j, bvec, v, smf);
            }
        }
        gsync();
    }
}

extern "C" void kernel_launch(void* const* d_in, const int* in_sizes, int n_in,
                              void* d_out, int out_size) {
    const float* x    = (const float*)d_in[0];
    const float* Ey_t = (const float*)d_in[1];
    const float* W    = (const float*)d_in[2];
    const float* U    = (const float*)d_in[3];
    const float* bvec = (const float*)d_in[4];
    const float* v    = (const float*)d_in[5];
    const float* W_ih = (const float*)d_in[6];
    const float* W_hh = (const float*)d_in[7];
    const float* b_ih = (const float*)d_in[8];
    const float* b_hh = (const float*)d_in[9];
    const float* U_o  = (const float*)d_in[10];
    const float* V_o  = (const float*)d_in[11];
    const float* C_o  = (const float*)d_in[12];
    const float* W_o  = (const float*)d_in[13];
    float* out = (float*)d_out;

    // arena: max over variants = 110592 B (NTILE=128, KS=64)
    cudaFuncSetAttribute(dec_kernel, cudaFuncAttributeMaxDynamicSharedMemorySize, 114688);
    dec_kernel<<<NB, NT, 110592>>>(x, Ey_t, W, U, bvec, v, W_ih, W_hh, b_ih, b_hh,
                                   U_o, V_o, C_o, W_o, out);
}

// round 9
// speedup vs baseline: 3.4128x; 3.1918x over previous
#include <cuda_runtime.h>
#include <cuda_bf16.h>
#include <math.h>

#define NB 148
#define NT 512
#define KY 32000
typedef __nv_bfloat16 bf;

// ---------------- device scratch ----------------
__device__ __align__(128) bf g_xh[4096*512], g_xl[4096*512];
__device__ __align__(128) bf g_Wph[512*1024], g_Wpl[512*1024];
__device__ __align__(128) bf g_Uph[512*512], g_Upl[512*512];
__device__ __align__(128) bf g_Wihh[3072*512], g_Wihl[3072*512];
__device__ __align__(128) bf g_Whhh[3072*1024], g_Whhl[3072*1024];
__device__ __align__(128) bf g_Uoph[1024*1024], g_Uopl[1024*1024];
__device__ __align__(128) bf g_Voph[1024*512], g_Vopl[1024*512];
__device__ __align__(128) bf g_Coph[1024*512], g_Copl[1024*512];
__device__ __align__(128) bf g_Woph[(size_t)KY*512], g_Wopl[(size_t)KY*512];
__device__ __align__(128) bf g_Eyph[(size_t)512*KY], g_Eypl[(size_t)512*KY];
__device__ __align__(128) bf g_sh[2][64*1024], g_sl[2][64*1024];
__device__ __align__(128) bf g_ctxh[64*512], g_ctxl[64*512];
__device__ __align__(128) bf g_yEh[64*512], g_yEl[64*512];
__device__ __align__(128) bf g_tmh[64*512], g_tml[64*512];
__device__ __align__(128) bf g_evh[(size_t)64*KY], g_evl[(size_t)64*KY];
__device__ __align__(128) float g_sf[2][64*1024];
__device__ __align__(128) float g_Uh[4096*512];
__device__ __align__(128) float g_wsbp[2][64*512];
__device__ __align__(128) float g_e[64*64];
__device__ __align__(128) float g_gip[2][64*3072];
__device__ __align__(128) float g_ghp[4][64*3072];
__device__ __align__(128) float g_tp[8][64*1024];
__device__ __align__(128) float g_yep[50][64*512];
__device__ __align__(128) float g_Zt[64*128];
__device__ __align__(128) float g_Zinv[64];

// ---------------- grid barrier ----------------
__device__ unsigned g_cnt = 0;
__device__ volatile unsigned g_gen = 0;

__device__ __forceinline__ void gsync() {
    __syncthreads();
    if (threadIdx.x == 0) {
        unsigned gen = g_gen;
        __threadfence();
        if (atomicAdd(&g_cnt, 1u) == NB - 1u) {
            atomicExch(&g_cnt, 0u);
            __threadfence();
            g_gen = gen + 1u;
        } else {
            while (g_gen == gen) __nanosleep(64);
            __threadfence();
        }
    }
    __syncthreads();
}

__device__ __forceinline__ float tanh_fast(float x) {
    float y; asm("tanh.approx.f32 %0, %1;" : "=f"(y) : "f"(x)); return y;
}

__device__ __forceinline__ void csplit(float x, bf& h, bf& l) {
    h = __float2bfloat16(x);
    l = __float2bfloat16(x - __bfloat162float(h));
}

#define MMA(d, a0, a1, a2, a3, b0, b1)                                        \
    asm volatile("mma.sync.aligned.m16n8k16.row.col.f32.bf16.bf16.f32 "       \
                 "{%0,%1,%2,%3}, {%4,%5,%6,%7}, {%8,%9}, {%0,%1,%2,%3};"      \
                 : "+f"(d[0]), "+f"(d[1]), "+f"(d[2]), "+f"(d[3])             \
                 : "r"(a0), "r"(a1), "r"(a2), "r"(a3), "r"(b0), "r"(b1))

// ------- core: acc = A[0:64][k0:k0+kc] * B^T (3-term bf16 split) -------
// Register 1-deep prefetch + double-buffered padded smem.
// FORCEINLINE is load-bearing: acc must stay in registers (see R5/R7/R8 post-mortem).
template<int NTILE, int KS>
__device__ __forceinline__ void mma_core(
    const bf* __restrict__ Ah, const bf* __restrict__ Al, int lda,
    const bf* __restrict__ Bh, const bf* __restrict__ Bl, int ldb,
    int n0, int k0, int kc, bf* __restrict__ sm, float* acc) {
    constexpr int STR  = KS + 8;
    constexpr int CPR  = KS / 8;          // 16B chunks per row
    constexpr int APL  = 64 * STR;        // A plane (one of hi/lo)
    constexpr int BPL  = NTILE * STR;
    constexpr int ASTG = 2 * APL;
    constexpr int BSTG = 2 * BPL;
    constexpr int CA   = KS / 32;         // uint4 per thread for A
    constexpr int CB   = (NTILE * KS) / 2048;
    constexpr int NJ   = NTILE / 32;
    constexpr int AHALF = 64 * CPR;
    constexpr int BHALF = NTILE * CPR;
    bf* sA = sm;
    bf* sB = sm + 2 * ASTG;
    const int tid = threadIdx.x;
    const int w = tid >> 5, lane = tid & 31;
    const int mr = (w & 3) << 4;
    const int nc = (w >> 2) * (NTILE / 4);
    const int fr = lane >> 2, fc = (lane & 3) << 1;
    const int aoff = (mr + fr) * STR + fc;
    const int boff = (nc + fr) * STR + fc;
#pragma unroll
    for (int i = 0; i < NJ * 4; i++) acc[i] = 0.f;

    uint4 rga[CA], rgb[CB];
    const int ns = kc / KS;

    // preload stage 0
#pragma unroll
    for (int i = 0; i < CA; i++) {
        int p = tid + i * 512, hl = p / AHALF, q = p % AHALF;
        int row = q / CPR, ck = q % CPR;
        rga[i] = *(const uint4*)((hl ? Al : Ah) + (size_t)row * lda + k0 + ck * 8);
    }
#pragma unroll
    for (int i = 0; i < CB; i++) {
        int p = tid + i * 512, hl = p / BHALF, q = p % BHALF;
        int row = q / CPR, ck = q % CPR;
        rgb[i] = *(const uint4*)((hl ? Bl : Bh) + (size_t)(n0 + row) * ldb + k0 + ck * 8);
    }
#pragma unroll
    for (int i = 0; i < CA; i++) {
        int p = tid + i * 512, hl = p / AHALF, q = p % AHALF;
        int row = q / CPR, ck = q % CPR;
        *(uint4*)(sA + hl * APL + row * STR + ck * 8) = rga[i];
    }
#pragma unroll
    for (int i = 0; i < CB; i++) {
        int p = tid + i * 512, hl = p / BHALF, q = p % BHALF;
        int row = q / CPR, ck = q % CPR;
        *(uint4*)(sB + hl * BPL + row * STR + ck * 8) = rgb[i];
    }
    __syncthreads();

    int st = 0;
    for (int s = 0; s < ns; s++) {
        const bool more = s + 1 < ns;
        if (more) {
            const int kk = k0 + (s + 1) * KS;
#pragma unroll
            for (int i = 0; i < CA; i++) {
                int p = tid + i * 512, hl = p / AHALF, q = p % AHALF;
                int row = q / CPR, ck = q % CPR;
                rga[i] = *(const uint4*)((hl ? Al : Ah) + (size_t)row * lda + kk + ck * 8);
            }
#pragma unroll
            for (int i = 0; i < CB; i++) {
                int p = tid + i * 512, hl = p / BHALF, q = p % BHALF;
                int row = q / CPR, ck = q % CPR;
                rgb[i] = *(const uint4*)((hl ? Bl : Bh) + (size_t)(n0 + row) * ldb + kk + ck * 8);
            }
        }
        const bf* sAs = sA + st * ASTG;
        const bf* sBs = sB + st * BSTG;
#pragma unroll
        for (int win = 0; win < KS / 16; win++) {
            const int ko = win << 4;
            const bf* pah = sAs + aoff + ko;
            unsigned ah0 = *(const unsigned*)(pah);
            unsigned ah1 = *(const unsigned*)(pah + 8 * STR);
            unsigned ah2 = *(const unsigned*)(pah + 8);
            unsigned ah3 = *(const unsigned*)(pah + 8 * STR + 8);
            const bf* pal = pah + APL;
            unsigned al0 = *(const unsigned*)(pal);
            unsigned al1 = *(const unsigned*)(pal + 8 * STR);
            unsigned al2 = *(const unsigned*)(pal + 8);
            unsigned al3 = *(const unsigned*)(pal + 8 * STR + 8);
#pragma unroll
            for (int j = 0; j < NJ; j++) {
                const bf* pbh = sBs + boff + ko + j * 8 * STR;
                unsigned bh0 = *(const unsigned*)(pbh);
                unsigned bh1 = *(const unsigned*)(pbh + 8);
                const bf* pbl = pbh + BPL;
                unsigned bl0 = *(const unsigned*)(pbl);
                unsigned bl1 = *(const unsigned*)(pbl + 8);
                float* d = acc + j * 4;
                MMA(d, ah0, ah1, ah2, ah3, bh0, bh1);
                MMA(d, ah0, ah1, ah2, ah3, bl0, bl1);
                MMA(d, al0, al1, al2, al3, bh0, bh1);
            }
        }
        if (more) {
            const int sn = st ^ 1;
            bf* dA = sA + sn * ASTG;
            bf* dB = sB + sn * BSTG;
#pragma unroll
            for (int i = 0; i < CA; i++) {
                int p = tid + i * 512, hl = p / AHALF, q = p % AHALF;
                int row = q / CPR, ck = q % CPR;
                *(uint4*)(dA + hl * APL + row * STR + ck * 8) = rga[i];
            }
#pragma unroll
            for (int i = 0; i < CB; i++) {
                int p = tid + i * 512, hl = p / BHALF, q = p % BHALF;
                int row = q / CPR, ck = q % CPR;
                *(uint4*)(dB + hl * BPL + row * STR + ck * 8) = rgb[i];
            }
        }
        __syncthreads();
        st ^= 1;
    }
}

template<int NTILE, int KS>
__device__ __noinline__ void mma_tile(
    const bf* __restrict__ Ah, const bf* __restrict__ Al, int lda,
    const bf* __restrict__ Bh, const bf* __restrict__ Bl, int ldb,
    float* __restrict__ C, int ldc, int n0, int k0, int kc, bf* sm) {
    float acc[(NTILE / 32) * 4];
    mma_core<NTILE, KS>(Ah, Al, lda, Bh, Bl, ldb, n0, k0, kc, sm, acc);
    const int tid = threadIdx.x;
    const int w = tid >> 5, lane = tid & 31;
    const int mr = (w & 3) << 4;
    const int nc = (w >> 2) * (NTILE / 4);
    const int fr = lane >> 2, fc = (lane & 3) << 1;
#pragma unroll
    for (int j = 0; j < NTILE / 32; j++) {
        int col = n0 + nc + j * 8 + fc;
        float* c0 = C + (size_t)(mr + fr) * ldc + col;
        *(float2*)c0 = make_float2(acc[j*4], acc[j*4+1]);
        *(float2*)(c0 + (size_t)8 * ldc) = make_float2(acc[j*4+2], acc[j*4+3]);
    }
}

// logits 64x256 tile -> exp into g_evh/evl + deterministic row sums g_Zt
__device__ __noinline__ void mma_tile_exp(
    const bf* __restrict__ Ah, const bf* __restrict__ Al,
    const bf* __restrict__ Bh, const bf* __restrict__ Bl,
    int n0, bf* sm) {
    float acc[32];
    mma_core<256, 32>(Ah, Al, 512, Bh, Bl, 512, n0, 0, 512, sm, acc);
    const int tid = threadIdx.x;
    const int w = tid >> 5, lane = tid & 31;
    const int mr = (w & 3) << 4, nc = (w >> 2) << 6;
    const int fr = lane >> 2, fc = (lane & 3) << 1;
    float rs0 = 0.f, rs1 = 0.f;
#pragma unroll
    for (int j = 0; j < 8; j++) {
#pragma unroll
        for (int q = 0; q < 2; q++) {
            int col = n0 + nc + j * 8 + fc + q;
            float e0 = __expf(acc[j*4+q]);
            float e1 = __expf(acc[j*4+2+q]);
            rs0 += e0; rs1 += e1;
            size_t i0 = (size_t)(mr + fr) * KY + col;
            size_t i1 = i0 + (size_t)8 * KY;
            csplit(e0, g_evh[i0], g_evl[i0]);
            csplit(e1, g_evh[i1], g_evl[i1]);
        }
    }
    rs0 += __shfl_xor_sync(~0u, rs0, 1); rs0 += __shfl_xor_sync(~0u, rs0, 2);
    rs1 += __shfl_xor_sync(~0u, rs1, 1); rs1 += __shfl_xor_sync(~0u, rs1, 2);
    float* srs = (float*)sm;
    if ((lane & 3) == 0) { srs[w * 16 + fr] = rs0; srs[w * 16 + 8 + fr] = rs1; }
    __syncthreads();
    if (tid < 64) {
        int mg = tid >> 4, rr = tid & 15;
        float z = srs[mg * 16 + rr] + srs[(4 + mg) * 16 + rr] +
                  srs[(8 + mg) * 16 + rr] + srs[(12 + mg) * 16 + rr];
        g_Zt[tid * 128 + (n0 >> 8)] = z;
    }
    __syncthreads();
}

// attention energy job j (b = j>>2, 16 rows of e per job)
__device__ void energy_job(int j, const float* __restrict__ bvec,
                           const float* __restrict__ v, float* smf) {
    int b = j >> 2, jg = j & 3;
    int tid = threadIdx.x, lane = tid & 31;
    __syncthreads();
    smf[tid] = g_wsbp[0][b * 512 + tid] + g_wsbp[1][b * 512 + tid] + bvec[tid];
    smf[512 + tid] = v[tid];
    __syncthreads();
    int jr = jg * 16 + (tid >> 5);
    const float* uh = g_Uh + (size_t)(b * 64 + jr) * 512;
    float acc = 0.f;
    for (int c = lane; c < 512; c += 32)
        acc += tanh_fast(smf[c] + uh[c]) * smf[512 + c];
#pragma unroll
    for (int o = 16; o > 0; o >>= 1) acc += __shfl_down_sync(~0u, acc, o);
    if (lane == 0) g_e[b * 64 + jr] = acc;
}

__device__ __forceinline__ float block_sum(float v, float* red) {
#pragma unroll
    for (int o = 16; o > 0; o >>= 1) v += __shfl_down_sync(0xffffffffu, v, o);
    if ((threadIdx.x & 31) == 0) red[threadIdx.x >> 5] = v;
    __syncthreads();
    float r = 0.f;
#pragma unroll
    for (int i = 0; i < 16; i++) r += red[i];
    __syncthreads();
    return r;
}

__device__ void convN(const float* __restrict__ in, size_t n,
                      bf* __restrict__ oh, bf* __restrict__ ol, size_t gth, size_t gs) {
    for (size_t i = gth; i < n; i += gs) csplit(in[i], oh[i], ol[i]);
}

__device__ void ttconv(const float* __restrict__ in, int R, int Cc,
                       bf* __restrict__ oh, bf* __restrict__ ol, float* sm) {
    int ntr = R >> 5, ntc = Cc >> 5;
    int tx = threadIdx.x & 31, ty = threadIdx.x >> 5;
    for (int tile = blockIdx.x; tile < ntr * ntc; tile += NB) {
        int tr = tile / ntc, tc = tile % ntc;
        int r0 = tr << 5, c0 = tc << 5;
        __syncthreads();
        sm[ty * 33 + tx]        = in[(size_t)(r0 + ty) * Cc + c0 + tx];
        sm[(ty + 16) * 33 + tx] = in[(size_t)(r0 + ty + 16) * Cc + c0 + tx];
        __syncthreads();
        size_t o0 = (size_t)(c0 + ty) * R + r0 + tx;
        size_t o1 = (size_t)(c0 + ty + 16) * R + r0 + tx;
        csplit(sm[tx * 33 + ty], oh[o0], ol[o0]);
        csplit(sm[tx * 33 + ty + 16], oh[o1], ol[o1]);
    }
}

__global__ __launch_bounds__(NT, 1) void dec_kernel(
    const float* __restrict__ x,    const float* __restrict__ Ey_t,
    const float* __restrict__ W,    const float* __restrict__ U,
    const float* __restrict__ bvec, const float* __restrict__ v,
    const float* __restrict__ W_ih, const float* __restrict__ W_hh,
    const float* __restrict__ b_ih, const float* __restrict__ b_hh,
    const float* __restrict__ U_o,  const float* __restrict__ V_o,
    const float* __restrict__ C_o,  const float* __restrict__ W_o,
    float* __restrict__ out) {
    extern __shared__ __align__(16) char sraw[];
    bf* smb = (bf*)sraw;
    float* smf = (float*)sraw;
    float* s_red = smf + 1024;
    const int tid = threadIdx.x, bid = blockIdx.x;
    const size_t gth = (size_t)bid * NT + tid, GS = (size_t)NB * NT;
    const bf z0 = __float2bfloat16(0.f);

    // ---- prep wave 0: zeros + weight packing ----
    for (size_t i = gth; i < 64 * 1024; i += GS) {
        g_sf[0][i] = 0.f; g_sh[0][i] = z0; g_sl[0][i] = z0;
    }
    for (size_t i = gth; i < 64 * 512; i += GS) { g_yEh[i] = z0; g_yEl[i] = z0; }
    convN(x, (size_t)4096 * 512, g_xh, g_xl, gth, GS);
    convN(W_ih, (size_t)3072 * 512, g_Wihh, g_Wihl, gth, GS);
    convN(W_hh, (size_t)3072 * 1024, g_Whhh, g_Whhl, gth, GS);
    ttconv(W, 1024, 512, g_Wph, g_Wpl, smf);
    ttconv(U, 512, 512, g_Uph, g_Upl, smf);
    ttconv(U_o, 1024, 1024, g_Uoph, g_Uopl, smf);
    ttconv(V_o, 512, 1024, g_Voph, g_Vopl, smf);
    ttconv(C_o, 512, 1024, g_Coph, g_Copl, smf);
    ttconv(W_o, 512, KY, g_Woph, g_Wopl, smf);
    ttconv(Ey_t, KY, 512, g_Eyph, g_Eypl, smf);
    gsync();

    // ---- prep wave 1: U_h = x @ U (128 jobs, 256-wide) + Wsb(s0) (8 jobs) ----
    for (int j = bid; j < 136; j += NB) {
        if (j < 128) {
            int mt = j >> 1, nt = j & 1;
            mma_tile<256, 32>(g_xh + (size_t)mt * 64 * 512, g_xl + (size_t)mt * 64 * 512, 512,
                              g_Uph, g_Upl, 512,
                              g_Uh + (size_t)mt * 64 * 512, 512, nt * 256, 0, 512, smb);
        } else {
            int q = j - 128, ch = q >> 2, nt = q & 3;
            mma_tile<128, 64>(g_sh[0], g_sl[0], 1024, g_Wph, g_Wpl, 1024,
                              g_wsbp[ch], 512, nt * 128, ch * 512, 512, smb);
        }
    }
    gsync();

    // ---- prep wave 2: energies for t=0 ----
    for (int j = bid; j < 256; j += NB) energy_job(j, bvec, v, smf);
    gsync();

    for (int t = 0; t < 64; t++) {
        const int cur = t & 1, nxt = cur ^ 1;

        // ---- B2: softmax+ctx (bid<64) / yE reduce+scale (bid>=64) ----
        if (bid < 64) {
            int b = bid;
            if (tid < 64) smf[tid] = g_e[b * 64 + tid];
            __syncthreads();
            float mx = -1e30f;
#pragma unroll
            for (int j = 0; j < 64; j++) mx = fmaxf(mx, smf[j]);
            float ex = (tid < 64) ? __expf(smf[tid] - mx) : 0.f;
            __syncthreads();
            if (tid < 64) smf[64 + tid] = ex;
            __syncthreads();
            float Z = 0.f;
#pragma unroll
            for (int j = 0; j < 64; j++) Z += smf[64 + j];
            float inv = 1.f / Z;
            const float* xb = x + (size_t)b * 64 * 512;
            float ca = 0.f;
            for (int j = 0; j < 64; j++) ca += smf[64 + j] * xb[j * 512 + tid];
            csplit(ca * inv, g_ctxh[b * 512 + tid], g_ctxl[b * 512 + tid]);
        } else if (t > 0) {
            for (size_t i = (size_t)(bid - 64) * NT + tid; i < 64 * 512; i += (size_t)84 * NT) {
                int b = (int)(i >> 9);
                float s = 0.f;
#pragma unroll
                for (int p = 0; p < 50; p++) s += g_yep[p][i];
                csplit(s * g_Zinv[b], g_yEh[i], g_yEl[i]);
            }
        }
        gsync();

        // ---- C: gi (48 jobs) + gh (96 jobs) ----
        for (int j = bid; j < 144; j += NB) {
            if (j < 48) {
                int ch = j / 24, nt = j % 24;
                mma_tile<128, 64>(g_ctxh, g_ctxl, 512, g_Wihh, g_Wihl, 512,
                                  g_gip[ch], 3072, nt * 128, ch * 256, 256, smb);
            } else {
                int q = j - 48, ch = q / 24, nt = q % 24;
                mma_tile<128, 64>(g_sh[cur], g_sl[cur], 1024, g_Whhh, g_Whhl, 1024,
                                  g_ghp[ch], 3072, nt * 128, ch * 256, 256, smb);
            }
        }
        gsync();

        // ---- D: gate combine ----
        for (size_t i = gth; i < 64 * 1024; i += GS) {
            int b = (int)(i >> 10), h = (int)(i & 1023);
            size_t bs = (size_t)b * 3072;
            float gr = b_ih[h], gz = b_ih[1024 + h], gn = b_ih[2048 + h];
            float hr = b_hh[h], hz = b_hh[1024 + h], hn = b_hh[2048 + h];
#pragma unroll
            for (int p = 0; p < 2; p++) {
                gr += g_gip[p][bs + h];
                gz += g_gip[p][bs + 1024 + h];
                gn += g_gip[p][bs + 2048 + h];
            }
#pragma unroll
            for (int p = 0; p < 4; p++) {
                hr += g_ghp[p][bs + h];
                hz += g_ghp[p][bs + 1024 + h];
                hn += g_ghp[p][bs + 2048 + h];
            }
            float r = 1.f / (1.f + __expf(-(gr + hr)));
            float zz = 1.f / (1.f + __expf(-(gz + hz)));
            float n = tanhf(gn + r * hn);
            float sn = (1.f - zz) * n + zz * g_sf[cur][i];
            g_sf[nxt][i] = sn;
            csplit(sn, g_sh[nxt][i], g_sl[nxt][i]);
        }
        gsync();

        // ---- E: t partials (64 jobs) ----
        for (int j = bid; j < 64; j += NB) {
            if (j < 32) {
                int ch = j >> 3, nt = j & 7;
                mma_tile<128, 64>(g_sh[nxt], g_sl[nxt], 1024, g_Uoph, g_Uopl, 1024,
                                  g_tp[ch], 1024, nt * 128, ch * 256, 256, smb);
            } else if (j < 48) {
                int q = j - 32, ch = q >> 3, nt = q & 7;
                mma_tile<128, 64>(g_yEh, g_yEl, 512, g_Voph, g_Vopl, 512,
                                  g_tp[4 + ch], 1024, nt * 128, ch * 256, 256, smb);
            } else {
                int q = j - 48, ch = q >> 3, nt = q & 7;
                mma_tile<128, 64>(g_ctxh, g_ctxl, 512, g_Coph, g_Copl, 512,
                                  g_tp[6 + ch], 1024, nt * 128, ch * 256, 256, smb);
            }
        }
        gsync();

        // ---- F: maxout ----
        for (size_t i = gth; i < 64 * 512; i += GS) {
            int b = (int)(i >> 9), d = (int)(i & 511);
            size_t base = (size_t)b * 1024 + 2 * d;
            float t0 = 0.f, t1 = 0.f;
#pragma unroll
            for (int p = 0; p < 8; p++) { t0 += g_tp[p][base]; t1 += g_tp[p][base + 1]; }
            csplit(fmaxf(t0, t1), g_tmh[i], g_tml[i]);
        }
        gsync();

        // ---- G: logits+exp+Zt (125 jobs, 256-wide) + Wsb t+1 (8 jobs): 1 wave ----
        for (int j = bid; j < 133; j += NB) {
            if (j < 125) {
                mma_tile_exp(g_tmh, g_tml, g_Woph, g_Wopl, j * 256, smb);
            } else {
                int q = j - 125, ch = q >> 2, nt = q & 3;
                mma_tile<128, 64>(g_sh[nxt], g_sl[nxt], 1024, g_Wph, g_Wpl, 1024,
                                  g_wsbp[ch], 512, nt * 128, ch * 512, 512, smb);
            }
        }
        gsync();

        // ---- I': yE MMA (blocks 0-99) | scale+Z + next-step energies (100-147) ----
        {
            float* po = out + (size_t)t * 64 * KY;
            if (bid < 100) {
                if (t < 63) {
                    int ch = bid >> 1, nt = bid & 1;
                    mma_tile<256, 32>(g_evh, g_evl, KY, g_Eyph, g_Eypl, KY,
                                      g_yep[ch], 512, nt * 256, ch * 640, 640, smb);
                }
            } else {
                for (int b = bid - 100; b < 64; b += 48) {
                    float z = (tid < 125) ? g_Zt[b * 128 + tid] : 0.f;
                    z = block_sum(z, s_red);
                    float inv = 1.f / z;
                    if (tid == 0) g_Zinv[b] = inv;
                    const bf* eh = g_evh + (size_t)b * KY;
                    const bf* el = g_evl + (size_t)b * KY;
                    float* pb = po + (size_t)b * KY;
                    for (int k = tid; k < KY; k += NT)
                        pb[k] = (__bfloat162float(eh[k]) + __bfloat162float(el[k])) * inv;
                    __syncthreads();
                }
                if (t < 63)
                    for (int j = bid - 100; j < 256; j += 48) energy_job(j, bvec, v, smf);
            }
        }
        gsync();
    }
}

extern "C" void kernel_launch(void* const* d_in, const int* in_sizes, int n_in,
                              void* d_out, int out_size) {
    const float* x    = (const float*)d_in[0];
    const float* Ey_t = (const float*)d_in[1];
    const float* W    = (const float*)d_in[2];
    const float* U    = (const float*)d_in[3];
    const float* bvec = (const float*)d_in[4];
    const float* v    = (const float*)d_in[5];
    const float* W_ih = (const float*)d_in[6];
    const float* W_hh = (const float*)d_in[7];
    const float* b_ih = (const float*)d_in[8];
    const float* b_hh = (const float*)d_in[9];
    const float* U_o  = (const float*)d_in[10];
    const float* V_o  = (const float*)d_in[11];
    const float* C_o  = (const float*)d_in[12];
    const float* W_o  = (const float*)d_in[13];
    float* out = (float*)d_out;

    // arena: max over variants = 110592 B (NTILE=128, KS=64)
    cudaFuncSetAttribute(dec_kernel, cudaFuncAttributeMaxDynamicSharedMemorySize, 114688);
    dec_kernel<<<NB, NT, 110592>>>(x, Ey_t, W, U, bvec, v, W_ih, W_hh, b_ih, b_hh,
                                   U_o, V_o, C_o, W_o, out);
}

// round 12
// speedup vs baseline: 3.5431x; 1.0382x over previous
#include <cuda_runtime.h>
#include <cuda_bf16.h>
#include <cuda_fp16.h>
#include <math.h>

#define NB 148
#define NT 512
#define KY 32000
typedef __nv_bfloat16 bf;
typedef __half hf;

// ---------------- device scratch ----------------
__device__ __align__(128) bf g_xh[4096*512], g_xl[4096*512];
__device__ __align__(128) bf g_Wph[512*1024], g_Wpl[512*1024];
__device__ __align__(128) bf g_Uph[512*512], g_Upl[512*512];
__device__ __align__(128) bf g_Wihh[3072*512], g_Wihl[3072*512];
__device__ __align__(128) bf g_Whhh[3072*1024], g_Whhl[3072*1024];
// fp16 single-plane weight packs (2-term output paths)
__device__ __align__(128) hf g_Uopf[1024*1024];
__device__ __align__(128) hf g_Vopf[1024*512];
__device__ __align__(128) hf g_Copf[1024*512];
__device__ __align__(128) hf g_Wopf[(size_t)KY*512];
__device__ __align__(128) hf g_Eypf[(size_t)512*KY];
// state: bf16 (3-term GRU/Wsb) + fp16 (2-term U_o)
__device__ __align__(128) bf g_sh[2][64*1024], g_sl[2][64*1024];
__device__ __align__(128) hf g_shf[2][64*1024], g_slf[2][64*1024];
__device__ __align__(128) bf g_ctxh[64*512], g_ctxl[64*512];
__device__ __align__(128) hf g_ctxhf[64*512], g_ctxlf[64*512];
__device__ __align__(128) hf g_yEhf[64*512], g_yElf[64*512];
__device__ __align__(128) hf g_tmhf[64*512], g_tmlf[64*512];
__device__ __align__(128) hf g_evhf[(size_t)64*KY], g_evlf[(size_t)64*KY];
__device__ __align__(128) float g_sf[2][64*1024];
__device__ __align__(128) float g_Uh[4096*512];
__device__ __align__(128) float g_wsbp[2][64*512];
__device__ __align__(128) float g_e[64*64];
__device__ __align__(128) float g_gip[2][64*3072];
__device__ __align__(128) float g_ghp[4][64*3072];
__device__ __align__(128) float g_tp[8][64*1024];
__device__ __align__(128) float g_yep[50][64*512];
__device__ __align__(128) float g_Zt[64*128];
__device__ __align__(128) float g_Zinv[64];

// ---------------- grid barrier ----------------
__device__ unsigned g_cnt = 0;
__device__ volatile unsigned g_gen = 0;

__device__ __forceinline__ void gsync() {
    __syncthreads();
    if (threadIdx.x == 0) {
        unsigned gen = g_gen;
        __threadfence();
        if (atomicAdd(&g_cnt, 1u) == NB - 1u) {
            atomicExch(&g_cnt, 0u);
            __threadfence();
            g_gen = gen + 1u;
        } else {
            while (g_gen == gen) __nanosleep(64);
            __threadfence();
        }
    }
    __syncthreads();
}

__device__ __forceinline__ float tanh_fast(float x) {
    float y; asm("tanh.approx.f32 %0, %1;" : "=f"(y) : "f"(x)); return y;
}

__device__ __forceinline__ void csplit(float x, bf& h, bf& l) {
    h = __float2bfloat16(x);
    l = __float2bfloat16(x - __bfloat162float(h));
}

__device__ __forceinline__ void csplitH(float x, hf& h, hf& l) {
    h = __float2half_rn(x);
    l = __float2half_rn(x - __half2float(h));
}

#define MMA(d, a0, a1, a2, a3, b0, b1)                                        \
    asm volatile("mma.sync.aligned.m16n8k16.row.col.f32.bf16.bf16.f32 "       \
                 "{%0,%1,%2,%3}, {%4,%5,%6,%7}, {%8,%9}, {%0,%1,%2,%3};"      \
                 : "+f"(d[0]), "+f"(d[1]), "+f"(d[2]), "+f"(d[3])             \
                 : "r"(a0), "r"(a1), "r"(a2), "r"(a3), "r"(b0), "r"(b1))

#define MMAH(d, a0, a1, a2, a3, b0, b1)                                       \
    asm volatile("mma.sync.aligned.m16n8k16.row.col.f32.f16.f16.f32 "         \
                 "{%0,%1,%2,%3}, {%4,%5,%6,%7}, {%8,%9}, {%0,%1,%2,%3};"      \
                 : "+f"(d[0]), "+f"(d[1]), "+f"(d[2]), "+f"(d[3])             \
                 : "r"(a0), "r"(a1), "r"(a2), "r"(a3), "r"(b0), "r"(b1))

// ------- 3-term bf16 core (A hi/lo x B hi/lo, drop AlBl): 1-deep prefetch -------
// FORCEINLINE is load-bearing: acc must stay in registers (R5/R7/R8 post-mortem).
template<int NTILE, int KS>
__device__ __forceinline__ void mma_core(
    const bf* __restrict__ Ah, const bf* __restrict__ Al, int lda,
    const bf* __restrict__ Bh, const bf* __restrict__ Bl, int ldb,
    int n0, int k0, int kc, bf* __restrict__ sm, float* acc) {
    constexpr int STR  = KS + 8;
    constexpr int CPR  = KS / 8;
    constexpr int APL  = 64 * STR;
    constexpr int BPL  = NTILE * STR;
    constexpr int ASTG = 2 * APL;
    constexpr int BSTG = 2 * BPL;
    constexpr int CA   = KS / 32;
    constexpr int CB   = (NTILE * KS) / 2048;
    constexpr int NJ   = NTILE / 32;
    constexpr int AHALF = 64 * CPR;
    constexpr int BHALF = NTILE * CPR;
    bf* sA = sm;
    bf* sB = sm + 2 * ASTG;
    const int tid = threadIdx.x;
    const int w = tid >> 5, lane = tid & 31;
    const int mr = (w & 3) << 4;
    const int nc = (w >> 2) * (NTILE / 4);
    const int fr = lane >> 2, fc = (lane & 3) << 1;
    const int aoff = (mr + fr) * STR + fc;
    const int boff = (nc + fr) * STR + fc;
#pragma unroll
    for (int i = 0; i < NJ * 4; i++) acc[i] = 0.f;

    uint4 rga[CA], rgb[CB];
    const int ns = kc / KS;

#pragma unroll
    for (int i = 0; i < CA; i++) {
        int p = tid + i * 512, hl = p / AHALF, q = p % AHALF;
        int row = q / CPR, ck = q % CPR;
        rga[i] = *(const uint4*)((hl ? Al : Ah) + (size_t)row * lda + k0 + ck * 8);
    }
#pragma unroll
    for (int i = 0; i < CB; i++) {
        int p = tid + i * 512, hl = p / BHALF, q = p % BHALF;
        int row = q / CPR, ck = q % CPR;
        rgb[i] = *(const uint4*)((hl ? Bl : Bh) + (size_t)(n0 + row) * ldb + k0 + ck * 8);
    }
#pragma unroll
    for (int i = 0; i < CA; i++) {
        int p = tid + i * 512, hl = p / AHALF, q = p % AHALF;
        int row = q / CPR, ck = q % CPR;
        *(uint4*)(sA + hl * APL + row * STR + ck * 8) = rga[i];
    }
#pragma unroll
    for (int i = 0; i < CB; i++) {
        int p = tid + i * 512, hl = p / BHALF, q = p % BHALF;
        int row = q / CPR, ck = q % CPR;
        *(uint4*)(sB + hl * BPL + row * STR + ck * 8) = rgb[i];
    }
    __syncthreads();

    int st = 0;
    for (int s = 0; s < ns; s++) {
        const bool more = s + 1 < ns;
        if (more) {
            const int kk = k0 + (s + 1) * KS;
#pragma unroll
            for (int i = 0; i < CA; i++) {
                int p = tid + i * 512, hl = p / AHALF, q = p % AHALF;
                int row = q / CPR, ck = q % CPR;
                rga[i] = *(const uint4*)((hl ? Al : Ah) + (size_t)row * lda + kk + ck * 8);
            }
#pragma unroll
            for (int i = 0; i < CB; i++) {
                int p = tid + i * 512, hl = p / BHALF, q = p % BHALF;
                int row = q / CPR, ck = q % CPR;
                rgb[i] = *(const uint4*)((hl ? Bl : Bh) + (size_t)(n0 + row) * ldb + kk + ck * 8);
            }
        }
        const bf* sAs = sA + st * ASTG;
        const bf* sBs = sB + st * BSTG;
#pragma unroll
        for (int win = 0; win < KS / 16; win++) {
            const int ko = win << 4;
            const bf* pah = sAs + aoff + ko;
            unsigned ah0 = *(const unsigned*)(pah);
            unsigned ah1 = *(const unsigned*)(pah + 8 * STR);
            unsigned ah2 = *(const unsigned*)(pah + 8);
            unsigned ah3 = *(const unsigned*)(pah + 8 * STR + 8);
            const bf* pal = pah + APL;
            unsigned al0 = *(const unsigned*)(pal);
            unsigned al1 = *(const unsigned*)(pal + 8 * STR);
            unsigned al2 = *(const unsigned*)(pal + 8);
            unsigned al3 = *(const unsigned*)(pal + 8 * STR + 8);
#pragma unroll
            for (int j = 0; j < NJ; j++) {
                const bf* pbh = sBs + boff + ko + j * 8 * STR;
                unsigned bh0 = *(const unsigned*)(pbh);
                unsigned bh1 = *(const unsigned*)(pbh + 8);
                const bf* pbl = pbh + BPL;
                unsigned bl0 = *(const unsigned*)(pbl);
                unsigned bl1 = *(const unsigned*)(pbl + 8);
                float* d = acc + j * 4;
                MMA(d, ah0, ah1, ah2, ah3, bh0, bh1);
                MMA(d, ah0, ah1, ah2, ah3, bl0, bl1);
                MMA(d, al0, al1, al2, al3, bh0, bh1);
            }
        }
        if (more) {
            const int sn = st ^ 1;
            bf* dA = sA + sn * ASTG;
            bf* dB = sB + sn * BSTG;
#pragma unroll
            for (int i = 0; i < CA; i++) {
                int p = tid + i * 512, hl = p / AHALF, q = p % AHALF;
                int row = q / CPR, ck = q % CPR;
                *(uint4*)(dA + hl * APL + row * STR + ck * 8) = rga[i];
            }
#pragma unroll
            for (int i = 0; i < CB; i++) {
                int p = tid + i * 512, hl = p / BHALF, q = p % BHALF;
                int row = q / CPR, ck = q % CPR;
                *(uint4*)(dB + hl * BPL + row * STR + ck * 8) = rgb[i];
            }
        }
        __syncthreads();
        st ^= 1;
    }
}

// ------- 2-term fp16 core ((Ah+Al) x Bh single plane): 2-deep prefetch, ns even -------
// Pointers passed as bf* (raw 16-bit lanes); MMAH interprets them as f16.
template<int NTILE, int KS>
__device__ __forceinline__ void mma_core2(
    const bf* __restrict__ Ah, const bf* __restrict__ Al, int lda,
    const bf* __restrict__ Bh, int ldb,
    int n0, int k0, int kc, bf* __restrict__ sm, float* acc) {
    constexpr int STR  = KS + 8;
    constexpr int CPR  = KS / 8;
    constexpr int APL  = 64 * STR;
    constexpr int ASTG = 2 * APL;
    constexpr int BPL  = NTILE * STR;
    constexpr int CA   = KS / 32;
    constexpr int CB   = (NTILE * KS) / 4096;
    constexpr int NJ   = NTILE / 32;
    constexpr int ACH  = 64 * CPR;
    bf* sA = sm;                  // [2][ASTG]
    bf* sB = sm + 2 * ASTG;       // [2][BPL]
    const int tid = threadIdx.x;
    const int w = tid >> 5, lane = tid & 31;
    const int mr = (w & 3) << 4;
    const int nc = (w >> 2) * (NTILE / 4);
    const int fr = lane >> 2, fc = (lane & 3) << 1;
    const int aoff = (mr + fr) * STR + fc;
    const int boff = (nc + fr) * STR + fc;
#pragma unroll
    for (int i = 0; i < NJ * 4; i++) acc[i] = 0.f;

    auto LD = [&](uint4* ra, uint4* rb, int kk) {
#pragma unroll
        for (int i = 0; i < CA; i++) {
            int p = tid + i * 512, hl = p / ACH, q = p % ACH;
            int row = q / CPR, ck = q % CPR;
            ra[i] = *(const uint4*)((hl ? Al : Ah) + (size_t)row * lda + kk + ck * 8);
        }
#pragma unroll
        for (int i = 0; i < CB; i++) {
            int p = tid + i * 512;
            int row = p / CPR, ck = p % CPR;
            rb[i] = *(const uint4*)(Bh + (size_t)(n0 + row) * ldb + kk + ck * 8);
        }
    };
    auto ST = [&](const uint4* ra, const uint4* rb, int buf) {
        bf* dA = sA + buf * ASTG;
        bf* dB = sB + buf * BPL;
#pragma unroll
        for (int i = 0; i < CA; i++) {
            int p = tid + i * 512, hl = p / ACH, q = p % ACH;
            int row = q / CPR, ck = q % CPR;
            *(uint4*)(dA + hl * APL + row * STR + ck * 8) = ra[i];
        }
#pragma unroll
        for (int i = 0; i < CB; i++) {
            int p = tid + i * 512;
            int row = p / CPR, ck = p % CPR;
            *(uint4*)(dB + row * STR + ck * 8) = rb[i];
        }
    };
    auto COMP = [&](int buf) {
        const bf* sAs = sA + buf * ASTG;
        const bf* sBs = sB + buf * BPL;
#pragma unroll
        for (int win = 0; win < KS / 16; win++) {
            const int ko = win << 4;
            const bf* pah = sAs + aoff + ko;
            unsigned ah0 = *(const unsigned*)(pah);
            unsigned ah1 = *(const unsigned*)(pah + 8 * STR);
            unsigned ah2 = *(const unsigned*)(pah + 8);
            unsigned ah3 = *(const unsigned*)(pah + 8 * STR + 8);
            const bf* pal = pah + APL;
            unsigned al0 = *(const unsigned*)(pal);
            unsigned al1 = *(const unsigned*)(pal + 8 * STR);
            unsigned al2 = *(const unsigned*)(pal + 8);
            unsigned al3 = *(const unsigned*)(pal + 8 * STR + 8);
#pragma unroll
            for (int j = 0; j < NJ; j++) {
                const bf* pbh = sBs + boff + ko + j * 8 * STR;
                unsigned bh0 = *(const unsigned*)(pbh);
                unsigned bh1 = *(const unsigned*)(pbh + 8);
                float* d = acc + j * 4;
                MMAH(d, ah0, ah1, ah2, ah3, bh0, bh1);
                MMAH(d, al0, al1, al2, al3, bh0, bh1);
            }
        }
    };

    uint4 ra0[CA], rb0[CB], ra1[CA], rb1[CB];
    const int ns = kc / KS;   // must be even
    LD(ra0, rb0, k0);
    ST(ra0, rb0, 0);
    LD(ra0, rb0, k0 + KS);
    __syncthreads();
    for (int s = 0; s < ns; s += 2) {
        if (s + 2 < ns) LD(ra1, rb1, k0 + (s + 2) * KS);
        COMP(0);
        ST(ra0, rb0, 1);
        __syncthreads();
        if (s + 3 < ns) LD(ra0, rb0, k0 + (s + 3) * KS);
        COMP(1);
        if (s + 2 < ns) ST(ra1, rb1, 0);
        __syncthreads();
    }
}

template<int NTILE, int KS>
__device__ __noinline__ void mma_tile(
    const bf* __restrict__ Ah, const bf* __restrict__ Al, int lda,
    const bf* __restrict__ Bh, const bf* __restrict__ Bl, int ldb,
    float* __restrict__ C, int ldc, int n0, int k0, int kc, bf* sm) {
    float acc[(NTILE / 32) * 4];
    mma_core<NTILE, KS>(Ah, Al, lda, Bh, Bl, ldb, n0, k0, kc, sm, acc);
    const int tid = threadIdx.x;
    const int w = tid >> 5, lane = tid & 31;
    const int mr = (w & 3) << 4;
    const int nc = (w >> 2) * (NTILE / 4);
    const int fr = lane >> 2, fc = (lane & 3) << 1;
#pragma unroll
    for (int j = 0; j < NTILE / 32; j++) {
        int col = n0 + nc + j * 8 + fc;
        float* c0 = C + (size_t)(mr + fr) * ldc + col;
        *(float2*)c0 = make_float2(acc[j*4], acc[j*4+1]);
        *(float2*)(c0 + (size_t)8 * ldc) = make_float2(acc[j*4+2], acc[j*4+3]);
    }
}

template<int NTILE, int KS>
__device__ __noinline__ void mma_tile2(
    const hf* __restrict__ Ah, const hf* __restrict__ Al, int lda,
    const hf* __restrict__ Bh, int ldb,
    float* __restrict__ C, int ldc, int n0, int k0, int kc, bf* sm) {
    float acc[(NTILE / 32) * 4];
    mma_core2<NTILE, KS>((const bf*)Ah, (const bf*)Al, lda, (const bf*)Bh, ldb,
                         n0, k0, kc, sm, acc);
    const int tid = threadIdx.x;
    const int w = tid >> 5, lane = tid & 31;
    const int mr = (w & 3) << 4;
    const int nc = (w >> 2) * (NTILE / 4);
    const int fr = lane >> 2, fc = (lane & 3) << 1;
#pragma unroll
    for (int j = 0; j < NTILE / 32; j++) {
        int col = n0 + nc + j * 8 + fc;
        float* c0 = C + (size_t)(mr + fr) * ldc + col;
        *(float2*)c0 = make_float2(acc[j*4], acc[j*4+1]);
        *(float2*)(c0 + (size_t)8 * ldc) = make_float2(acc[j*4+2], acc[j*4+3]);
    }
}

// logits 64x256 tile (fp16 2-term) -> exp into g_evhf/evlf + row sums g_Zt
__device__ __noinline__ void mma_tile_exp(
    const hf* __restrict__ Ah, const hf* __restrict__ Al,
    const hf* __restrict__ Bh, int n0, bf* sm) {
    float acc[32];
    mma_core2<256, 32>((const bf*)Ah, (const bf*)Al, 512, (const bf*)Bh, 512,
                       n0, 0, 512, sm, acc);
    const int tid = threadIdx.x;
    const int w = tid >> 5, lane = tid & 31;
    const int mr = (w & 3) << 4, nc = (w >> 2) << 6;
    const int fr = lane >> 2, fc = (lane & 3) << 1;
    float rs0 = 0.f, rs1 = 0.f;
#pragma unroll
    for (int j = 0; j < 8; j++) {
#pragma unroll
        for (int q = 0; q < 2; q++) {
            int col = n0 + nc + j * 8 + fc + q;
            float e0 = __expf(acc[j*4+q]);
            float e1 = __expf(acc[j*4+2+q]);
            rs0 += e0; rs1 += e1;
            size_t i0 = (size_t)(mr + fr) * KY + col;
            size_t i1 = i0 + (size_t)8 * KY;
            csplitH(e0, g_evhf[i0], g_evlf[i0]);
            csplitH(e1, g_evhf[i1], g_evlf[i1]);
        }
    }
    rs0 += __shfl_xor_sync(~0u, rs0, 1); rs0 += __shfl_xor_sync(~0u, rs0, 2);
    rs1 += __shfl_xor_sync(~0u, rs1, 1); rs1 += __shfl_xor_sync(~0u, rs1, 2);
    float* srs = (float*)sm;
    if ((lane & 3) == 0) { srs[w * 16 + fr] = rs0; srs[w * 16 + 8 + fr] = rs1; }
    __syncthreads();
    if (tid < 64) {
        int mg = tid >> 4, rr = tid & 15;
        float z = srs[mg * 16 + rr] + srs[(4 + mg) * 16 + rr] +
                  srs[(8 + mg) * 16 + rr] + srs[(12 + mg) * 16 + rr];
        g_Zt[tid * 128 + (n0 >> 8)] = z;
    }
    __syncthreads();
}

// attention energy job j (b = j>>2, 16 rows of e per job)
__device__ void energy_job(int j, const float* __restrict__ bvec,
                           const float* __restrict__ v, float* smf) {
    int b = j >> 2, jg = j & 3;
    int tid = threadIdx.x, lane = tid & 31;
    __syncthreads();
    smf[tid] = g_wsbp[0][b * 512 + tid] + g_wsbp[1][b * 512 + tid] + bvec[tid];
    smf[512 + tid] = v[tid];
    __syncthreads();
    int jr = jg * 16 + (tid >> 5);
    const float* uh = g_Uh + (size_t)(b * 64 + jr) * 512;
    float acc = 0.f;
    for (int c = lane; c < 512; c += 32)
        acc += tanh_fast(smf[c] + uh[c]) * smf[512 + c];
#pragma unroll
    for (int o = 16; o > 0; o >>= 1) acc += __shfl_down_sync(~0u, acc, o);
    if (lane == 0) g_e[b * 64 + jr] = acc;
}

__device__ __forceinline__ float block_sum(float v, float* red) {
#pragma unroll
    for (int o = 16; o > 0; o >>= 1) v += __shfl_down_sync(0xffffffffu, v, o);
    if ((threadIdx.x & 31) == 0) red[threadIdx.x >> 5] = v;
    __syncthreads();
    float r = 0.f;
#pragma unroll
    for (int i = 0; i < 16; i++) r += red[i];
    __syncthreads();
    return r;
}

__device__ void convN(const float* __restrict__ in, size_t n,
                      bf* __restrict__ oh, bf* __restrict__ ol, size_t gth, size_t gs) {
    for (size_t i = gth; i < n; i += gs) csplit(in[i], oh[i], ol[i]);
}

// transpose-convert fp32 -> bf16 hi/lo
__device__ void ttconv(const float* __restrict__ in, int R, int Cc,
                       bf* __restrict__ oh, bf* __restrict__ ol, float* sm) {
    int ntr = R >> 5, ntc = Cc >> 5;
    int tx = threadIdx.x & 31, ty = threadIdx.x >> 5;
    for (int tile = blockIdx.x; tile < ntr * ntc; tile += NB) {
        int tr = tile / ntc, tc = tile % ntc;
        int r0 = tr << 5, c0 = tc << 5;
        __syncthreads();
        sm[ty * 33 + tx]        = in[(size_t)(r0 + ty) * Cc + c0 + tx];
        sm[(ty + 16) * 33 + tx] = in[(size_t)(r0 + ty + 16) * Cc + c0 + tx];
        __syncthreads();
        size_t o0 = (size_t)(c0 + ty) * R + r0 + tx;
        size_t o1 = (size_t)(c0 + ty + 16) * R + r0 + tx;
        csplit(sm[tx * 33 + ty], oh[o0], ol[o0]);
        csplit(sm[tx * 33 + ty + 16], oh[o1], ol[o1]);
    }
}

// transpose-convert fp32 -> fp16 hi only
__device__ void ttconvh(const float* __restrict__ in, int R, int Cc,
                        hf* __restrict__ oh, float* sm) {
    int ntr = R >> 5, ntc = Cc >> 5;
    int tx = threadIdx.x & 31, ty = threadIdx.x >> 5;
    for (int tile = blockIdx.x; tile < ntr * ntc; tile += NB) {
        int tr = tile / ntc, tc = tile % ntc;
        int r0 = tr << 5, c0 = tc << 5;
        __syncthreads();
        sm[ty * 33 + tx]        = in[(size_t)(r0 + ty) * Cc + c0 + tx];
        sm[(ty + 16) * 33 + tx] = in[(size_t)(r0 + ty + 16) * Cc + c0 + tx];
        __syncthreads();
        size_t o0 = (size_t)(c0 + ty) * R + r0 + tx;
        size_t o1 = (size_t)(c0 + ty + 16) * R + r0 + tx;
        oh[o0] = __float2half_rn(sm[tx * 33 + ty]);
        oh[o1] = __float2half_rn(sm[tx * 33 + ty + 16]);
    }
}

__global__ __launch_bounds__(NT, 1) void dec_kernel(
    const float* __restrict__ x,    const float* __restrict__ Ey_t,
    const float* __restrict__ W,    const float* __restrict__ U,
    const float* __restrict__ bvec, const float* __restrict__ v,
    const float* __restrict__ W_ih, const float* __restrict__ W_hh,
    const float* __restrict__ b_ih, const float* __restrict__ b_hh,
    const float* __restrict__ U_o,  const float* __restrict__ V_o,
    const float* __restrict__ C_o,  const float* __restrict__ W_o,
    float* __restrict__ out) {
    extern __shared__ __align__(16) char sraw[];
    bf* smb = (bf*)sraw;
    float* smf = (float*)sraw;
    float* s_red = smf + 1024;
    const int tid = threadIdx.x, bid = blockIdx.x;
    const size_t gth = (size_t)bid * NT + tid, GS = (size_t)NB * NT;
    const bf z0 = __float2bfloat16(0.f);
    const hf h0 = __float2half_rn(0.f);

    // ---- prep wave 0: zeros + weight packing ----
    for (size_t i = gth; i < 64 * 1024; i += GS) {
        g_sf[0][i] = 0.f; g_sh[0][i] = z0; g_sl[0][i] = z0;
        g_shf[0][i] = h0; g_slf[0][i] = h0;
    }
    for (size_t i = gth; i < 64 * 512; i += GS) { g_yEhf[i] = h0; g_yElf[i] = h0; }
    convN(x, (size_t)4096 * 512, g_xh, g_xl, gth, GS);
    convN(W_ih, (size_t)3072 * 512, g_Wihh, g_Wihl, gth, GS);
    convN(W_hh, (size_t)3072 * 1024, g_Whhh, g_Whhl, gth, GS);
    ttconv(W, 1024, 512, g_Wph, g_Wpl, smf);
    ttconv(U, 512, 512, g_Uph, g_Upl, smf);
    ttconvh(U_o, 1024, 1024, g_Uopf, smf);
    ttconvh(V_o, 512, 1024, g_Vopf, smf);
    ttconvh(C_o, 512, 1024, g_Copf, smf);
    ttconvh(W_o, 512, KY, g_Wopf, smf);
    ttconvh(Ey_t, KY, 512, g_Eypf, smf);
    gsync();

    // ---- prep wave 1: U_h = x @ U (128 jobs, 3-term 256-wide) + Wsb(s0) (8 jobs) ----
    for (int j = bid; j < 136; j += NB) {
        if (j < 128) {
            int mt = j >> 1, nt = j & 1;
            mma_tile<256, 32>(g_xh + (size_t)mt * 64 * 512, g_xl + (size_t)mt * 64 * 512, 512,
                              g_Uph, g_Upl, 512,
                              g_Uh + (size_t)mt * 64 * 512, 512, nt * 256, 0, 512, smb);
        } else {
            int q = j - 128, ch = q >> 2, nt = q & 3;
            mma_tile<128, 64>(g_sh[0], g_sl[0], 1024, g_Wph, g_Wpl, 1024,
                              g_wsbp[ch], 512, nt * 128, ch * 512, 512, smb);
        }
    }
    gsync();

    // ---- prep wave 2: energies for t=0 ----
    for (int j = bid; j < 256; j += NB) energy_job(j, bvec, v, smf);
    gsync();

    for (int t = 0; t < 64; t++) {
        const int cur = t & 1, nxt = cur ^ 1;

        // ---- B2: softmax+ctx (bid<64) / yE reduce+scale (bid>=64) ----
        if (bid < 64) {
            int b = bid;
            if (tid < 64) smf[tid] = g_e[b * 64 + tid];
            __syncthreads();
            float mx = -1e30f;
#pragma unroll
            for (int j = 0; j < 64; j++) mx = fmaxf(mx, smf[j]);
            float ex = (tid < 64) ? __expf(smf[tid] - mx) : 0.f;
            __syncthreads();
            if (tid < 64) smf[64 + tid] = ex;
            __syncthreads();
            float Z = 0.f;
#pragma unroll
            for (int j = 0; j < 64; j++) Z += smf[64 + j];
            float inv = 1.f / Z;
            const float* xb = x + (size_t)b * 64 * 512;
            float ca = 0.f;
            for (int j = 0; j < 64; j++) ca += smf[64 + j] * xb[j * 512 + tid];
            float cv = ca * inv;
            csplit(cv, g_ctxh[b * 512 + tid], g_ctxl[b * 512 + tid]);
            csplitH(cv, g_ctxhf[b * 512 + tid], g_ctxlf[b * 512 + tid]);
        } else if (t > 0) {
            for (size_t i = (size_t)(bid - 64) * NT + tid; i < 64 * 512; i += (size_t)84 * NT) {
                int b = (int)(i >> 9);
                float s = 0.f;
#pragma unroll
                for (int p = 0; p < 50; p++) s += g_yep[p][i];
                csplitH(s * g_Zinv[b], g_yEhf[i], g_yElf[i]);
            }
        }
        gsync();

        // ---- C: gi (48 jobs) + gh (96 jobs), 3-term bf16 (recurrent precision) ----
        for (int j = bid; j < 144; j += NB) {
            if (j < 48) {
                int ch = j / 24, nt = j % 24;
                mma_tile<128, 64>(g_ctxh, g_ctxl, 512, g_Wihh, g_Wihl, 512,
                                  g_gip[ch], 3072, nt * 128, ch * 256, 256, smb);
            } else {
                int q = j - 48, ch = q / 24, nt = q % 24;
                mma_tile<128, 64>(g_sh[cur], g_sl[cur], 1024, g_Whhh, g_Whhl, 1024,
                                  g_ghp[ch], 3072, nt * 128, ch * 256, 256, smb);
            }
        }
        gsync();

        // ---- D: V_o/C_o MMA (blocks 0-31, fp16 2-term) | gate combine (32-147) ----
        if (bid < 32) {
            if (bid < 16) {
                int ch = bid >> 3, nt = bid & 7;
                mma_tile2<128, 64>(g_yEhf, g_yElf, 512, g_Vopf, 512,
                                   g_tp[4 + ch], 1024, nt * 128, ch * 256, 256, smb);
            } else {
                int q = bid - 16, ch = q >> 3, nt = q & 7;
                mma_tile2<128, 64>(g_ctxhf, g_ctxlf, 512, g_Copf, 512,
                                   g_tp[6 + ch], 1024, nt * 128, ch * 256, 256, smb);
            }
        } else {
            for (size_t i = (size_t)(bid - 32) * NT + tid; i < 64 * 1024; i += (size_t)116 * NT) {
                int b = (int)(i >> 10), h = (int)(i & 1023);
                size_t bs = (size_t)b * 3072;
                float gr = b_ih[h], gz = b_ih[1024 + h], gn = b_ih[2048 + h];
                float hr = b_hh[h], hz = b_hh[1024 + h], hn = b_hh[2048 + h];
#pragma unroll
                for (int p = 0; p < 2; p++) {
                    gr += g_gip[p][bs + h];
                    gz += g_gip[p][bs + 1024 + h];
                    gn += g_gip[p][bs + 2048 + h];
                }
#pragma unroll
                for (int p = 0; p < 4; p++) {
                    hr += g_ghp[p][bs + h];
                    hz += g_ghp[p][bs + 1024 + h];
                    hn += g_ghp[p][bs + 2048 + h];
                }
                float r = 1.f / (1.f + __expf(-(gr + hr)));
                float zz = 1.f / (1.f + __expf(-(gz + hz)));
                float n = tanhf(gn + r * hn);
                float sn = (1.f - zz) * n + zz * g_sf[cur][i];
                g_sf[nxt][i] = sn;
                csplit(sn, g_sh[nxt][i], g_sl[nxt][i]);
                csplitH(sn, g_shf[nxt][i], g_slf[nxt][i]);
            }
        }
        gsync();

        // ---- E: U_o partials (32 jobs, fp16 2-term) ----
        for (int j = bid; j < 32; j += NB) {
            int ch = j >> 3, nt = j & 7;
            mma_tile2<128, 64>(g_shf[nxt], g_slf[nxt], 1024, g_Uopf, 1024,
                               g_tp[ch], 1024, nt * 128, ch * 256, 256, smb);
        }
        gsync();

        // ---- F: maxout ----
        for (size_t i = gth; i < 64 * 512; i += GS) {
            int b = (int)(i >> 9), d = (int)(i & 511);
            size_t base = (size_t)b * 1024 + 2 * d;
            float t0 = 0.f, t1 = 0.f;
#pragma unroll
            for (int p = 0; p < 8; p++) { t0 += g_tp[p][base]; t1 += g_tp[p][base + 1]; }
            csplitH(fmaxf(t0, t1), g_tmhf[i], g_tmlf[i]);
        }
        gsync();

        // ---- G: logits+exp+Zt (125 jobs, fp16 2-term 256-wide) + Wsb t+1 (8 jobs) ----
        for (int j = bid; j < 133; j += NB) {
            if (j < 125) {
                mma_tile_exp(g_tmhf, g_tmlf, g_Wopf, j * 256, smb);
            } else {
                int q = j - 125, ch = q >> 2, nt = q & 3;
                mma_tile<128, 64>(g_sh[nxt], g_sl[nxt], 1024, g_Wph, g_Wpl, 1024,
                                  g_wsbp[ch], 512, nt * 128, ch * 512, 512, smb);
            }
        }
        gsync();

        // ---- I': yE MMA (blocks 0-99, fp16 2-term) | scale+Z + next energies ----
        {
            float* po = out + (size_t)t * 64 * KY;
            if (bid < 100) {
                if (t < 63) {
                    int ch = bid >> 1, nt = bid & 1;
                    mma_tile2<256, 32>(g_evhf, g_evlf, KY, g_Eypf, KY,
                                       g_yep[ch], 512, nt * 256, ch * 640, 640, smb);
                }
            } else {
                for (int b = bid - 100; b < 64; b += 48) {
                    float z = (tid < 125) ? g_Zt[b * 128 + tid] : 0.f;
                    z = block_sum(z, s_red);
                    float inv = 1.f / z;
                    if (tid == 0) g_Zinv[b] = inv;
                    const hf* eh = g_evhf + (size_t)b * KY;
                    const hf* el = g_evlf + (size_t)b * KY;
                    float* pb = po + (size_t)b * KY;
                    for (int k = tid; k < KY; k += NT)
                        pb[k] = (__half2float(eh[k]) + __half2float(el[k])) * inv;
                    __syncthreads();
                }
                if (t < 63)
                    for (int j = bid - 100; j < 256; j += 48) energy_job(j, bvec, v, smf);
            }
        }
        gsync();
    }
}

extern "C" void kernel_launch(void* const* d_in, const int* in_sizes, int n_in,
                              void* d_out, int out_size) {
    const float* x    = (const float*)d_in[0];
    const float* Ey_t = (const float*)d_in[1];
    const float* W    = (const float*)d_in[2];
    const float* U    = (const float*)d_in[3];
    const float* bvec = (const float*)d_in[4];
    const float* v    = (const float*)d_in[5];
    const float* W_ih = (const float*)d_in[6];
    const float* W_hh = (const float*)d_in[7];
    const float* b_ih = (const float*)d_in[8];
    const float* b_hh = (const float*)d_in[9];
    const float* U_o  = (const float*)d_in[10];
    const float* V_o  = (const float*)d_in[11];
    const float* C_o  = (const float*)d_in[12];
    const float* W_o  = (const float*)d_in[13];
    float* out = (float*)d_out;

    // arena: max over variants = 110592 B (NTILE=128, KS=64, 3-term)
    cudaFuncSetAttribute(dec_kernel, cudaFuncAttributeMaxDynamicSharedMemorySize, 114688);
    dec_kernel<<<NB, NT, 110592>>>(x, Ey_t, W, U, bvec, v, W_ih, W_hh, b_ih, b_hh,
                                   U_o, V_o, C_o, W_o, out);
}

// round 13
// speedup vs baseline: 3.5432x; 1.0000x over previous
#include <cuda_runtime.h>
#include <cuda_bf16.h>
#include <cuda_fp16.h>
#include <math.h>

#define NB 148
#define NT 512
#define KY 32000
typedef __nv_bfloat16 bf;
typedef __half hf;

// ---------------- device scratch ----------------
__device__ __align__(128) bf g_xh[4096*512], g_xl[4096*512];
__device__ __align__(128) bf g_Wph[512*1024], g_Wpl[512*1024];
__device__ __align__(128) bf g_Uph[512*512], g_Upl[512*512];
__device__ __align__(128) bf g_Wihh[3072*512], g_Wihl[3072*512];
__device__ __align__(128) bf g_Whhh[3072*1024], g_Whhl[3072*1024];
// fp16 single-plane weight packs (2-term output paths)
__device__ __align__(128) hf g_Uopf[1024*1024];
__device__ __align__(128) hf g_Vopf[1024*512];
__device__ __align__(128) hf g_Copf[1024*512];
__device__ __align__(128) hf g_Wopf[(size_t)KY*512];
__device__ __align__(128) hf g_Eypf[(size_t)512*KY];
// state: bf16 (3-term GRU/Wsb) + fp16 (2-term U_o)
__device__ __align__(128) bf g_sh[2][64*1024], g_sl[2][64*1024];
__device__ __align__(128) hf g_shf[2][64*1024], g_slf[2][64*1024];
__device__ __align__(128) bf g_ctxh[64*512], g_ctxl[64*512];
__device__ __align__(128) hf g_ctxhf[64*512], g_ctxlf[64*512];
__device__ __align__(128) hf g_yEhf[64*512], g_yElf[64*512];
__device__ __align__(128) hf g_tmhf[64*512], g_tmlf[64*512];
__device__ __align__(128) hf g_evhf[(size_t)64*KY], g_evlf[(size_t)64*KY];
__device__ __align__(128) float g_sf[2][64*1024];
__device__ __align__(128) float g_Uh[4096*512];
__device__ __align__(128) float g_wsbp[2][64*512];
__device__ __align__(128) float g_e[64*64];
__device__ __align__(128) float g_gip[2][64*3072];
__device__ __align__(128) float g_ghp[4][64*3072];
__device__ __align__(128) float g_tp[8][64*1024];
__device__ __align__(128) float g_yep[50][64*512];
__device__ __align__(128) float g_Zt[64*128];
__device__ __align__(128) float g_Zinv[64];

// ---------------- grid barrier ----------------
__device__ unsigned g_cnt = 0;
__device__ volatile unsigned g_gen = 0;

__device__ __forceinline__ void gsync() {
    __syncthreads();
    if (threadIdx.x == 0) {
        unsigned gen = g_gen;
        __threadfence();
        if (atomicAdd(&g_cnt, 1u) == NB - 1u) {
            atomicExch(&g_cnt, 0u);
            __threadfence();
            g_gen = gen + 1u;
        } else {
            while (g_gen == gen) __nanosleep(64);
            __threadfence();
        }
    }
    __syncthreads();
}

__device__ __forceinline__ float tanh_fast(float x) {
    float y; asm("tanh.approx.f32 %0, %1;" : "=f"(y) : "f"(x)); return y;
}

__device__ __forceinline__ void csplit(float x, bf& h, bf& l) {
    h = __float2bfloat16(x);
    l = __float2bfloat16(x - __bfloat162float(h));
}

__device__ __forceinline__ void csplitH(float x, hf& h, hf& l) {
    h = __float2half_rn(x);
    l = __float2half_rn(x - __half2float(h));
}

__device__ __forceinline__ void cpa16(bf* s, const bf* g) {
    unsigned sa = (unsigned)__cvta_generic_to_shared(s);
    asm volatile("cp.async.cg.shared.global [%0], [%1], 16;" :: "r"(sa), "l"(g));
}

#define MMA(d, a0, a1, a2, a3, b0, b1)                                        \
    asm volatile("mma.sync.aligned.m16n8k16.row.col.f32.bf16.bf16.f32 "       \
                 "{%0,%1,%2,%3}, {%4,%5,%6,%7}, {%8,%9}, {%0,%1,%2,%3};"      \
                 : "+f"(d[0]), "+f"(d[1]), "+f"(d[2]), "+f"(d[3])             \
                 : "r"(a0), "r"(a1), "r"(a2), "r"(a3), "r"(b0), "r"(b1))

#define MMAH(d, a0, a1, a2, a3, b0, b1)                                       \
    asm volatile("mma.sync.aligned.m16n8k16.row.col.f32.f16.f16.f32 "         \
                 "{%0,%1,%2,%3}, {%4,%5,%6,%7}, {%8,%9}, {%0,%1,%2,%3};"      \
                 : "+f"(d[0]), "+f"(d[1]), "+f"(d[2]), "+f"(d[3])             \
                 : "r"(a0), "r"(a1), "r"(a2), "r"(a3), "r"(b0), "r"(b1))

// ------- 3-term bf16 core (A hi/lo x B hi/lo, drop AlBl): 1-deep reg prefetch -------
// FORCEINLINE is load-bearing: acc must stay in registers (R5/R7/R8 post-mortem).
template<int NTILE, int KS>
__device__ __forceinline__ void mma_core(
    const bf* __restrict__ Ah, const bf* __restrict__ Al, int lda,
    const bf* __restrict__ Bh, const bf* __restrict__ Bl, int ldb,
    int n0, int k0, int kc, bf* __restrict__ sm, float* acc) {
    constexpr int STR  = KS + 8;
    constexpr int CPR  = KS / 8;
    constexpr int APL  = 64 * STR;
    constexpr int BPL  = NTILE * STR;
    constexpr int ASTG = 2 * APL;
    constexpr int BSTG = 2 * BPL;
    constexpr int CA   = KS / 32;
    constexpr int CB   = (NTILE * KS) / 2048;
    constexpr int NJ   = NTILE / 32;
    constexpr int AHALF = 64 * CPR;
    constexpr int BHALF = NTILE * CPR;
    bf* sA = sm;
    bf* sB = sm + 2 * ASTG;
    const int tid = threadIdx.x;
    const int w = tid >> 5, lane = tid & 31;
    const int mr = (w & 3) << 4;
    const int nc = (w >> 2) * (NTILE / 4);
    const int fr = lane >> 2, fc = (lane & 3) << 1;
    const int aoff = (mr + fr) * STR + fc;
    const int boff = (nc + fr) * STR + fc;
#pragma unroll
    for (int i = 0; i < NJ * 4; i++) acc[i] = 0.f;

    uint4 rga[CA], rgb[CB];
    const int ns = kc / KS;

#pragma unroll
    for (int i = 0; i < CA; i++) {
        int p = tid + i * 512, hl = p / AHALF, q = p % AHALF;
        int row = q / CPR, ck = q % CPR;
        rga[i] = *(const uint4*)((hl ? Al : Ah) + (size_t)row * lda + k0 + ck * 8);
    }
#pragma unroll
    for (int i = 0; i < CB; i++) {
        int p = tid + i * 512, hl = p / BHALF, q = p % BHALF;
        int row = q / CPR, ck = q % CPR;
        rgb[i] = *(const uint4*)((hl ? Bl : Bh) + (size_t)(n0 + row) * ldb + k0 + ck * 8);
    }
#pragma unroll
    for (int i = 0; i < CA; i++) {
        int p = tid + i * 512, hl = p / AHALF, q = p % AHALF;
        int row = q / CPR, ck = q % CPR;
        *(uint4*)(sA + hl * APL + row * STR + ck * 8) = rga[i];
    }
#pragma unroll
    for (int i = 0; i < CB; i++) {
        int p = tid + i * 512, hl = p / BHALF, q = p % BHALF;
        int row = q / CPR, ck = q % CPR;
        *(uint4*)(sB + hl * BPL + row * STR + ck * 8) = rgb[i];
    }
    __syncthreads();

    int st = 0;
    for (int s = 0; s < ns; s++) {
        const bool more = s + 1 < ns;
        if (more) {
            const int kk = k0 + (s + 1) * KS;
#pragma unroll
            for (int i = 0; i < CA; i++) {
                int p = tid + i * 512, hl = p / AHALF, q = p % AHALF;
                int row = q / CPR, ck = q % CPR;
                rga[i] = *(const uint4*)((hl ? Al : Ah) + (size_t)row * lda + kk + ck * 8);
            }
#pragma unroll
            for (int i = 0; i < CB; i++) {
                int p = tid + i * 512, hl = p / BHALF, q = p % BHALF;
                int row = q / CPR, ck = q % CPR;
                rgb[i] = *(const uint4*)((hl ? Bl : Bh) + (size_t)(n0 + row) * ldb + kk + ck * 8);
            }
        }
        const bf* sAs = sA + st * ASTG;
        const bf* sBs = sB + st * BSTG;
#pragma unroll
        for (int win = 0; win < KS / 16; win++) {
            const int ko = win << 4;
            const bf* pah = sAs + aoff + ko;
            unsigned ah0 = *(const unsigned*)(pah);
            unsigned ah1 = *(const unsigned*)(pah + 8 * STR);
            unsigned ah2 = *(const unsigned*)(pah + 8);
            unsigned ah3 = *(const unsigned*)(pah + 8 * STR + 8);
            const bf* pal = pah + APL;
            unsigned al0 = *(const unsigned*)(pal);
            unsigned al1 = *(const unsigned*)(pal + 8 * STR);
            unsigned al2 = *(const unsigned*)(pal + 8);
            unsigned al3 = *(const unsigned*)(pal + 8 * STR + 8);
#pragma unroll
            for (int j = 0; j < NJ; j++) {
                const bf* pbh = sBs + boff + ko + j * 8 * STR;
                unsigned bh0 = *(const unsigned*)(pbh);
                unsigned bh1 = *(const unsigned*)(pbh + 8);
                const bf* pbl = pbh + BPL;
                unsigned bl0 = *(const unsigned*)(pbl);
                unsigned bl1 = *(const unsigned*)(pbl + 8);
                float* d = acc + j * 4;
                MMA(d, ah0, ah1, ah2, ah3, bh0, bh1);
                MMA(d, ah0, ah1, ah2, ah3, bl0, bl1);
                MMA(d, al0, al1, al2, al3, bh0, bh1);
            }
        }
        if (more) {
            const int sn = st ^ 1;
            bf* dA = sA + sn * ASTG;
            bf* dB = sB + sn * BSTG;
#pragma unroll
            for (int i = 0; i < CA; i++) {
                int p = tid + i * 512, hl = p / AHALF, q = p % AHALF;
                int row = q / CPR, ck = q % CPR;
                *(uint4*)(dA + hl * APL + row * STR + ck * 8) = rga[i];
            }
#pragma unroll
            for (int i = 0; i < CB; i++) {
                int p = tid + i * 512, hl = p / BHALF, q = p % BHALF;
                int row = q / CPR, ck = q % CPR;
                *(uint4*)(dB + hl * BPL + row * STR + ck * 8) = rgb[i];
            }
        }
        __syncthreads();
        st ^= 1;
    }
}

// ------- 2-term fp16 core ((Ah+Al) x Bh): cp.async 4-stage ring, KS=32 -------
// Loads bypass registers into a 4-slot smem ring; wait_group 2 keeps 3 stages
// in flight. Raw 16-bit pointers; MMAH interprets as f16.
template<int NTILE>
__device__ __forceinline__ void mma_core2(
    const bf* __restrict__ Ah, const bf* __restrict__ Al, int lda,
    const bf* __restrict__ Bh, int ldb,
    int n0, int k0, int kc, bf* __restrict__ sm, float* acc) {
    constexpr int STR = 40;
    constexpr int APL = 64 * 40;        // 2560 el per A plane
    constexpr int AST = 2 * APL;        // 5120 el (hi+lo)
    constexpr int BST = NTILE * 40;
    constexpr int SST = AST + BST;      // slot stride (elements)
    constexpr int NJ  = NTILE / 32;
    const int tid = threadIdx.x;
    const int w = tid >> 5, lane = tid & 31;
    const int mr = (w & 3) << 4;
    const int nc = (w >> 2) * (NTILE / 4);
    const int fr = lane >> 2, fc = (lane & 3) << 1;
    const int aoff = (mr + fr) * STR + fc;
    const int boff = (nc + fr) * STR + fc;
#pragma unroll
    for (int i = 0; i < NJ * 4; i++) acc[i] = 0.f;

    // A: 512 chunks (2 planes x 64 rows x 4), exactly one per thread
    const int ahl  = tid >> 8;
    const int arow = (tid & 255) >> 2;
    const int ack  = tid & 3;
    const bf* Ag = (ahl ? Al : Ah) + (size_t)arow * lda + k0 + ack * 8;
    const unsigned adst = (unsigned)(ahl * APL + arow * STR + ack * 8);

    const int ns = kc >> 5;
#pragma unroll
    for (int s = 0; s < 3; s++) {
        if (s < ns) {
            bf* base = sm + (s & 3) * SST;
            cpa16(base + adst, Ag + s * 32);
#pragma unroll
            for (int i = 0; i < NTILE / 128; i++) {
                int p = tid + i * 512, row = p >> 2, ck = p & 3;
                cpa16(base + AST + row * STR + ck * 8,
                      Bh + (size_t)(n0 + row) * ldb + k0 + s * 32 + ck * 8);
            }
        }
        asm volatile("cp.async.commit_group;" ::: "memory");
    }
    for (int s = 0; s < ns; s++) {
        asm volatile("cp.async.wait_group 2;" ::: "memory");
        __syncthreads();
        if (s + 3 < ns) {
            bf* base = sm + ((s + 3) & 3) * SST;
            cpa16(base + adst, Ag + (s + 3) * 32);
#pragma unroll
            for (int i = 0; i < NTILE / 128; i++) {
                int p = tid + i * 512, row = p >> 2, ck = p & 3;
                cpa16(base + AST + row * STR + ck * 8,
                      Bh + (size_t)(n0 + row) * ldb + k0 + (s + 3) * 32 + ck * 8);
            }
        }
        asm volatile("cp.async.commit_group;" ::: "memory");
        const bf* sAs = sm + (s & 3) * SST;
        const bf* sBs = sAs + AST;
#pragma unroll
        for (int win = 0; win < 2; win++) {
            const int ko = win << 4;
            const bf* pah = sAs + aoff + ko;
            unsigned ah0 = *(const unsigned*)(pah);
            unsigned ah1 = *(const unsigned*)(pah + 8 * STR);
            unsigned ah2 = *(const unsigned*)(pah + 8);
            unsigned ah3 = *(const unsigned*)(pah + 8 * STR + 8);
            const bf* pal = pah + APL;
            unsigned al0 = *(const unsigned*)(pal);
            unsigned al1 = *(const unsigned*)(pal + 8 * STR);
            unsigned al2 = *(const unsigned*)(pal + 8);
            unsigned al3 = *(const unsigned*)(pal + 8 * STR + 8);
#pragma unroll
            for (int j = 0; j < NJ; j++) {
                const bf* pbh = sBs + boff + ko + j * 8 * STR;
                unsigned bh0 = *(const unsigned*)(pbh);
                unsigned bh1 = *(const unsigned*)(pbh + 8);
                float* d = acc + j * 4;
                MMAH(d, ah0, ah1, ah2, ah3, bh0, bh1);
                MMAH(d, al0, al1, al2, al3, bh0, bh1);
            }
        }
    }
    __syncthreads();
}

template<int NTILE, int KS>
__device__ __noinline__ void mma_tile(
    const bf* __restrict__ Ah, const bf* __restrict__ Al, int lda,
    const bf* __restrict__ Bh, const bf* __restrict__ Bl, int ldb,
    float* __restrict__ C, int ldc, int n0, int k0, int kc, bf* sm) {
    float acc[(NTILE / 32) * 4];
    mma_core<NTILE, KS>(Ah, Al, lda, Bh, Bl, ldb, n0, k0, kc, sm, acc);
    const int tid = threadIdx.x;
    const int w = tid >> 5, lane = tid & 31;
    const int mr = (w & 3) << 4;
    const int nc = (w >> 2) * (NTILE / 4);
    const int fr = lane >> 2, fc = (lane & 3) << 1;
#pragma unroll
    for (int j = 0; j < NTILE / 32; j++) {
        int col = n0 + nc + j * 8 + fc;
        float* c0 = C + (size_t)(mr + fr) * ldc + col;
        *(float2*)c0 = make_float2(acc[j*4], acc[j*4+1]);
        *(float2*)(c0 + (size_t)8 * ldc) = make_float2(acc[j*4+2], acc[j*4+3]);
    }
}

template<int NTILE>
__device__ __noinline__ void mma_tile2(
    const hf* __restrict__ Ah, const hf* __restrict__ Al, int lda,
    const hf* __restrict__ Bh, int ldb,
    float* __restrict__ C, int ldc, int n0, int k0, int kc, bf* sm) {
    float acc[(NTILE / 32) * 4];
    mma_core2<NTILE>((const bf*)Ah, (const bf*)Al, lda, (const bf*)Bh, ldb,
                     n0, k0, kc, sm, acc);
    const int tid = threadIdx.x;
    const int w = tid >> 5, lane = tid & 31;
    const int mr = (w & 3) << 4;
    const int nc = (w >> 2) * (NTILE / 4);
    const int fr = lane >> 2, fc = (lane & 3) << 1;
#pragma unroll
    for (int j = 0; j < NTILE / 32; j++) {
        int col = n0 + nc + j * 8 + fc;
        float* c0 = C + (size_t)(mr + fr) * ldc + col;
        *(float2*)c0 = make_float2(acc[j*4], acc[j*4+1]);
        *(float2*)(c0 + (size_t)8 * ldc) = make_float2(acc[j*4+2], acc[j*4+3]);
    }
}

// logits 64x256 tile (fp16 2-term) -> exp into g_evhf/evlf + row sums g_Zt
__device__ __noinline__ void mma_tile_exp(
    const hf* __restrict__ Ah, const hf* __restrict__ Al,
    const hf* __restrict__ Bh, int n0, bf* sm) {
    float acc[32];
    mma_core2<256>((const bf*)Ah, (const bf*)Al, 512, (const bf*)Bh, 512,
                   n0, 0, 512, sm, acc);
    const int tid = threadIdx.x;
    const int w = tid >> 5, lane = tid & 31;
    const int mr = (w & 3) << 4, nc = (w >> 2) << 6;
    const int fr = lane >> 2, fc = (lane & 3) << 1;
    float rs0 = 0.f, rs1 = 0.f;
#pragma unroll
    for (int j = 0; j < 8; j++) {
#pragma unroll
        for (int q = 0; q < 2; q++) {
            int col = n0 + nc + j * 8 + fc + q;
            float e0 = __expf(acc[j*4+q]);
            float e1 = __expf(acc[j*4+2+q]);
            rs0 += e0; rs1 += e1;
            size_t i0 = (size_t)(mr + fr) * KY + col;
            size_t i1 = i0 + (size_t)8 * KY;
            csplitH(e0, g_evhf[i0], g_evlf[i0]);
            csplitH(e1, g_evhf[i1], g_evlf[i1]);
        }
    }
    rs0 += __shfl_xor_sync(~0u, rs0, 1); rs0 += __shfl_xor_sync(~0u, rs0, 2);
    rs1 += __shfl_xor_sync(~0u, rs1, 1); rs1 += __shfl_xor_sync(~0u, rs1, 2);
    float* srs = (float*)sm;
    if ((lane & 3) == 0) { srs[w * 16 + fr] = rs0; srs[w * 16 + 8 + fr] = rs1; }
    __syncthreads();
    if (tid < 64) {
        int mg = tid >> 4, rr = tid & 15;
        float z = srs[mg * 16 + rr] + srs[(4 + mg) * 16 + rr] +
                  srs[(8 + mg) * 16 + rr] + srs[(12 + mg) * 16 + rr];
        g_Zt[tid * 128 + (n0 >> 8)] = z;
    }
    __syncthreads();
}

// attention energy job j (b = j>>2, 16 rows of e per job)
__device__ void energy_job(int j, const float* __restrict__ bvec,
                           const float* __restrict__ v, float* smf) {
    int b = j >> 2, jg = j & 3;
    int tid = threadIdx.x, lane = tid & 31;
    __syncthreads();
    smf[tid] = g_wsbp[0][b * 512 + tid] + g_wsbp[1][b * 512 + tid] + bvec[tid];
    smf[512 + tid] = v[tid];
    __syncthreads();
    int jr = jg * 16 + (tid >> 5);
    const float* uh = g_Uh + (size_t)(b * 64 + jr) * 512;
    float acc = 0.f;
    for (int c = lane; c < 512; c += 32)
        acc += tanh_fast(smf[c] + uh[c]) * smf[512 + c];
#pragma unroll
    for (int o = 16; o > 0; o >>= 1) acc += __shfl_down_sync(~0u, acc, o);
    if (lane == 0) g_e[b * 64 + jr] = acc;
}

__device__ __forceinline__ float block_sum(float v, float* red) {
#pragma unroll
    for (int o = 16; o > 0; o >>= 1) v += __shfl_down_sync(0xffffffffu, v, o);
    if ((threadIdx.x & 31) == 0) red[threadIdx.x >> 5] = v;
    __syncthreads();
    float r = 0.f;
#pragma unroll
    for (int i = 0; i < 16; i++) r += red[i];
    __syncthreads();
    return r;
}

__device__ void convN(const float* __restrict__ in, size_t n,
                      bf* __restrict__ oh, bf* __restrict__ ol, size_t gth, size_t gs) {
    for (size_t i = gth; i < n; i += gs) csplit(in[i], oh[i], ol[i]);
}

// transpose-convert fp32 -> bf16 hi/lo
__device__ void ttconv(const float* __restrict__ in, int R, int Cc,
                       bf* __restrict__ oh, bf* __restrict__ ol, float* sm) {
    int ntr = R >> 5, ntc = Cc >> 5;
    int tx = threadIdx.x & 31, ty = threadIdx.x >> 5;
    for (int tile = blockIdx.x; tile < ntr * ntc; tile += NB) {
        int tr = tile / ntc, tc = tile % ntc;
        int r0 = tr << 5, c0 = tc << 5;
        __syncthreads();
        sm[ty * 33 + tx]        = in[(size_t)(r0 + ty) * Cc + c0 + tx];
        sm[(ty + 16) * 33 + tx] = in[(size_t)(r0 + ty + 16) * Cc + c0 + tx];
        __syncthreads();
        size_t o0 = (size_t)(c0 + ty) * R + r0 + tx;
        size_t o1 = (size_t)(c0 + ty + 16) * R + r0 + tx;
        csplit(sm[tx * 33 + ty], oh[o0], ol[o0]);
        csplit(sm[tx * 33 + ty + 16], oh[o1], ol[o1]);
    }
}

// transpose-convert fp32 -> fp16 hi only
__device__ void ttconvh(const float* __restrict__ in, int R, int Cc,
                        hf* __restrict__ oh, float* sm) {
    int ntr = R >> 5, ntc = Cc >> 5;
    int tx = threadIdx.x & 31, ty = threadIdx.x >> 5;
    for (int tile = blockIdx.x; tile < ntr * ntc; tile += NB) {
        int tr = tile / ntc, tc = tile % ntc;
        int r0 = tr << 5, c0 = tc << 5;
        __syncthreads();
        sm[ty * 33 + tx]        = in[(size_t)(r0 + ty) * Cc + c0 + tx];
        sm[(ty + 16) * 33 + tx] = in[(size_t)(r0 + ty + 16) * Cc + c0 + tx];
        __syncthreads();
        size_t o0 = (size_t)(c0 + ty) * R + r0 + tx;
        size_t o1 = (size_t)(c0 + ty + 16) * R + r0 + tx;
        oh[o0] = __float2half_rn(sm[tx * 33 + ty]);
        oh[o1] = __float2half_rn(sm[tx * 33 + ty + 16]);
    }
}

__global__ __launch_bounds__(NT, 1) void dec_kernel(
    const float* __restrict__ x,    const float* __restrict__ Ey_t,
    const float* __restrict__ W,    const float* __restrict__ U,
    const float* __restrict__ bvec, const float* __restrict__ v,
    const float* __restrict__ W_ih, const float* __restrict__ W_hh,
    const float* __restrict__ b_ih, const float* __restrict__ b_hh,
    const float* __restrict__ U_o,  const float* __restrict__ V_o,
    const float* __restrict__ C_o,  const float* __restrict__ W_o,
    float* __restrict__ out) {
    extern __shared__ __align__(16) char sraw[];
    bf* smb = (bf*)sraw;
    float* smf = (float*)sraw;
    float* s_red = smf + 1024;
    const int tid = threadIdx.x, bid = blockIdx.x;
    const size_t gth = (size_t)bid * NT + tid, GS = (size_t)NB * NT;
    const bf z0 = __float2bfloat16(0.f);
    const hf h0 = __float2half_rn(0.f);

    // ---- prep wave 0: zeros + weight packing ----
    for (size_t i = gth; i < 64 * 1024; i += GS) {
        g_sf[0][i] = 0.f; g_sh[0][i] = z0; g_sl[0][i] = z0;
        g_shf[0][i] = h0; g_slf[0][i] = h0;
    }
    for (size_t i = gth; i < 64 * 512; i += GS) { g_yEhf[i] = h0; g_yElf[i] = h0; }
    convN(x, (size_t)4096 * 512, g_xh, g_xl, gth, GS);
    convN(W_ih, (size_t)3072 * 512, g_Wihh, g_Wihl, gth, GS);
    convN(W_hh, (size_t)3072 * 1024, g_Whhh, g_Whhl, gth, GS);
    ttconv(W, 1024, 512, g_Wph, g_Wpl, smf);
    ttconv(U, 512, 512, g_Uph, g_Upl, smf);
    ttconvh(U_o, 1024, 1024, g_Uopf, smf);
    ttconvh(V_o, 512, 1024, g_Vopf, smf);
    ttconvh(C_o, 512, 1024, g_Copf, smf);
    ttconvh(W_o, 512, KY, g_Wopf, smf);
    ttconvh(Ey_t, KY, 512, g_Eypf, smf);
    gsync();

    // ---- prep wave 1: U_h = x @ U (128 jobs, 3-term 256-wide) + Wsb(s0) (8 jobs) ----
    for (int j = bid; j < 136; j += NB) {
        if (j < 128) {
            int mt = j >> 1, nt = j & 1;
            mma_tile<256, 32>(g_xh + (size_t)mt * 64 * 512, g_xl + (size_t)mt * 64 * 512, 512,
                              g_Uph, g_Upl, 512,
                              g_Uh + (size_t)mt * 64 * 512, 512, nt * 256, 0, 512, smb);
        } else {
            int q = j - 128, ch = q >> 2, nt = q & 3;
            mma_tile<128, 64>(g_sh[0], g_sl[0], 1024, g_Wph, g_Wpl, 1024,
                              g_wsbp[ch], 512, nt * 128, ch * 512, 512, smb);
        }
    }
    gsync();

    // ---- prep wave 2: energies for t=0 ----
    for (int j = bid; j < 256; j += NB) energy_job(j, bvec, v, smf);
    gsync();

    for (int t = 0; t < 64; t++) {
        const int cur = t & 1, nxt = cur ^ 1;

        // ---- B2: softmax+ctx (bid<64) / yE reduce+scale (bid>=64) ----
        if (bid < 64) {
            int b = bid;
            if (tid < 64) smf[tid] = g_e[b * 64 + tid];
            __syncthreads();
            float mx = -1e30f;
#pragma unroll
            for (int j = 0; j < 64; j++) mx = fmaxf(mx, smf[j]);
            float ex = (tid < 64) ? __expf(smf[tid] - mx) : 0.f;
            __syncthreads();
            if (tid < 64) smf[64 + tid] = ex;
            __syncthreads();
            float Z = 0.f;
#pragma unroll
            for (int j = 0; j < 64; j++) Z += smf[64 + j];
            float inv = 1.f / Z;
            const float* xb = x + (size_t)b * 64 * 512;
            float ca = 0.f;
            for (int j = 0; j < 64; j++) ca += smf[64 + j] * xb[j * 512 + tid];
            float cv = ca * inv;
            csplit(cv, g_ctxh[b * 512 + tid], g_ctxl[b * 512 + tid]);
            csplitH(cv, g_ctxhf[b * 512 + tid], g_ctxlf[b * 512 + tid]);
        } else if (t > 0) {
            for (size_t i = (size_t)(bid - 64) * NT + tid; i < 64 * 512; i += (size_t)84 * NT) {
                int b = (int)(i >> 9);
                float s = 0.f;
#pragma unroll
                for (int p = 0; p < 50; p++) s += g_yep[p][i];
                csplitH(s * g_Zinv[b], g_yEhf[i], g_yElf[i]);
            }
        }
        gsync();

        // ---- C: gi (48 jobs) + gh (96 jobs), 3-term bf16 (recurrent precision) ----
        for (int j = bid; j < 144; j += NB) {
            if (j < 48) {
                int ch = j / 24, nt = j % 24;
                mma_tile<128, 64>(g_ctxh, g_ctxl, 512, g_Wihh, g_Wihl, 512,
                                  g_gip[ch], 3072, nt * 128, ch * 256, 256, smb);
            } else {
                int q = j - 48, ch = q / 24, nt = q % 24;
                mma_tile<128, 64>(g_sh[cur], g_sl[cur], 1024, g_Whhh, g_Whhl, 1024,
                                  g_ghp[ch], 3072, nt * 128, ch * 256, 256, smb);
            }
        }
        gsync();

        // ---- D: V_o/C_o MMA (blocks 0-31, fp16 2-term) | gate combine (32-147) ----
        if (bid < 32) {
            if (bid < 16) {
                int ch = bid >> 3, nt = bid & 7;
                mma_tile2<128>(g_yEhf, g_yElf, 512, g_Vopf, 512,
                               g_tp[4 + ch], 1024, nt * 128, ch * 256, 256, smb);
            } else {
                int q = bid - 16, ch = q >> 3, nt = q & 7;
                mma_tile2<128>(g_ctxhf, g_ctxlf, 512, g_Copf, 512,
                               g_tp[6 + ch], 1024, nt * 128, ch * 256, 256, smb);
            }
        } else {
            for (size_t i = (size_t)(bid - 32) * NT + tid; i < 64 * 1024; i += (size_t)116 * NT) {
                int b = (int)(i >> 10), h = (int)(i & 1023);
                size_t bs = (size_t)b * 3072;
                float gr = b_ih[h], gz = b_ih[1024 + h], gn = b_ih[2048 + h];
                float hr = b_hh[h], hz = b_hh[1024 + h], hn = b_hh[2048 + h];
#pragma unroll
                for (int p = 0; p < 2; p++) {
                    gr += g_gip[p][bs + h];
                    gz += g_gip[p][bs + 1024 + h];
                    gn += g_gip[p][bs + 2048 + h];
                }
#pragma unroll
                for (int p = 0; p < 4; p++) {
                    hr += g_ghp[p][bs + h];
                    hz += g_ghp[p][bs + 1024 + h];
                    hn += g_ghp[p][bs + 2048 + h];
                }
                float r = 1.f / (1.f + __expf(-(gr + hr)));
                float zz = 1.f / (1.f + __expf(-(gz + hz)));
                float n = tanhf(gn + r * hn);
                float sn = (1.f - zz) * n + zz * g_sf[cur][i];
                g_sf[nxt][i] = sn;
                csplit(sn, g_sh[nxt][i], g_sl[nxt][i]);
                csplitH(sn, g_shf[nxt][i], g_slf[nxt][i]);
            }
        }
        gsync();

        // ---- E: U_o partials (32 jobs, fp16 2-term) ----
        for (int j = bid; j < 32; j += NB) {
            int ch = j >> 3, nt = j & 7;
            mma_tile2<128>(g_shf[nxt], g_slf[nxt], 1024, g_Uopf, 1024,
                           g_tp[ch], 1024, nt * 128, ch * 256, 256, smb);
        }
        gsync();

        // ---- F: maxout ----
        for (size_t i = gth; i < 64 * 512; i += GS) {
            int b = (int)(i >> 9), d = (int)(i & 511);
            size_t base = (size_t)b * 1024 + 2 * d;
            float t0 = 0.f, t1 = 0.f;
#pragma unroll
            for (int p = 0; p < 8; p++) { t0 += g_tp[p][base]; t1 += g_tp[p][base + 1]; }
            csplitH(fmaxf(t0, t1), g_tmhf[i], g_tmlf[i]);
        }
        gsync();

        // ---- G: logits+exp+Zt (125 jobs, fp16 2-term 256-wide) + Wsb t+1 (8 jobs) ----
        for (int j = bid; j < 133; j += NB) {
            if (j < 125) {
                mma_tile_exp(g_tmhf, g_tmlf, g_Wopf, j * 256, smb);
            } else {
                int q = j - 125, ch = q >> 2, nt = q & 3;
                mma_tile<128, 64>(g_sh[nxt], g_sl[nxt], 1024, g_Wph, g_Wpl, 1024,
                                  g_wsbp[ch], 512, nt * 128, ch * 512, 512, smb);
            }
        }
        gsync();

        // ---- I': yE MMA (blocks 0-99, fp16 2-term) | scale+Z + next energies ----
        {
            float* po = out + (size_t)t * 64 * KY;
            if (bid < 100) {
                if (t < 63) {
                    int ch = bid >> 1, nt = bid & 1;
                    mma_tile2<256>(g_evhf, g_evlf, KY, g_Eypf, KY,
                                   g_yep[ch], 512, nt * 256, ch * 640, 640, smb);
                }
            } else {
                for (int b = bid - 100; b < 64; b += 48) {
                    float z = (tid < 125) ? g_Zt[b * 128 + tid] : 0.f;
                    z = block_sum(z, s_red);
                    float inv = 1.f / z;
                    if (tid == 0) g_Zinv[b] = inv;
                    const hf* eh = g_evhf + (size_t)b * KY;
                    const hf* el = g_evlf + (size_t)b * KY;
                    float* pb = po + (size_t)b * KY;
                    for (int k = tid; k < KY; k += NT)
                        pb[k] = (__half2float(eh[k]) + __half2float(el[k])) * inv;
                    __syncthreads();
                }
                if (t < 63)
                    for (int j = bid - 100; j < 256; j += 48) energy_job(j, bvec, v, smf);
            }
        }
        gsync();
    }
}

extern "C" void kernel_launch(void* const* d_in, const int* in_sizes, int n_in,
                              void* d_out, int out_size) {
    const float* x    = (const float*)d_in[0];
    const float* Ey_t = (const float*)d_in[1];
    const float* W    = (const float*)d_in[2];
    const float* U    = (const float*)d_in[3];
    const float* bvec = (const float*)d_in[4];
    const float* v    = (const float*)d_in[5];
    const float* W_ih = (const float*)d_in[6];
    const float* W_hh = (const float*)d_in[7];
    const float* b_ih = (const float*)d_in[8];
    const float* b_hh = (const float*)d_in[9];
    const float* U_o  = (const float*)d_in[10];
    const float* V_o  = (const float*)d_in[11];
    const float* C_o  = (const float*)d_in[12];
    const float* W_o  = (const float*)d_in[13];
    float* out = (float*)d_out;

    // arena: max(3-term KS=64: 110592B, cp.async 2-term NTILE=256: 4*30720 = 122880B)
    cudaFuncSetAttribute(dec_kernel, cudaFuncAttributeMaxDynamicSharedMemorySize, 131072);
    dec_kernel<<<NB, NT, 122880>>>(x, Ey_t, W, U, bvec, v, W_ih, W_hh, b_ih, b_hh,
                                   U_o, V_o, C_o, W_o, out);
}

// round 15
// speedup vs baseline: 3.6937x; 1.0425x over previous
#include <cuda_runtime.h>
#include <cuda_bf16.h>
#include <cuda_fp16.h>
#include <math.h>

#define NB 148
#define NT 512
#define KY 32000
typedef __nv_bfloat16 bf;
typedef __half hf;

// ---------------- device scratch ----------------
__device__ __align__(128) bf g_xh[4096*512], g_xl[4096*512];
__device__ __align__(128) bf g_Wph[512*1024], g_Wpl[512*1024];
__device__ __align__(128) bf g_Uph[512*512], g_Upl[512*512];
__device__ __align__(128) bf g_Wihh[3072*512], g_Wihl[3072*512];
__device__ __align__(128) bf g_Whhh[3072*1024], g_Whhl[3072*1024];
__device__ __align__(128) hf g_Uopf[1024*1024];
__device__ __align__(128) hf g_Vopf[1024*512];
__device__ __align__(128) hf g_Copf[1024*512];
__device__ __align__(128) hf g_Wopf[(size_t)KY*512];
__device__ __align__(128) hf g_Eypf[(size_t)512*KY];
__device__ __align__(128) bf g_sh[2][64*1024], g_sl[2][64*1024];
__device__ __align__(128) hf g_shf[2][64*1024], g_slf[2][64*1024];
__device__ __align__(128) bf g_ctxh[64*512], g_ctxl[64*512];
__device__ __align__(128) hf g_ctxhf[64*512], g_ctxlf[64*512];
__device__ __align__(128) hf g_yEhf[64*512], g_yElf[64*512];
__device__ __align__(128) hf g_tmhf[64*512], g_tmlf[64*512];
__device__ __align__(128) hf g_evhf[(size_t)64*KY], g_evlf[(size_t)64*KY];
__device__ __align__(128) float g_sf[2][64*1024];
__device__ __align__(128) float g_Uh[4096*512];
__device__ __align__(128) float g_wsbp[2][64*512];
__device__ __align__(128) float g_e[64*64];
__device__ __align__(128) float g_gip[2][64*3072];
__device__ __align__(128) float g_ghp[4][64*3072];
__device__ __align__(128) float g_tp[8][64*1024];
__device__ __align__(128) float g_yep[50][64*512];
__device__ __align__(128) float g_Zt[64*128];
__device__ __align__(128) float g_Zinv[64];

// ---------------- grid barrier ----------------
__device__ unsigned g_cnt = 0;
__device__ volatile unsigned g_gen = 0;

__device__ __forceinline__ void gsync() {
    __syncthreads();
    if (threadIdx.x == 0) {
        unsigned gen = g_gen;
        __threadfence();
        if (atomicAdd(&g_cnt, 1u) == NB - 1u) {
            atomicExch(&g_cnt, 0u);
            __threadfence();
            g_gen = gen + 1u;
        } else {
            while (g_gen == gen) __nanosleep(64);
            __threadfence();
        }
    }
    __syncthreads();
}

__device__ __forceinline__ float tanh_fast(float x) {
    float y; asm("tanh.approx.f32 %0, %1;" : "=f"(y) : "f"(x)); return y;
}

// FMA-pipe exp: 2^k * e^r, k = rint(x*log2e), r = x - k*ln2 (|r| <= 0.3466).
// Degree-5 Taylor: rel err <= 2.4e-6. Zero MUFU.
__device__ __forceinline__ float fexp(float x) {
    float kf = rintf(x * 1.44269504088896f);
    kf = fmaxf(-120.f, fminf(120.f, kf));
    float r = fmaf(kf, -0.693147180559945f, x);
    float p = 8.3333333e-3f;                 // 1/120
    p = fmaf(p, r, 4.1666667e-2f);           // 1/24
    p = fmaf(p, r, 1.6666667e-1f);           // 1/6
    p = fmaf(p, r, 0.5f);
    p = fmaf(p, r, 1.f);
    p = fmaf(p, r, 1.f);
    float s = __int_as_float(((int)kf + 127) << 23);
    return p * s;
}

__device__ __forceinline__ void csplit(float x, bf& h, bf& l) {
    h = __float2bfloat16(x);
    l = __float2bfloat16(x - __bfloat162float(h));
}

__device__ __forceinline__ void csplitH(float x, hf& h, hf& l) {
    h = __float2half_rn(x);
    l = __float2half_rn(x - __half2float(h));
}

__device__ __forceinline__ void cpa16(bf* s, const bf* g) {
    unsigned sa = (unsigned)__cvta_generic_to_shared(s);
    asm volatile("cp.async.cg.shared.global [%0], [%1], 16;" :: "r"(sa), "l"(g));
}

#define MMA(d, a0, a1, a2, a3, b0, b1)                                        \
    asm volatile("mma.sync.aligned.m16n8k16.row.col.f32.bf16.bf16.f32 "       \
                 "{%0,%1,%2,%3}, {%4,%5,%6,%7}, {%8,%9}, {%0,%1,%2,%3};"      \
                 : "+f"(d[0]), "+f"(d[1]), "+f"(d[2]), "+f"(d[3])             \
                 : "r"(a0), "r"(a1), "r"(a2), "r"(a3), "r"(b0), "r"(b1))

#define MMAH(d, a0, a1, a2, a3, b0, b1)                                       \
    asm volatile("mma.sync.aligned.m16n8k16.row.col.f32.f16.f16.f32 "         \
                 "{%0,%1,%2,%3}, {%4,%5,%6,%7}, {%8,%9}, {%0,%1,%2,%3};"      \
                 : "+f"(d[0]), "+f"(d[1]), "+f"(d[2]), "+f"(d[3])             \
                 : "r"(a0), "r"(a1), "r"(a2), "r"(a3), "r"(b0), "r"(b1))

// ------- 3-term bf16 core: 1-deep reg prefetch (FORCEINLINE load-bearing) -------
template<int NTILE, int KS>
__device__ __forceinline__ void mma_core(
    const bf* __restrict__ Ah, const bf* __restrict__ Al, int lda,
    const bf* __restrict__ Bh, const bf* __restrict__ Bl, int ldb,
    int n0, int k0, int kc, bf* __restrict__ sm, float* acc) {
    constexpr int STR  = KS + 8;
    constexpr int CPR  = KS / 8;
    constexpr int APL  = 64 * STR;
    constexpr int BPL  = NTILE * STR;
    constexpr int ASTG = 2 * APL;
    constexpr int BSTG = 2 * BPL;
    constexpr int CA   = KS / 32;
    constexpr int CB   = (NTILE * KS) / 2048;
    constexpr int NJ   = NTILE / 32;
    constexpr int AHALF = 64 * CPR;
    constexpr int BHALF = NTILE * CPR;
    bf* sA = sm;
    bf* sB = sm + 2 * ASTG;
    const int tid = threadIdx.x;
    const int w = tid >> 5, lane = tid & 31;
    const int mr = (w & 3) << 4;
    const int nc = (w >> 2) * (NTILE / 4);
    const int fr = lane >> 2, fc = (lane & 3) << 1;
    const int aoff = (mr + fr) * STR + fc;
    const int boff = (nc + fr) * STR + fc;
#pragma unroll
    for (int i = 0; i < NJ * 4; i++) acc[i] = 0.f;

    uint4 rga[CA], rgb[CB];
    const int ns = kc / KS;

#pragma unroll
    for (int i = 0; i < CA; i++) {
        int p = tid + i * 512, hl = p / AHALF, q = p % AHALF;
        int row = q / CPR, ck = q % CPR;
        rga[i] = *(const uint4*)((hl ? Al : Ah) + (size_t)row * lda + k0 + ck * 8);
    }
#pragma unroll
    for (int i = 0; i < CB; i++) {
        int p = tid + i * 512, hl = p / BHALF, q = p % BHALF;
        int row = q / CPR, ck = q % CPR;
        rgb[i] = *(const uint4*)((hl ? Bl : Bh) + (size_t)(n0 + row) * ldb + k0 + ck * 8);
    }
#pragma unroll
    for (int i = 0; i < CA; i++) {
        int p = tid + i * 512, hl = p / AHALF, q = p % AHALF;
        int row = q / CPR, ck = q % CPR;
        *(uint4*)(sA + hl * APL + row * STR + ck * 8) = rga[i];
    }
#pragma unroll
    for (int i = 0; i < CB; i++) {
        int p = tid + i * 512, hl = p / BHALF, q = p % BHALF;
        int row = q / CPR, ck = q % CPR;
        *(uint4*)(sB + hl * BPL + row * STR + ck * 8) = rgb[i];
    }
    __syncthreads();

    int st = 0;
    for (int s = 0; s < ns; s++) {
        const bool more = s + 1 < ns;
        if (more) {
            const int kk = k0 + (s + 1) * KS;
#pragma unroll
            for (int i = 0; i < CA; i++) {
                int p = tid + i * 512, hl = p / AHALF, q = p % AHALF;
                int row = q / CPR, ck = q % CPR;
                rga[i] = *(const uint4*)((hl ? Al : Ah) + (size_t)row * lda + kk + ck * 8);
            }
#pragma unroll
            for (int i = 0; i < CB; i++) {
                int p = tid + i * 512, hl = p / BHALF, q = p % BHALF;
                int row = q / CPR, ck = q % CPR;
                rgb[i] = *(const uint4*)((hl ? Bl : Bh) + (size_t)(n0 + row) * ldb + kk + ck * 8);
            }
        }
        const bf* sAs = sA + st * ASTG;
        const bf* sBs = sB + st * BSTG;
#pragma unroll
        for (int win = 0; win < KS / 16; win++) {
            const int ko = win << 4;
            const bf* pah = sAs + aoff + ko;
            unsigned ah0 = *(const unsigned*)(pah);
            unsigned ah1 = *(const unsigned*)(pah + 8 * STR);
            unsigned ah2 = *(const unsigned*)(pah + 8);
            unsigned ah3 = *(const unsigned*)(pah + 8 * STR + 8);
            const bf* pal = pah + APL;
            unsigned al0 = *(const unsigned*)(pal);
            unsigned al1 = *(const unsigned*)(pal + 8 * STR);
            unsigned al2 = *(const unsigned*)(pal + 8);
            unsigned al3 = *(const unsigned*)(pal + 8 * STR + 8);
#pragma unroll
            for (int j = 0; j < NJ; j++) {
                const bf* pbh = sBs + boff + ko + j * 8 * STR;
                unsigned bh0 = *(const unsigned*)(pbh);
                unsigned bh1 = *(const unsigned*)(pbh + 8);
                const bf* pbl = pbh + BPL;
                unsigned bl0 = *(const unsigned*)(pbl);
                unsigned bl1 = *(const unsigned*)(pbl + 8);
                float* d = acc + j * 4;
                MMA(d, ah0, ah1, ah2, ah3, bh0, bh1);
                MMA(d, ah0, ah1, ah2, ah3, bl0, bl1);
                MMA(d, al0, al1, al2, al3, bh0, bh1);
            }
        }
        if (more) {
            const int sn = st ^ 1;
            bf* dA = sA + sn * ASTG;
            bf* dB = sB + sn * BSTG;
#pragma unroll
            for (int i = 0; i < CA; i++) {
                int p = tid + i * 512, hl = p / AHALF, q = p % AHALF;
                int row = q / CPR, ck = q % CPR;
                *(uint4*)(dA + hl * APL + row * STR + ck * 8) = rga[i];
            }
#pragma unroll
            for (int i = 0; i < CB; i++) {
                int p = tid + i * 512, hl = p / BHALF, q = p % BHALF;
                int row = q / CPR, ck = q % CPR;
                *(uint4*)(dB + hl * BPL + row * STR + ck * 8) = rgb[i];
            }
        }
        __syncthreads();
        st ^= 1;
    }
}

// ------- 2-term fp16 core: cp.async 4-stage ring, KS=32 -------
template<int NTILE>
__device__ __forceinline__ void mma_core2(
    const bf* __restrict__ Ah, const bf* __restrict__ Al, int lda,
    const bf* __restrict__ Bh, int ldb,
    int n0, int k0, int kc, bf* __restrict__ sm, float* acc) {
    constexpr int STR = 40;
    constexpr int APL = 64 * 40;
    constexpr int AST = 2 * APL;
    constexpr int BST = NTILE * 40;
    constexpr int SST = AST + BST;
    constexpr int NJ  = NTILE / 32;
    const int tid = threadIdx.x;
    const int w = tid >> 5, lane = tid & 31;
    const int mr = (w & 3) << 4;
    const int nc = (w >> 2) * (NTILE / 4);
    const int fr = lane >> 2, fc = (lane & 3) << 1;
    const int aoff = (mr + fr) * STR + fc;
    const int boff = (nc + fr) * STR + fc;
#pragma unroll
    for (int i = 0; i < NJ * 4; i++) acc[i] = 0.f;

    const int ahl  = tid >> 8;
    const int arow = (tid & 255) >> 2;
    const int ack  = tid & 3;
    const bf* Ag = (ahl ? Al : Ah) + (size_t)arow * lda + k0 + ack * 8;
    const unsigned adst = (unsigned)(ahl * APL + arow * STR + ack * 8);

    const int ns = kc >> 5;
#pragma unroll
    for (int s = 0; s < 3; s++) {
        if (s < ns) {
            bf* base = sm + (s & 3) * SST;
            cpa16(base + adst, Ag + s * 32);
#pragma unroll
            for (int i = 0; i < NTILE / 128; i++) {
                int p = tid + i * 512, row = p >> 2, ck = p & 3;
                cpa16(base + AST + row * STR + ck * 8,
                      Bh + (size_t)(n0 + row) * ldb + k0 + s * 32 + ck * 8);
            }
        }
        asm volatile("cp.async.commit_group;" ::: "memory");
    }
    for (int s = 0; s < ns; s++) {
        asm volatile("cp.async.wait_group 2;" ::: "memory");
        __syncthreads();
        if (s + 3 < ns) {
            bf* base = sm + ((s + 3) & 3) * SST;
            cpa16(base + adst, Ag + (s + 3) * 32);
#pragma unroll
            for (int i = 0; i < NTILE / 128; i++) {
                int p = tid + i * 512, row = p >> 2, ck = p & 3;
                cpa16(base + AST + row * STR + ck * 8,
                      Bh + (size_t)(n0 + row) * ldb + k0 + (s + 3) * 32 + ck * 8);
            }
        }
        asm volatile("cp.async.commit_group;" ::: "memory");
        const bf* sAs = sm + (s & 3) * SST;
        const bf* sBs = sAs + AST;
#pragma unroll
        for (int win = 0; win < 2; win++) {
            const int ko = win << 4;
            const bf* pah = sAs + aoff + ko;
            unsigned ah0 = *(const unsigned*)(pah);
            unsigned ah1 = *(const unsigned*)(pah + 8 * STR);
            unsigned ah2 = *(const unsigned*)(pah + 8);
            unsigned ah3 = *(const unsigned*)(pah + 8 * STR + 8);
            const bf* pal = pah + APL;
            unsigned al0 = *(const unsigned*)(pal);
            unsigned al1 = *(const unsigned*)(pal + 8 * STR);
            unsigned al2 = *(const unsigned*)(pal + 8);
            unsigned al3 = *(const unsigned*)(pal + 8 * STR + 8);
#pragma unroll
            for (int j = 0; j < NJ; j++) {
                const bf* pbh = sBs + boff + ko + j * 8 * STR;
                unsigned bh0 = *(const unsigned*)(pbh);
                unsigned bh1 = *(const unsigned*)(pbh + 8);
                float* d = acc + j * 4;
                MMAH(d, ah0, ah1, ah2, ah3, bh0, bh1);
                MMAH(d, al0, al1, al2, al3, bh0, bh1);
            }
        }
    }
    __syncthreads();
}

template<int NTILE, int KS>
__device__ __noinline__ void mma_tile(
    const bf* __restrict__ Ah, const bf* __restrict__ Al, int lda,
    const bf* __restrict__ Bh, const bf* __restrict__ Bl, int ldb,
    float* __restrict__ C, int ldc, int n0, int k0, int kc, bf* sm) {
    float acc[(NTILE / 32) * 4];
    mma_core<NTILE, KS>(Ah, Al, lda, Bh, Bl, ldb, n0, k0, kc, sm, acc);
    const int tid = threadIdx.x;
    const int w = tid >> 5, lane = tid & 31;
    const int mr = (w & 3) << 4;
    const int nc = (w >> 2) * (NTILE / 4);
    const int fr = lane >> 2, fc = (lane & 3) << 1;
#pragma unroll
    for (int j = 0; j < NTILE / 32; j++) {
        int col = n0 + nc + j * 8 + fc;
        float* c0 = C + (size_t)(mr + fr) * ldc + col;
        *(float2*)c0 = make_float2(acc[j*4], acc[j*4+1]);
        *(float2*)(c0 + (size_t)8 * ldc) = make_float2(acc[j*4+2], acc[j*4+3]);
    }
}

template<int NTILE>
__device__ __noinline__ void mma_tile2(
    const hf* __restrict__ Ah, const hf* __restrict__ Al, int lda,
    const hf* __restrict__ Bh, int ldb,
    float* __restrict__ C, int ldc, int n0, int k0, int kc, bf* sm) {
    float acc[(NTILE / 32) * 4];
    mma_core2<NTILE>((const bf*)Ah, (const bf*)Al, lda, (const bf*)Bh, ldb,
                     n0, k0, kc, sm, acc);
    const int tid = threadIdx.x;
    const int w = tid >> 5, lane = tid & 31;
    const int mr = (w & 3) << 4;
    const int nc = (w >> 2) * (NTILE / 4);
    const int fr = lane >> 2, fc = (lane & 3) << 1;
#pragma unroll
    for (int j = 0; j < NTILE / 32; j++) {
        int col = n0 + nc + j * 8 + fc;
        float* c0 = C + (size_t)(mr + fr) * ldc + col;
        *(float2*)c0 = make_float2(acc[j*4], acc[j*4+1]);
        *(float2*)(c0 + (size_t)8 * ldc) = make_float2(acc[j*4+2], acc[j*4+3]);
    }
}

// logits 64x256 tile -> exp (FMA-pipe fexp) into g_evhf/evlf + row sums g_Zt
__device__ __noinline__ void mma_tile_exp(
    const hf* __restrict__ Ah, const hf* __restrict__ Al,
    const hf* __restrict__ Bh, int n0, bf* sm) {
    float acc[32];
    mma_core2<256>((const bf*)Ah, (const bf*)Al, 512, (const bf*)Bh, 512,
                   n0, 0, 512, sm, acc);
    const int tid = threadIdx.x;
    const int w = tid >> 5, lane = tid & 31;
    const int mr = (w & 3) << 4, nc = (w >> 2) << 6;
    const int fr = lane >> 2, fc = (lane & 3) << 1;
    float rs0 = 0.f, rs1 = 0.f;
#pragma unroll
    for (int j = 0; j < 8; j++) {
#pragma unroll
        for (int q = 0; q < 2; q++) {
            int col = n0 + nc + j * 8 + fc + q;
            float e0 = fexp(acc[j*4+q]);
            float e1 = fexp(acc[j*4+2+q]);
            rs0 += e0; rs1 += e1;
            size_t i0 = (size_t)(mr + fr) * KY + col;
            size_t i1 = i0 + (size_t)8 * KY;
            csplitH(e0, g_evhf[i0], g_evlf[i0]);
            csplitH(e1, g_evhf[i1], g_evlf[i1]);
        }
    }
    rs0 += __shfl_xor_sync(~0u, rs0, 1); rs0 += __shfl_xor_sync(~0u, rs0, 2);
    rs1 += __shfl_xor_sync(~0u, rs1, 1); rs1 += __shfl_xor_sync(~0u, rs1, 2);
    float* srs = (float*)sm;
    if ((lane & 3) == 0) { srs[w * 16 + fr] = rs0; srs[w * 16 + 8 + fr] = rs1; }
    __syncthreads();
    if (tid < 64) {
        int mg = tid >> 4, rr = tid & 15;
        float z = srs[mg * 16 + rr] + srs[(4 + mg) * 16 + rr] +
                  srs[(8 + mg) * 16 + rr] + srs[(12 + mg) * 16 + rr];
        g_Zt[tid * 128 + (n0 >> 8)] = z;
    }
    __syncthreads();
}

// attention energy job j (b = j>>2, 16 rows of e per job)
__device__ void energy_job(int j, const float* __restrict__ bvec,
                           const float* __restrict__ v, float* smf) {
    int b = j >> 2, jg = j & 3;
    int tid = threadIdx.x, lane = tid & 31;
    __syncthreads();
    smf[tid] = g_wsbp[0][b * 512 + tid] + g_wsbp[1][b * 512 + tid] + bvec[tid];
    smf[512 + tid] = v[tid];
    __syncthreads();
    int jr = jg * 16 + (tid >> 5);
    const float* uh = g_Uh + (size_t)(b * 64 + jr) * 512;
    float acc = 0.f;
    for (int c = lane; c < 512; c += 32)
        acc += tanh_fast(smf[c] + uh[c]) * smf[512 + c];
#pragma unroll
    for (int o = 16; o > 0; o >>= 1) acc += __shfl_down_sync(~0u, acc, o);
    if (lane == 0) g_e[b * 64 + jr] = acc;
}

__device__ __forceinline__ float block_sum(float v, float* red) {
#pragma unroll
    for (int o = 16; o > 0; o >>= 1) v += __shfl_down_sync(0xffffffffu, v, o);
    if ((threadIdx.x & 31) == 0) red[threadIdx.x >> 5] = v;
    __syncthreads();
    float r = 0.f;
#pragma unroll
    for (int i = 0; i < 16; i++) r += red[i];
    __syncthreads();
    return r;
}

__device__ void convN(const float* __restrict__ in, size_t n,
                      bf* __restrict__ oh, bf* __restrict__ ol, size_t gth, size_t gs) {
    for (size_t i = gth; i < n; i += gs) csplit(in[i], oh[i], ol[i]);
}

__device__ void ttconv(const float* __restrict__ in, int R, int Cc,
                       bf* __restrict__ oh, bf* __restrict__ ol, float* sm) {
    int ntr = R >> 5, ntc = Cc >> 5;
    int tx = threadIdx.x & 31, ty = threadIdx.x >> 5;
    for (int tile = blockIdx.x; tile < ntr * ntc; tile += NB) {
        int tr = tile / ntc, tc = tile % ntc;
        int r0 = tr << 5, c0 = tc << 5;
        __syncthreads();
        sm[ty * 33 + tx]        = in[(size_t)(r0 + ty) * Cc + c0 + tx];
        sm[(ty + 16) * 33 + tx] = in[(size_t)(r0 + ty + 16) * Cc + c0 + tx];
        __syncthreads();
        size_t o0 = (size_t)(c0 + ty) * R + r0 + tx;
        size_t o1 = (size_t)(c0 + ty + 16) * R + r0 + tx;
        csplit(sm[tx * 33 + ty], oh[o0], ol[o0]);
        csplit(sm[tx * 33 + ty + 16], oh[o1], ol[o1]);
    }
}

__device__ void ttconvh(const float* __restrict__ in, int R, int Cc,
                        hf* __restrict__ oh, float* sm) {
    int ntr = R >> 5, ntc = Cc >> 5;
    int tx = threadIdx.x & 31, ty = threadIdx.x >> 5;
    for (int tile = blockIdx.x; tile < ntr * ntc; tile += NB) {
        int tr = tile / ntc, tc = tile % ntc;
        int r0 = tr << 5, c0 = tc << 5;
        __syncthreads();
        sm[ty * 33 + tx]        = in[(size_t)(r0 + ty) * Cc + c0 + tx];
        sm[(ty + 16) * 33 + tx] = in[(size_t)(r0 + ty + 16) * Cc + c0 + tx];
        __syncthreads();
        size_t o0 = (size_t)(c0 + ty) * R + r0 + tx;
        size_t o1 = (size_t)(c0 + ty + 16) * R + r0 + tx;
        oh[o0] = __float2half_rn(sm[tx * 33 + ty]);
        oh[o1] = __float2half_rn(sm[tx * 33 + ty + 16]);
    }
}

__global__ __launch_bounds__(NT, 1) void dec_kernel(
    const float* __restrict__ x,    const float* __restrict__ Ey_t,
    const float* __restrict__ W,    const float* __restrict__ U,
    const float* __restrict__ bvec, const float* __restrict__ v,
    const float* __restrict__ W_ih, const float* __restrict__ W_hh,
    const float* __restrict__ b_ih, const float* __restrict__ b_hh,
    const float* __restrict__ U_o,  const float* __restrict__ V_o,
    const float* __restrict__ C_o,  const float* __restrict__ W_o,
    float* __restrict__ out) {
    extern __shared__ __align__(16) char sraw[];
    bf* smb = (bf*)sraw;
    float* smf = (float*)sraw;
    float* s_red = smf + 1024;
    const int tid = threadIdx.x, bid = blockIdx.x;
    const size_t gth = (size_t)bid * NT + tid, GS = (size_t)NB * NT;
    const bf z0 = __float2bfloat16(0.f);
    const hf h0 = __float2half_rn(0.f);

    // ---- prep wave 0 ----
    for (size_t i = gth; i < 64 * 1024; i += GS) {
        g_sf[0][i] = 0.f; g_sh[0][i] = z0; g_sl[0][i] = z0;
        g_shf[0][i] = h0; g_slf[0][i] = h0;
    }
    for (size_t i = gth; i < 64 * 512; i += GS) { g_yEhf[i] = h0; g_yElf[i] = h0; }
    convN(x, (size_t)4096 * 512, g_xh, g_xl, gth, GS);
    convN(W_ih, (size_t)3072 * 512, g_Wihh, g_Wihl, gth, GS);
    convN(W_hh, (size_t)3072 * 1024, g_Whhh, g_Whhl, gth, GS);
    ttconv(W, 1024, 512, g_Wph, g_Wpl, smf);
    ttconv(U, 512, 512, g_Uph, g_Upl, smf);
    ttconvh(U_o, 1024, 1024, g_Uopf, smf);
    ttconvh(V_o, 512, 1024, g_Vopf, smf);
    ttconvh(C_o, 512, 1024, g_Copf, smf);
    ttconvh(W_o, 512, KY, g_Wopf, smf);
    ttconvh(Ey_t, KY, 512, g_Eypf, smf);
    gsync();

    // ---- prep wave 1: U_h (128 jobs) + Wsb(s0) (8 jobs) ----
    for (int j = bid; j < 136; j += NB) {
        if (j < 128) {
            int mt = j >> 1, nt = j & 1;
            mma_tile<256, 32>(g_xh + (size_t)mt * 64 * 512, g_xl + (size_t)mt * 64 * 512, 512,
                              g_Uph, g_Upl, 512,
                              g_Uh + (size_t)mt * 64 * 512, 512, nt * 256, 0, 512, smb);
        } else {
            int q = j - 128, ch = q >> 2, nt = q & 3;
            mma_tile<128, 64>(g_sh[0], g_sl[0], 1024, g_Wph, g_Wpl, 1024,
                              g_wsbp[ch], 512, nt * 128, ch * 512, 512, smb);
        }
    }
    gsync();

    // ---- prep wave 2: energies for t=0 ----
    for (int j = bid; j < 256; j += NB) energy_job(j, bvec, v, smf);
    gsync();

    for (int t = 0; t < 64; t++) {
        const int cur = t & 1, nxt = cur ^ 1;

        // ---- B2: softmax+ctx (bid<64) / yE reduce+scale (bid>=64) ----
        if (bid < 64) {
            int b = bid;
            if (tid < 64) smf[tid] = g_e[b * 64 + tid];
            __syncthreads();
            float mx = -1e30f;
#pragma unroll
            for (int j = 0; j < 64; j++) mx = fmaxf(mx, smf[j]);
            float ex = (tid < 64) ? __expf(smf[tid] - mx) : 0.f;
            __syncthreads();
            if (tid < 64) smf[64 + tid] = ex;
            __syncthreads();
            float Z = 0.f;
#pragma unroll
            for (int j = 0; j < 64; j++) Z += smf[64 + j];
            float inv = 1.f / Z;
            const float* xb = x + (size_t)b * 64 * 512;
            float ca = 0.f;
            for (int j = 0; j < 64; j++) ca += smf[64 + j] * xb[j * 512 + tid];
            float cv = ca * inv;
            csplit(cv, g_ctxh[b * 512 + tid], g_ctxl[b * 512 + tid]);
            csplitH(cv, g_ctxhf[b * 512 + tid], g_ctxlf[b * 512 + tid]);
        } else if (t > 0) {
            for (size_t i = (size_t)(bid - 64) * NT + tid; i < 64 * 512; i += (size_t)84 * NT) {
                int b = (int)(i >> 9);
                float s = 0.f;
#pragma unroll
                for (int p = 0; p < 50; p++) s += g_yep[p][i];
                csplitH(s * g_Zinv[b], g_yEhf[i], g_yElf[i]);
            }
        }
        gsync();

        // ---- C: gi (48 jobs) + gh (96 jobs), 3-term bf16 ----
        for (int j = bid; j < 144; j += NB) {
            if (j < 48) {
                int ch = j / 24, nt = j % 24;
                mma_tile<128, 64>(g_ctxh, g_ctxl, 512, g_Wihh, g_Wihl, 512,
                                  g_gip[ch], 3072, nt * 128, ch * 256, 256, smb);
            } else {
                int q = j - 48, ch = q / 24, nt = q % 24;
                mma_tile<128, 64>(g_sh[cur], g_sl[cur], 1024, g_Whhh, g_Whhl, 1024,
                                  g_ghp[ch], 3072, nt * 128, ch * 256, 256, smb);
            }
        }
        gsync();

        // ---- D: V_o/C_o MMA (blocks 0-31) | gate combine (32-147) ----
        if (bid < 32) {
            if (bid < 16) {
                int ch = bid >> 3, nt = bid & 7;
                mma_tile2<128>(g_yEhf, g_yElf, 512, g_Vopf, 512,
                               g_tp[4 + ch], 1024, nt * 128, ch * 256, 256, smb);
            } else {
                int q = bid - 16, ch = q >> 3, nt = q & 7;
                mma_tile2<128>(g_ctxhf, g_ctxlf, 512, g_Copf, 512,
                               g_tp[6 + ch], 1024, nt * 128, ch * 256, 256, smb);
            }
        } else {
            for (size_t i = (size_t)(bid - 32) * NT + tid; i < 64 * 1024; i += (size_t)116 * NT) {
                int b = (int)(i >> 10), h = (int)(i & 1023);
                size_t bs = (size_t)b * 3072;
                float gr = b_ih[h], gz = b_ih[1024 + h], gn = b_ih[2048 + h];
                float hr = b_hh[h], hz = b_hh[1024 + h], hn = b_hh[2048 + h];
#pragma unroll
                for (int p = 0; p < 2; p++) {
                    gr += g_gip[p][bs + h];
                    gz += g_gip[p][bs + 1024 + h];
                    gn += g_gip[p][bs + 2048 + h];
                }
#pragma unroll
                for (int p = 0; p < 4; p++) {
                    hr += g_ghp[p][bs + h];
                    hz += g_ghp[p][bs + 1024 + h];
                    hn += g_ghp[p][bs + 2048 + h];
                }
                float r = 1.f / (1.f + __expf(-(gr + hr)));
                float zz = 1.f / (1.f + __expf(-(gz + hz)));
                float n = tanhf(gn + r * hn);
                float sn = (1.f - zz) * n + zz * g_sf[cur][i];
                g_sf[nxt][i] = sn;
                csplit(sn, g_sh[nxt][i], g_sl[nxt][i]);
                csplitH(sn, g_shf[nxt][i], g_slf[nxt][i]);
            }
        }
        gsync();

        // ---- E: U_o partials (32 jobs) ----
        for (int j = bid; j < 32; j += NB) {
            int ch = j >> 3, nt = j & 7;
            mma_tile2<128>(g_shf[nxt], g_slf[nxt], 1024, g_Uopf, 1024,
                           g_tp[ch], 1024, nt * 128, ch * 256, 256, smb);
        }
        gsync();

        // ---- F: maxout ----
        for (size_t i = gth; i < 64 * 512; i += GS) {
            int b = (int)(i >> 9), d = (int)(i & 511);
            size_t base = (size_t)b * 1024 + 2 * d;
            float t0 = 0.f, t1 = 0.f;
#pragma unroll
            for (int p = 0; p < 8; p++) { t0 += g_tp[p][base]; t1 += g_tp[p][base + 1]; }
            csplitH(fmaxf(t0, t1), g_tmhf[i], g_tmlf[i]);
        }
        gsync();

        // ---- G: logits+exp+Zt (125 jobs) + Wsb t+1 (8 jobs) ----
        for (int j = bid; j < 133; j += NB) {
            if (j < 125) {
                mma_tile_exp(g_tmhf, g_tmlf, g_Wopf, j * 256, smb);
            } else {
                int q = j - 125, ch = q >> 2, nt = q & 3;
                mma_tile<128, 64>(g_sh[nxt], g_sl[nxt], 1024, g_Wph, g_Wpl, 1024,
                                  g_wsbp[ch], 512, nt * 128, ch * 512, 512, smb);
            }
        }
        gsync();

        // ---- I': yE MMA (blocks 0-99) | scale+Z + next energies (100-147) ----
        {
            float* po = out + (size_t)t * 64 * KY;
            if (bid < 100) {
                if (t < 63) {
                    int ch = bid >> 1, nt = bid & 1;
                    mma_tile2<256>(g_evhf, g_evlf, KY, g_Eypf, KY,
                                   g_yep[ch], 512, nt * 256, ch * 640, 640, smb);
                }
            } else {
                for (int b = bid - 100; b < 64; b += 48) {
                    float z = (tid < 125) ? g_Zt[b * 128 + tid] : 0.f;
                    z = block_sum(z, s_red);
                    float inv = 1.f / z;
                    if (tid == 0) g_Zinv[b] = inv;
                    const hf* eh = g_evhf + (size_t)b * KY;
                    const hf* el = g_evlf + (size_t)b * KY;
                    float* pb = po + (size_t)b * KY;
                    for (int k = tid; k < KY; k += NT)
                        pb[k] = (__half2float(eh[k]) + __half2float(el[k])) * inv;
                    __syncthreads();
                }
                if (t < 63)
                    for (int j = bid - 100; j < 256; j += 48) energy_job(j, bvec, v, smf);
            }
        }
        gsync();
    }
}

extern "C" void kernel_launch(void* const* d_in, const int* in_sizes, int n_in,
                              void* d_out, int out_size) {
    const float* x    = (const float*)d_in[0];
    const float* Ey_t = (const float*)d_in[1];
    const float* W    = (const float*)d_in[2];
    const float* U    = (const float*)d_in[3];
    const float* bvec = (const float*)d_in[4];
    const float* v    = (const float*)d_in[5];
    const float* W_ih = (const float*)d_in[6];
    const float* W_hh = (const float*)d_in[7];
    const float* b_ih = (const float*)d_in[8];
    const float* b_hh = (const float*)d_in[9];
    const float* U_o  = (const float*)d_in[10];
    const float* V_o  = (const float*)d_in[11];
    const float* C_o  = (const float*)d_in[12];
    const float* W_o  = (const float*)d_in[13];
    float* out = (float*)d_out;

    cudaFuncSetAttribute(dec_kernel, cudaFuncAttributeMaxDynamicSharedMemorySize, 131072);
    dec_kernel<<<NB, NT, 122880>>>(x, Ey_t, W, U, bvec, v, W_ih, W_hh, b_ih, b_hh,
                                   U_o, V_o, C_o, W_o, out);
}

// round 16
// speedup vs baseline: 3.7663x; 1.0196x over previous
#include <cuda_runtime.h>
#include <cuda_bf16.h>
#include <cuda_fp16.h>
#include <math.h>

#define NB 148
#define NT 512
#define KY 32000
typedef __nv_bfloat16 bf;
typedef __half hf;

// ---------------- device scratch ----------------
__device__ __align__(128) bf g_xh[4096*512], g_xl[4096*512];
__device__ __align__(128) bf g_Wph[512*1024], g_Wpl[512*1024];
__device__ __align__(128) bf g_Uph[512*512], g_Upl[512*512];
__device__ __align__(128) bf g_Wihh[3072*512], g_Wihl[3072*512];
__device__ __align__(128) bf g_Whhh[3072*1024], g_Whhl[3072*1024];
__device__ __align__(128) hf g_Uopf[1024*1024];
__device__ __align__(128) hf g_Vopf[1024*512];
__device__ __align__(128) hf g_Copf[1024*512];
__device__ __align__(128) hf g_Wopf[(size_t)KY*512];
__device__ __align__(128) hf g_Eypf[(size_t)512*KY];
__device__ __align__(128) bf g_sh[2][64*1024], g_sl[2][64*1024];
__device__ __align__(128) hf g_shf[2][64*1024], g_slf[2][64*1024];
__device__ __align__(128) bf g_ctxh[64*512], g_ctxl[64*512];
__device__ __align__(128) hf g_ctxhf[64*512], g_ctxlf[64*512];
__device__ __align__(128) hf g_yEhf[64*512], g_yElf[64*512];
__device__ __align__(128) hf g_tmhf[64*512], g_tmlf[64*512];
__device__ __align__(128) hf g_evhf[(size_t)64*KY], g_evlf[(size_t)64*KY];
__device__ __align__(128) float g_sf[2][64*1024];
__device__ __align__(128) float g_Uh[4096*512];
__device__ __align__(128) float g_wsbp[2][64*512];
__device__ __align__(128) float g_e[64*64];
__device__ __align__(128) float g_gip[2][64*3072];
__device__ __align__(128) float g_ghp[4][64*3072];
__device__ __align__(128) float g_tp[8][64*1024];
__device__ __align__(128) float g_yep[25][64*512];
__device__ __align__(128) float g_Zt[64*128];
__device__ __align__(128) float g_Zinv[64];

// ---------------- grid barrier ----------------
__device__ unsigned g_cnt = 0;
__device__ volatile unsigned g_gen = 0;

__device__ __forceinline__ void gsync() {
    __syncthreads();
    if (threadIdx.x == 0) {
        unsigned gen = g_gen;
        __threadfence();
        if (atomicAdd(&g_cnt, 1u) == NB - 1u) {
            atomicExch(&g_cnt, 0u);
            __threadfence();
            g_gen = gen + 1u;
        } else {
            while (g_gen == gen) __nanosleep(64);
            __threadfence();
        }
    }
    __syncthreads();
}

__device__ __forceinline__ float tanh_fast(float x) {
    float y; asm("tanh.approx.f32 %0, %1;" : "=f"(y) : "f"(x)); return y;
}

// FMA-pipe exp: 2^k * e^r, k = rint(x*log2e), r = x - k*ln2 (|r| <= 0.3466).
__device__ __forceinline__ float fexp(float x) {
    float kf = rintf(x * 1.44269504088896f);
    kf = fmaxf(-120.f, fminf(120.f, kf));
    float r = fmaf(kf, -0.693147180559945f, x);
    float p = 8.3333333e-3f;
    p = fmaf(p, r, 4.1666667e-2f);
    p = fmaf(p, r, 1.6666667e-1f);
    p = fmaf(p, r, 0.5f);
    p = fmaf(p, r, 1.f);
    p = fmaf(p, r, 1.f);
    float s = __int_as_float(((int)kf + 127) << 23);
    return p * s;
}

__device__ __forceinline__ void csplit(float x, bf& h, bf& l) {
    h = __float2bfloat16(x);
    l = __float2bfloat16(x - __bfloat162float(h));
}

__device__ __forceinline__ void csplitH(float x, hf& h, hf& l) {
    h = __float2half_rn(x);
    l = __float2half_rn(x - __half2float(h));
}

__device__ __forceinline__ void cpa16(bf* s, const bf* g) {
    unsigned sa = (unsigned)__cvta_generic_to_shared(s);
    asm volatile("cp.async.cg.shared.global [%0], [%1], 16;" :: "r"(sa), "l"(g));
}

#define MMA(d, a0, a1, a2, a3, b0, b1)                                        \
    asm volatile("mma.sync.aligned.m16n8k16.row.col.f32.bf16.bf16.f32 "       \
                 "{%0,%1,%2,%3}, {%4,%5,%6,%7}, {%8,%9}, {%0,%1,%2,%3};"      \
                 : "+f"(d[0]), "+f"(d[1]), "+f"(d[2]), "+f"(d[3])             \
                 : "r"(a0), "r"(a1), "r"(a2), "r"(a3), "r"(b0), "r"(b1))

#define MMAH(d, a0, a1, a2, a3, b0, b1)                                       \
    asm volatile("mma.sync.aligned.m16n8k16.row.col.f32.f16.f16.f32 "         \
                 "{%0,%1,%2,%3}, {%4,%5,%6,%7}, {%8,%9}, {%0,%1,%2,%3};"      \
                 : "+f"(d[0]), "+f"(d[1]), "+f"(d[2]), "+f"(d[3])             \
                 : "r"(a0), "r"(a1), "r"(a2), "r"(a3), "r"(b0), "r"(b1))

// ------- 3-term bf16 core: 1-deep reg prefetch (FORCEINLINE load-bearing) -------
template<int NTILE, int KS>
__device__ __forceinline__ void mma_core(
    const bf* __restrict__ Ah, const bf* __restrict__ Al, int lda,
    const bf* __restrict__ Bh, const bf* __restrict__ Bl, int ldb,
    int n0, int k0, int kc, bf* __restrict__ sm, float* acc) {
    constexpr int STR  = KS + 8;
    constexpr int CPR  = KS / 8;
    constexpr int APL  = 64 * STR;
    constexpr int BPL  = NTILE * STR;
    constexpr int ASTG = 2 * APL;
    constexpr int BSTG = 2 * BPL;
    constexpr int CA   = KS / 32;
    constexpr int CB   = (NTILE * KS) / 2048;
    constexpr int NJ   = NTILE / 32;
    constexpr int AHALF = 64 * CPR;
    constexpr int BHALF = NTILE * CPR;
    bf* sA = sm;
    bf* sB = sm + 2 * ASTG;
    const int tid = threadIdx.x;
    const int w = tid >> 5, lane = tid & 31;
    const int mr = (w & 3) << 4;
    const int nc = (w >> 2) * (NTILE / 4);
    const int fr = lane >> 2, fc = (lane & 3) << 1;
    const int aoff = (mr + fr) * STR + fc;
    const int boff = (nc + fr) * STR + fc;
#pragma unroll
    for (int i = 0; i < NJ * 4; i++) acc[i] = 0.f;

    uint4 rga[CA], rgb[CB];
    const int ns = kc / KS;

#pragma unroll
    for (int i = 0; i < CA; i++) {
        int p = tid + i * 512, hl = p / AHALF, q = p % AHALF;
        int row = q / CPR, ck = q % CPR;
        rga[i] = *(const uint4*)((hl ? Al : Ah) + (size_t)row * lda + k0 + ck * 8);
    }
#pragma unroll
    for (int i = 0; i < CB; i++) {
        int p = tid + i * 512, hl = p / BHALF, q = p % BHALF;
        int row = q / CPR, ck = q % CPR;
        rgb[i] = *(const uint4*)((hl ? Bl : Bh) + (size_t)(n0 + row) * ldb + k0 + ck * 8);
    }
#pragma unroll
    for (int i = 0; i < CA; i++) {
        int p = tid + i * 512, hl = p / AHALF, q = p % AHALF;
        int row = q / CPR, ck = q % CPR;
        *(uint4*)(sA + hl * APL + row * STR + ck * 8) = rga[i];
    }
#pragma unroll
    for (int i = 0; i < CB; i++) {
        int p = tid + i * 512, hl = p / BHALF, q = p % BHALF;
        int row = q / CPR, ck = q % CPR;
        *(uint4*)(sB + hl * BPL + row * STR + ck * 8) = rgb[i];
    }
    __syncthreads();

    int st = 0;
    for (int s = 0; s < ns; s++) {
        const bool more = s + 1 < ns;
        if (more) {
            const int kk = k0 + (s + 1) * KS;
#pragma unroll
            for (int i = 0; i < CA; i++) {
                int p = tid + i * 512, hl = p / AHALF, q = p % AHALF;
                int row = q / CPR, ck = q % CPR;
                rga[i] = *(const uint4*)((hl ? Al : Ah) + (size_t)row * lda + kk + ck * 8);
            }
#pragma unroll
            for (int i = 0; i < CB; i++) {
                int p = tid + i * 512, hl = p / BHALF, q = p % BHALF;
                int row = q / CPR, ck = q % CPR;
                rgb[i] = *(const uint4*)((hl ? Bl : Bh) + (size_t)(n0 + row) * ldb + kk + ck * 8);
            }
        }
        const bf* sAs = sA + st * ASTG;
        const bf* sBs = sB + st * BSTG;
#pragma unroll
        for (int win = 0; win < KS / 16; win++) {
            const int ko = win << 4;
            const bf* pah = sAs + aoff + ko;
            unsigned ah0 = *(const unsigned*)(pah);
            unsigned ah1 = *(const unsigned*)(pah + 8 * STR);
            unsigned ah2 = *(const unsigned*)(pah + 8);
            unsigned ah3 = *(const unsigned*)(pah + 8 * STR + 8);
            const bf* pal = pah + APL;
            unsigned al0 = *(const unsigned*)(pal);
            unsigned al1 = *(const unsigned*)(pal + 8 * STR);
            unsigned al2 = *(const unsigned*)(pal + 8);
            unsigned al3 = *(const unsigned*)(pal + 8 * STR + 8);
#pragma unroll
            for (int j = 0; j < NJ; j++) {
                const bf* pbh = sBs + boff + ko + j * 8 * STR;
                unsigned bh0 = *(const unsigned*)(pbh);
                unsigned bh1 = *(const unsigned*)(pbh + 8);
                const bf* pbl = pbh + BPL;
                unsigned bl0 = *(const unsigned*)(pbl);
                unsigned bl1 = *(const unsigned*)(pbl + 8);
                float* d = acc + j * 4;
                MMA(d, ah0, ah1, ah2, ah3, bh0, bh1);
                MMA(d, ah0, ah1, ah2, ah3, bl0, bl1);
                MMA(d, al0, al1, al2, al3, bh0, bh1);
            }
        }
        if (more) {
            const int sn = st ^ 1;
            bf* dA = sA + sn * ASTG;
            bf* dB = sB + sn * BSTG;
#pragma unroll
            for (int i = 0; i < CA; i++) {
                int p = tid + i * 512, hl = p / AHALF, q = p % AHALF;
                int row = q / CPR, ck = q % CPR;
                *(uint4*)(dA + hl * APL + row * STR + ck * 8) = rga[i];
            }
#pragma unroll
            for (int i = 0; i < CB; i++) {
                int p = tid + i * 512, hl = p / BHALF, q = p % BHALF;
                int row = q / CPR, ck = q % CPR;
                *(uint4*)(dB + hl * BPL + row * STR + ck * 8) = rgb[i];
            }
        }
        __syncthreads();
        st ^= 1;
    }
}

// ------- 2-term fp16 core: cp.async 4-stage ring, KS=32 -------
template<int NTILE>
__device__ __forceinline__ void mma_core2(
    const bf* __restrict__ Ah, const bf* __restrict__ Al, int lda,
    const bf* __restrict__ Bh, int ldb,
    int n0, int k0, int kc, bf* __restrict__ sm, float* acc) {
    constexpr int STR = 40;
    constexpr int APL = 64 * 40;
    constexpr int AST = 2 * APL;
    constexpr int BST = NTILE * 40;
    constexpr int SST = AST + BST;
    constexpr int NJ  = NTILE / 32;
    const int tid = threadIdx.x;
    const int w = tid >> 5, lane = tid & 31;
    const int mr = (w & 3) << 4;
    const int nc = (w >> 2) * (NTILE / 4);
    const int fr = lane >> 2, fc = (lane & 3) << 1;
    const int aoff = (mr + fr) * STR + fc;
    const int boff = (nc + fr) * STR + fc;
#pragma unroll
    for (int i = 0; i < NJ * 4; i++) acc[i] = 0.f;

    const int ahl  = tid >> 8;
    const int arow = (tid & 255) >> 2;
    const int ack  = tid & 3;
    const bf* Ag = (ahl ? Al : Ah) + (size_t)arow * lda + k0 + ack * 8;
    const unsigned adst = (unsigned)(ahl * APL + arow * STR + ack * 8);

    const int ns = kc >> 5;
#pragma unroll
    for (int s = 0; s < 3; s++) {
        if (s < ns) {
            bf* base = sm + (s & 3) * SST;
            cpa16(base + adst, Ag + s * 32);
#pragma unroll
            for (int i = 0; i < NTILE / 128; i++) {
                int p = tid + i * 512, row = p >> 2, ck = p & 3;
                cpa16(base + AST + row * STR + ck * 8,
                      Bh + (size_t)(n0 + row) * ldb + k0 + s * 32 + ck * 8);
            }
        }
        asm volatile("cp.async.commit_group;" ::: "memory");
    }
    for (int s = 0; s < ns; s++) {
        asm volatile("cp.async.wait_group 2;" ::: "memory");
        __syncthreads();
        if (s + 3 < ns) {
            bf* base = sm + ((s + 3) & 3) * SST;
            cpa16(base + adst, Ag + (s + 3) * 32);
#pragma unroll
            for (int i = 0; i < NTILE / 128; i++) {
                int p = tid + i * 512, row = p >> 2, ck = p & 3;
                cpa16(base + AST + row * STR + ck * 8,
                      Bh + (size_t)(n0 + row) * ldb + k0 + (s + 3) * 32 + ck * 8);
            }
        }
        asm volatile("cp.async.commit_group;" ::: "memory");
        const bf* sAs = sm + (s & 3) * SST;
        const bf* sBs = sAs + AST;
#pragma unroll
        for (int win = 0; win < 2; win++) {
            const int ko = win << 4;
            const bf* pah = sAs + aoff + ko;
            unsigned ah0 = *(const unsigned*)(pah);
            unsigned ah1 = *(const unsigned*)(pah + 8 * STR);
            unsigned ah2 = *(const unsigned*)(pah + 8);
            unsigned ah3 = *(const unsigned*)(pah + 8 * STR + 8);
            const bf* pal = pah + APL;
            unsigned al0 = *(const unsigned*)(pal);
            unsigned al1 = *(const unsigned*)(pal + 8 * STR);
            unsigned al2 = *(const unsigned*)(pal + 8);
            unsigned al3 = *(const unsigned*)(pal + 8 * STR + 8);
#pragma unroll
            for (int j = 0; j < NJ; j++) {
                const bf* pbh = sBs + boff + ko + j * 8 * STR;
                unsigned bh0 = *(const unsigned*)(pbh);
                unsigned bh1 = *(const unsigned*)(pbh + 8);
                float* d = acc + j * 4;
                MMAH(d, ah0, ah1, ah2, ah3, bh0, bh1);
                MMAH(d, al0, al1, al2, al3, bh0, bh1);
            }
        }
    }
    __syncthreads();
}

template<int NTILE, int KS>
__device__ __noinline__ void mma_tile(
    const bf* __restrict__ Ah, const bf* __restrict__ Al, int lda,
    const bf* __restrict__ Bh, const bf* __restrict__ Bl, int ldb,
    float* __restrict__ C, int ldc, int n0, int k0, int kc, bf* sm) {
    float acc[(NTILE / 32) * 4];
    mma_core<NTILE, KS>(Ah, Al, lda, Bh, Bl, ldb, n0, k0, kc, sm, acc);
    const int tid = threadIdx.x;
    const int w = tid >> 5, lane = tid & 31;
    const int mr = (w & 3) << 4;
    const int nc = (w >> 2) * (NTILE / 4);
    const int fr = lane >> 2, fc = (lane & 3) << 1;
#pragma unroll
    for (int j = 0; j < NTILE / 32; j++) {
        int col = n0 + nc + j * 8 + fc;
        float* c0 = C + (size_t)(mr + fr) * ldc + col;
        *(float2*)c0 = make_float2(acc[j*4], acc[j*4+1]);
        *(float2*)(c0 + (size_t)8 * ldc) = make_float2(acc[j*4+2], acc[j*4+3]);
    }
}

template<int NTILE>
__device__ __noinline__ void mma_tile2(
    const hf* __restrict__ Ah, const hf* __restrict__ Al, int lda,
    const hf* __restrict__ Bh, int ldb,
    float* __restrict__ C, int ldc, int n0, int k0, int kc, bf* sm) {
    float acc[(NTILE / 32) * 4];
    mma_core2<NTILE>((const bf*)Ah, (const bf*)Al, lda, (const bf*)Bh, ldb,
                     n0, k0, kc, sm, acc);
    const int tid = threadIdx.x;
    const int w = tid >> 5, lane = tid & 31;
    const int mr = (w & 3) << 4;
    const int nc = (w >> 2) * (NTILE / 4);
    const int fr = lane >> 2, fc = (lane & 3) << 1;
#pragma unroll
    for (int j = 0; j < NTILE / 32; j++) {
        int col = n0 + nc + j * 8 + fc;
        float* c0 = C + (size_t)(mr + fr) * ldc + col;
        *(float2*)c0 = make_float2(acc[j*4], acc[j*4+1]);
        *(float2*)(c0 + (size_t)8 * ldc) = make_float2(acc[j*4+2], acc[j*4+3]);
    }
}

// logits 64x256 tile -> exp (fexp) into g_evhf/evlf + row sums g_Zt
__device__ __noinline__ void mma_tile_exp(
    const hf* __restrict__ Ah, const hf* __restrict__ Al,
    const hf* __restrict__ Bh, int n0, bf* sm) {
    float acc[32];
    mma_core2<256>((const bf*)Ah, (const bf*)Al, 512, (const bf*)Bh, 512,
                   n0, 0, 512, sm, acc);
    const int tid = threadIdx.x;
    const int w = tid >> 5, lane = tid & 31;
    const int mr = (w & 3) << 4, nc = (w >> 2) << 6;
    const int fr = lane >> 2, fc = (lane & 3) << 1;
    float rs0 = 0.f, rs1 = 0.f;
#pragma unroll
    for (int j = 0; j < 8; j++) {
#pragma unroll
        for (int q = 0; q < 2; q++) {
            int col = n0 + nc + j * 8 + fc + q;
            float e0 = fexp(acc[j*4+q]);
            float e1 = fexp(acc[j*4+2+q]);
            rs0 += e0; rs1 += e1;
            size_t i0 = (size_t)(mr + fr) * KY + col;
            size_t i1 = i0 + (size_t)8 * KY;
            csplitH(e0, g_evhf[i0], g_evlf[i0]);
            csplitH(e1, g_evhf[i1], g_evlf[i1]);
        }
    }
    rs0 += __shfl_xor_sync(~0u, rs0, 1); rs0 += __shfl_xor_sync(~0u, rs0, 2);
    rs1 += __shfl_xor_sync(~0u, rs1, 1); rs1 += __shfl_xor_sync(~0u, rs1, 2);
    float* srs = (float*)sm;
    if ((lane & 3) == 0) { srs[w * 16 + fr] = rs0; srs[w * 16 + 8 + fr] = rs1; }
    __syncthreads();
    if (tid < 64) {
        int mg = tid >> 4, rr = tid & 15;
        float z = srs[mg * 16 + rr] + srs[(4 + mg) * 16 + rr] +
                  srs[(8 + mg) * 16 + rr] + srs[(12 + mg) * 16 + rr];
        g_Zt[tid * 128 + (n0 >> 8)] = z;
    }
    __syncthreads();
}

// attention energy job j (b = j>>2, 16 rows of e per job)
__device__ void energy_job(int j, const float* __restrict__ bvec,
                           const float* __restrict__ v, float* smf) {
    int b = j >> 2, jg = j & 3;
    int tid = threadIdx.x, lane = tid & 31;
    __syncthreads();
    smf[tid] = g_wsbp[0][b * 512 + tid] + g_wsbp[1][b * 512 + tid] + bvec[tid];
    smf[512 + tid] = v[tid];
    __syncthreads();
    int jr = jg * 16 + (tid >> 5);
    const float* uh = g_Uh + (size_t)(b * 64 + jr) * 512;
    float acc = 0.f;
    for (int c = lane; c < 512; c += 32)
        acc += tanh_fast(smf[c] + uh[c]) * smf[512 + c];
#pragma unroll
    for (int o = 16; o > 0; o >>= 1) acc += __shfl_down_sync(~0u, acc, o);
    if (lane == 0) g_e[b * 64 + jr] = acc;
}

__device__ __forceinline__ float block_sum(float v, float* red) {
#pragma unroll
    for (int o = 16; o > 0; o >>= 1) v += __shfl_down_sync(0xffffffffu, v, o);
    if ((threadIdx.x & 31) == 0) red[threadIdx.x >> 5] = v;
    __syncthreads();
    float r = 0.f;
#pragma unroll
    for (int i = 0; i < 16; i++) r += red[i];
    __syncthreads();
    return r;
}

__device__ void convN(const float* __restrict__ in, size_t n,
                      bf* __restrict__ oh, bf* __restrict__ ol, size_t gth, size_t gs) {
    for (size_t i = gth; i < n; i += gs) csplit(in[i], oh[i], ol[i]);
}

__device__ void ttconv(const float* __restrict__ in, int R, int Cc,
                       bf* __restrict__ oh, bf* __restrict__ ol, float* sm) {
    int ntr = R >> 5, ntc = Cc >> 5;
    int tx = threadIdx.x & 31, ty = threadIdx.x >> 5;
    for (int tile = blockIdx.x; tile < ntr * ntc; tile += NB) {
        int tr = tile / ntc, tc = tile % ntc;
        int r0 = tr << 5, c0 = tc << 5;
        __syncthreads();
        sm[ty * 33 + tx]        = in[(size_t)(r0 + ty) * Cc + c0 + tx];
        sm[(ty + 16) * 33 + tx] = in[(size_t)(r0 + ty + 16) * Cc + c0 + tx];
        __syncthreads();
        size_t o0 = (size_t)(c0 + ty) * R + r0 + tx;
        size_t o1 = (size_t)(c0 + ty + 16) * R + r0 + tx;
        csplit(sm[tx * 33 + ty], oh[o0], ol[o0]);
        csplit(sm[tx * 33 + ty + 16], oh[o1], ol[o1]);
    }
}

__device__ void ttconvh(const float* __restrict__ in, int R, int Cc,
                        hf* __restrict__ oh, float* sm) {
    int ntr = R >> 5, ntc = Cc >> 5;
    int tx = threadIdx.x & 31, ty = threadIdx.x >> 5;
    for (int tile = blockIdx.x; tile < ntr * ntc; tile += NB) {
        int tr = tile / ntc, tc = tile % ntc;
        int r0 = tr << 5, c0 = tc << 5;
        __syncthreads();
        sm[ty * 33 + tx]        = in[(size_t)(r0 + ty) * Cc + c0 + tx];
        sm[(ty + 16) * 33 + tx] = in[(size_t)(r0 + ty + 16) * Cc + c0 + tx];
        __syncthreads();
        size_t o0 = (size_t)(c0 + ty) * R + r0 + tx;
        size_t o1 = (size_t)(c0 + ty + 16) * R + r0 + tx;
        oh[o0] = __float2half_rn(sm[tx * 33 + ty]);
        oh[o1] = __float2half_rn(sm[tx * 33 + ty + 16]);
    }
}

__global__ __launch_bounds__(NT, 1) void dec_kernel(
    const float* __restrict__ x,    const float* __restrict__ Ey_t,
    const float* __restrict__ W,    const float* __restrict__ U,
    const float* __restrict__ bvec, const float* __restrict__ v,
    const float* __restrict__ W_ih, const float* __restrict__ W_hh,
    const float* __restrict__ b_ih, const float* __restrict__ b_hh,
    const float* __restrict__ U_o,  const float* __restrict__ V_o,
    const float* __restrict__ C_o,  const float* __restrict__ W_o,
    float* __restrict__ out) {
    extern __shared__ __align__(16) char sraw[];
    bf* smb = (bf*)sraw;
    float* smf = (float*)sraw;
    float* s_red = smf + 1024;
    const int tid = threadIdx.x, bid = blockIdx.x;
    const size_t gth = (size_t)bid * NT + tid, GS = (size_t)NB * NT;
    const bf z0 = __float2bfloat16(0.f);
    const hf h0 = __float2half_rn(0.f);

    // ---- prep wave 0 ----
    for (size_t i = gth; i < 64 * 1024; i += GS) {
        g_sf[0][i] = 0.f; g_sh[0][i] = z0; g_sl[0][i] = z0;
        g_shf[0][i] = h0; g_slf[0][i] = h0;
    }
    for (size_t i = gth; i < 64 * 512; i += GS) { g_yEhf[i] = h0; g_yElf[i] = h0; }
    convN(x, (size_t)4096 * 512, g_xh, g_xl, gth, GS);
    convN(W_ih, (size_t)3072 * 512, g_Wihh, g_Wihl, gth, GS);
    convN(W_hh, (size_t)3072 * 1024, g_Whhh, g_Whhl, gth, GS);
    ttconv(W, 1024, 512, g_Wph, g_Wpl, smf);
    ttconv(U, 512, 512, g_Uph, g_Upl, smf);
    ttconvh(U_o, 1024, 1024, g_Uopf, smf);
    ttconvh(V_o, 512, 1024, g_Vopf, smf);
    ttconvh(C_o, 512, 1024, g_Copf, smf);
    ttconvh(W_o, 512, KY, g_Wopf, smf);
    ttconvh(Ey_t, KY, 512, g_Eypf, smf);
    gsync();

    // ---- prep wave 1: U_h (128 jobs) + Wsb(s0) (8 jobs) ----
    for (int j = bid; j < 136; j += NB) {
        if (j < 128) {
            int mt = j >> 1, nt = j & 1;
            mma_tile<256, 32>(g_xh + (size_t)mt * 64 * 512, g_xl + (size_t)mt * 64 * 512, 512,
                              g_Uph, g_Upl, 512,
                              g_Uh + (size_t)mt * 64 * 512, 512, nt * 256, 0, 512, smb);
        } else {
            int q = j - 128, ch = q >> 2, nt = q & 3;
            mma_tile<128, 64>(g_sh[0], g_sl[0], 1024, g_Wph, g_Wpl, 1024,
                              g_wsbp[ch], 512, nt * 128, ch * 512, 512, smb);
        }
    }
    gsync();

    // ---- prep wave 2: energies for t=0 ----
    for (int j = bid; j < 256; j += NB) energy_job(j, bvec, v, smf);
    gsync();

    for (int t = 0; t < 64; t++) {
        const int cur = t & 1, nxt = cur ^ 1;

        // ---- B2: softmax+ctx (bid<64) / yE reduce+scale (bid>=64) ----
        if (bid < 64) {
            int b = bid;
            if (tid < 64) smf[tid] = g_e[b * 64 + tid];
            __syncthreads();
            float mx = -1e30f;
#pragma unroll
            for (int j = 0; j < 64; j++) mx = fmaxf(mx, smf[j]);
            float ex = (tid < 64) ? __expf(smf[tid] - mx) : 0.f;
            __syncthreads();
            if (tid < 64) smf[64 + tid] = ex;
            __syncthreads();
            float Z = 0.f;
#pragma unroll
            for (int j = 0; j < 64; j++) Z += smf[64 + j];
            float inv = 1.f / Z;
            const float* xb = x + (size_t)b * 64 * 512;
            float ca = 0.f;
            for (int j = 0; j < 64; j++) ca += smf[64 + j] * xb[j * 512 + tid];
            float cv = ca * inv;
            csplit(cv, g_ctxh[b * 512 + tid], g_ctxl[b * 512 + tid]);
            csplitH(cv, g_ctxhf[b * 512 + tid], g_ctxlf[b * 512 + tid]);
        } else if (t > 0) {
            for (size_t i = (size_t)(bid - 64) * NT + tid; i < 64 * 512; i += (size_t)84 * NT) {
                int b = (int)(i >> 9);
                float s = 0.f;
#pragma unroll
                for (int p = 0; p < 25; p++) s += g_yep[p][i];
                csplitH(s * g_Zinv[b], g_yEhf[i], g_yElf[i]);
            }
        }
        gsync();

        // ---- C: gi (48 jobs) + gh (96 jobs), 3-term bf16 ----
        for (int j = bid; j < 144; j += NB) {
            if (j < 48) {
                int ch = j / 24, nt = j % 24;
                mma_tile<128, 64>(g_ctxh, g_ctxl, 512, g_Wihh, g_Wihl, 512,
                                  g_gip[ch], 3072, nt * 128, ch * 256, 256, smb);
            } else {
                int q = j - 48, ch = q / 24, nt = q % 24;
                mma_tile<128, 64>(g_sh[cur], g_sl[cur], 1024, g_Whhh, g_Whhl, 1024,
                                  g_ghp[ch], 3072, nt * 128, ch * 256, 256, smb);
            }
        }
        gsync();

        // ---- D: V_o/C_o MMA (blocks 0-31) | gate combine (32-147) ----
        if (bid < 32) {
            if (bid < 16) {
                int ch = bid >> 3, nt = bid & 7;
                mma_tile2<128>(g_yEhf, g_yElf, 512, g_Vopf, 512,
                               g_tp[4 + ch], 1024, nt * 128, ch * 256, 256, smb);
            } else {
                int q = bid - 16, ch = q >> 3, nt = q & 7;
                mma_tile2<128>(g_ctxhf, g_ctxlf, 512, g_Copf, 512,
                               g_tp[6 + ch], 1024, nt * 128, ch * 256, 256, smb);
            }
        } else {
            for (size_t i = (size_t)(bid - 32) * NT + tid; i < 64 * 1024; i += (size_t)116 * NT) {
                int b = (int)(i >> 10), h = (int)(i & 1023);
                size_t bs = (size_t)b * 3072;
                float gr = b_ih[h], gz = b_ih[1024 + h], gn = b_ih[2048 + h];
                float hr = b_hh[h], hz = b_hh[1024 + h], hn = b_hh[2048 + h];
#pragma unroll
                for (int p = 0; p < 2; p++) {
                    gr += g_gip[p][bs + h];
                    gz += g_gip[p][bs + 1024 + h];
                    gn += g_gip[p][bs + 2048 + h];
                }
#pragma unroll
                for (int p = 0; p < 4; p++) {
                    hr += g_ghp[p][bs + h];
                    hz += g_ghp[p][bs + 1024 + h];
                    hn += g_ghp[p][bs + 2048 + h];
                }
                float r = 1.f / (1.f + __expf(-(gr + hr)));
                float zz = 1.f / (1.f + __expf(-(gz + hz)));
                float n = tanhf(gn + r * hn);
                float sn = (1.f - zz) * n + zz * g_sf[cur][i];
                g_sf[nxt][i] = sn;
                csplit(sn, g_sh[nxt][i], g_sl[nxt][i]);
                csplitH(sn, g_shf[nxt][i], g_slf[nxt][i]);
            }
        }
        gsync();

        // ---- E: U_o partials (32 jobs) ----
        for (int j = bid; j < 32; j += NB) {
            int ch = j >> 3, nt = j & 7;
            mma_tile2<128>(g_shf[nxt], g_slf[nxt], 1024, g_Uopf, 1024,
                           g_tp[ch], 1024, nt * 128, ch * 256, 256, smb);
        }
        gsync();

        // ---- F: maxout ----
        for (size_t i = gth; i < 64 * 512; i += GS) {
            int b = (int)(i >> 9), d = (int)(i & 511);
            size_t base = (size_t)b * 1024 + 2 * d;
            float t0 = 0.f, t1 = 0.f;
#pragma unroll
            for (int p = 0; p < 8; p++) { t0 += g_tp[p][base]; t1 += g_tp[p][base + 1]; }
            csplitH(fmaxf(t0, t1), g_tmhf[i], g_tmlf[i]);
        }
        gsync();

        // ---- G: logits+exp+Zt (125 jobs) + Wsb t+1 (8 jobs) ----
        for (int j = bid; j < 133; j += NB) {
            if (j < 125) {
                mma_tile_exp(g_tmhf, g_tmlf, g_Wopf, j * 256, smb);
            } else {
                int q = j - 125, ch = q >> 2, nt = q & 3;
                mma_tile<128, 64>(g_sh[nxt], g_sl[nxt], 1024, g_Wph, g_Wpl, 1024,
                                  g_wsbp[ch], 512, nt * 128, ch * 512, 512, smb);
            }
        }
        gsync();

        // ---- I': yE MMA 50 jobs kc=1280 (blocks 0-49) |
        //      scale+Z + next energies (blocks 50-147, 98 blocks) ----
        {
            float* po = out + (size_t)t * 64 * KY;
            if (bid < 50) {
                if (t < 63) {
                    int ch = bid >> 1, nt = bid & 1;
                    mma_tile2<256>(g_evhf, g_evlf, KY, g_Eypf, KY,
                                   g_yep[ch], 512, nt * 256, ch * 1280, 1280, smb);
                }
            } else {
                for (int b = bid - 50; b < 64; b += 98) {
                    float z = (tid < 125) ? g_Zt[b * 128 + tid] : 0.f;
                    z = block_sum(z, s_red);
                    float inv = 1.f / z;
                    if (tid == 0) g_Zinv[b] = inv;
                    const hf* eh = g_evhf + (size_t)b * KY;
                    const hf* el = g_evlf + (size_t)b * KY;
                    float* pb = po + (size_t)b * KY;
                    for (int k = tid; k < KY; k += NT)
                        pb[k] = (__half2float(eh[k]) + __half2float(el[k])) * inv;
                    __syncthreads();
                }
                if (t < 63)
                    for (int j = bid - 50; j < 256; j += 98) energy_job(j, bvec, v, smf);
            }
        }
        gsync();
    }
}

extern "C" void kernel_launch(void* const* d_in, const int* in_sizes, int n_in,
                              void* d_out, int out_size) {
    const float* x    = (const float*)d_in[0];
    const float* Ey_t = (const float*)d_in[1];
    const float* W    = (const float*)d_in[2];
    const float* U    = (const float*)d_in[3];
    const float* bvec = (const float*)d_in[4];
    const float* v    = (const float*)d_in[5];
    const float* W_ih = (const float*)d_in[6];
    const float* W_hh = (const float*)d_in[7];
    const float* b_ih = (const float*)d_in[8];
    const float* b_hh = (const float*)d_in[9];
    const float* U_o  = (const float*)d_in[10];
    const float* V_o  = (const float*)d_in[11];
    const float* C_o  = (const float*)d_in[12];
    const float* W_o  = (const float*)d_in[13];
    float* out = (float*)d_out;

    cudaFuncSetAttribute(dec_kernel, cudaFuncAttributeMaxDynamicSharedMemorySize, 131072);
    dec_kernel<<<NB, NT, 122880>>>(x, Ey_t, W, U, bvec, v, W_ih, W_hh, b_ih, b_hh,
                                   U_o, V_o, C_o, W_o, out);
}

// round 17
// speedup vs baseline: 4.5720x; 1.2139x over previous
#include <cuda_runtime.h>
#include <cuda_bf16.h>
#include <cuda_fp16.h>
#include <math.h>

#define NB 148
#define NT 512
#define KY 32000
typedef __nv_bfloat16 bf;
typedef __half hf;

// ---------------- device scratch ----------------
__device__ __align__(128) bf g_xh[4096*512], g_xl[4096*512];
__device__ __align__(128) bf g_Wph[512*1024], g_Wpl[512*1024];
__device__ __align__(128) bf g_Uph[512*512], g_Upl[512*512];
__device__ __align__(128) bf g_Wihh[3072*512], g_Wihl[3072*512];
__device__ __align__(128) bf g_Whhh[3072*1024], g_Whhl[3072*1024];
__device__ __align__(128) hf g_Uopf[1024*1024];
__device__ __align__(128) hf g_Vopf[1024*512];
__device__ __align__(128) hf g_Copf[1024*512];
__device__ __align__(128) hf g_Wopf[(size_t)KY*512];
__device__ __align__(128) hf g_Eypf[(size_t)512*KY];
__device__ __align__(128) bf g_sh[2][64*1024], g_sl[2][64*1024];
__device__ __align__(128) hf g_shf[2][64*1024];
__device__ __align__(128) bf g_ctxh[64*512], g_ctxl[64*512];
__device__ __align__(128) hf g_ctxhf[64*512];
__device__ __align__(128) hf g_yEhf[64*512];
__device__ __align__(128) hf g_tmhf[64*512];
__device__ __align__(128) hf g_evhf[(size_t)64*KY], g_evlf[(size_t)64*KY];
__device__ __align__(128) float g_sf[2][64*1024];
__device__ __align__(128) float g_Uh[4096*512];
__device__ __align__(128) float g_wsbp[2][64*512];
__device__ __align__(128) float g_e[64*64];
__device__ __align__(128) float g_gip[2][64*3072];
__device__ __align__(128) float g_ghp[4][64*3072];
__device__ __align__(128) float g_tp[8][64*1024];
__device__ __align__(128) float g_yep[25][64*512];
__device__ __align__(128) float g_Zt[64*128];
__device__ __align__(128) float g_Zinv[64];

// ---------------- grid barrier ----------------
__device__ unsigned g_cnt = 0;
__device__ volatile unsigned g_gen = 0;

__device__ __forceinline__ void gsync() {
    __syncthreads();
    if (threadIdx.x == 0) {
        unsigned gen = g_gen;
        __threadfence();
        if (atomicAdd(&g_cnt, 1u) == NB - 1u) {
            atomicExch(&g_cnt, 0u);
            __threadfence();
            g_gen = gen + 1u;
        } else {
            while (g_gen == gen) __nanosleep(64);
            __threadfence();
        }
    }
    __syncthreads();
}

__device__ __forceinline__ float tanh_fast(float x) {
    float y; asm("tanh.approx.f32 %0, %1;" : "=f"(y) : "f"(x)); return y;
}

// FMA-pipe exp: 2^k * e^r (|r| <= 0.3466), degree-5 Taylor. Zero MUFU.
__device__ __forceinline__ float fexp(float x) {
    float kf = rintf(x * 1.44269504088896f);
    kf = fmaxf(-120.f, fminf(120.f, kf));
    float r = fmaf(kf, -0.693147180559945f, x);
    float p = 8.3333333e-3f;
    p = fmaf(p, r, 4.1666667e-2f);
    p = fmaf(p, r, 1.6666667e-1f);
    p = fmaf(p, r, 0.5f);
    p = fmaf(p, r, 1.f);
    p = fmaf(p, r, 1.f);
    float s = __int_as_float(((int)kf + 127) << 23);
    return p * s;
}

__device__ __forceinline__ void csplit(float x, bf& h, bf& l) {
    h = __float2bfloat16(x);
    l = __float2bfloat16(x - __bfloat162float(h));
}

__device__ __forceinline__ void csplitH(float x, hf& h, hf& l) {
    h = __float2half_rn(x);
    l = __float2half_rn(x - __half2float(h));
}

__device__ __forceinline__ void cpa16(bf* s, const bf* g) {
    unsigned sa = (unsigned)__cvta_generic_to_shared(s);
    asm volatile("cp.async.cg.shared.global [%0], [%1], 16;" :: "r"(sa), "l"(g));
}

#define MMA(d, a0, a1, a2, a3, b0, b1)                                        \
    asm volatile("mma.sync.aligned.m16n8k16.row.col.f32.bf16.bf16.f32 "       \
                 "{%0,%1,%2,%3}, {%4,%5,%6,%7}, {%8,%9}, {%0,%1,%2,%3};"      \
                 : "+f"(d[0]), "+f"(d[1]), "+f"(d[2]), "+f"(d[3])             \
                 : "r"(a0), "r"(a1), "r"(a2), "r"(a3), "r"(b0), "r"(b1))

#define MMAH(d, a0, a1, a2, a3, b0, b1)                                       \
    asm volatile("mma.sync.aligned.m16n8k16.row.col.f32.f16.f16.f32 "         \
                 "{%0,%1,%2,%3}, {%4,%5,%6,%7}, {%8,%9}, {%0,%1,%2,%3};"      \
                 : "+f"(d[0]), "+f"(d[1]), "+f"(d[2]), "+f"(d[3])             \
                 : "r"(a0), "r"(a1), "r"(a2), "r"(a3), "r"(b0), "r"(b1))

// ------- 3-term bf16 core: 1-deep reg prefetch (FORCEINLINE load-bearing) -------
template<int NTILE, int KS>
__device__ __forceinline__ void mma_core(
    const bf* __restrict__ Ah, const bf* __restrict__ Al, int lda,
    const bf* __restrict__ Bh, const bf* __restrict__ Bl, int ldb,
    int n0, int k0, int kc, bf* __restrict__ sm, float* acc) {
    constexpr int STR  = KS + 8;
    constexpr int CPR  = KS / 8;
    constexpr int APL  = 64 * STR;
    constexpr int BPL  = NTILE * STR;
    constexpr int ASTG = 2 * APL;
    constexpr int BSTG = 2 * BPL;
    constexpr int CA   = KS / 32;
    constexpr int CB   = (NTILE * KS) / 2048;
    constexpr int NJ   = NTILE / 32;
    constexpr int AHALF = 64 * CPR;
    constexpr int BHALF = NTILE * CPR;
    bf* sA = sm;
    bf* sB = sm + 2 * ASTG;
    const int tid = threadIdx.x;
    const int w = tid >> 5, lane = tid & 31;
    const int mr = (w & 3) << 4;
    const int nc = (w >> 2) * (NTILE / 4);
    const int fr = lane >> 2, fc = (lane & 3) << 1;
    const int aoff = (mr + fr) * STR + fc;
    const int boff = (nc + fr) * STR + fc;
#pragma unroll
    for (int i = 0; i < NJ * 4; i++) acc[i] = 0.f;

    uint4 rga[CA], rgb[CB];
    const int ns = kc / KS;

#pragma unroll
    for (int i = 0; i < CA; i++) {
        int p = tid + i * 512, hl = p / AHALF, q = p % AHALF;
        int row = q / CPR, ck = q % CPR;
        rga[i] = *(const uint4*)((hl ? Al : Ah) + (size_t)row * lda + k0 + ck * 8);
    }
#pragma unroll
    for (int i = 0; i < CB; i++) {
        int p = tid + i * 512, hl = p / BHALF, q = p % BHALF;
        int row = q / CPR, ck = q % CPR;
        rgb[i] = *(const uint4*)((hl ? Bl : Bh) + (size_t)(n0 + row) * ldb + k0 + ck * 8);
    }
#pragma unroll
    for (int i = 0; i < CA; i++) {
        int p = tid + i * 512, hl = p / AHALF, q = p % AHALF;
        int row = q / CPR, ck = q % CPR;
        *(uint4*)(sA + hl * APL + row * STR + ck * 8) = rga[i];
    }
#pragma unroll
    for (int i = 0; i < CB; i++) {
        int p = tid + i * 512, hl = p / BHALF, q = p % BHALF;
        int row = q / CPR, ck = q % CPR;
        *(uint4*)(sB + hl * BPL + row * STR + ck * 8) = rgb[i];
    }
    __syncthreads();

    int st = 0;
    for (int s = 0; s < ns; s++) {
        const bool more = s + 1 < ns;
        if (more) {
            const int kk = k0 + (s + 1) * KS;
#pragma unroll
            for (int i = 0; i < CA; i++) {
                int p = tid + i * 512, hl = p / AHALF, q = p % AHALF;
                int row = q / CPR, ck = q % CPR;
                rga[i] = *(const uint4*)((hl ? Al : Ah) + (size_t)row * lda + kk + ck * 8);
            }
#pragma unroll
            for (int i = 0; i < CB; i++) {
                int p = tid + i * 512, hl = p / BHALF, q = p % BHALF;
                int row = q / CPR, ck = q % CPR;
                rgb[i] = *(const uint4*)((hl ? Bl : Bh) + (size_t)(n0 + row) * ldb + kk + ck * 8);
            }
        }
        const bf* sAs = sA + st * ASTG;
        const bf* sBs = sB + st * BSTG;
#pragma unroll
        for (int win = 0; win < KS / 16; win++) {
            const int ko = win << 4;
            const bf* pah = sAs + aoff + ko;
            unsigned ah0 = *(const unsigned*)(pah);
            unsigned ah1 = *(const unsigned*)(pah + 8 * STR);
            unsigned ah2 = *(const unsigned*)(pah + 8);
            unsigned ah3 = *(const unsigned*)(pah + 8 * STR + 8);
            const bf* pal = pah + APL;
            unsigned al0 = *(const unsigned*)(pal);
            unsigned al1 = *(const unsigned*)(pal + 8 * STR);
            unsigned al2 = *(const unsigned*)(pal + 8);
            unsigned al3 = *(const unsigned*)(pal + 8 * STR + 8);
#pragma unroll
            for (int j = 0; j < NJ; j++) {
                const bf* pbh = sBs + boff + ko + j * 8 * STR;
                unsigned bh0 = *(const unsigned*)(pbh);
                unsigned bh1 = *(const unsigned*)(pbh + 8);
                const bf* pbl = pbh + BPL;
                unsigned bl0 = *(const unsigned*)(pbl);
                unsigned bl1 = *(const unsigned*)(pbl + 8);
                float* d = acc + j * 4;
                MMA(d, ah0, ah1, ah2, ah3, bh0, bh1);
                MMA(d, ah0, ah1, ah2, ah3, bl0, bl1);
                MMA(d, al0, al1, al2, al3, bh0, bh1);
            }
        }
        if (more) {
            const int sn = st ^ 1;
            bf* dA = sA + sn * ASTG;
            bf* dB = sB + sn * BSTG;
#pragma unroll
            for (int i = 0; i < CA; i++) {
                int p = tid + i * 512, hl = p / AHALF, q = p % AHALF;
                int row = q / CPR, ck = q % CPR;
                *(uint4*)(dA + hl * APL + row * STR + ck * 8) = rga[i];
            }
#pragma unroll
            for (int i = 0; i < CB; i++) {
                int p = tid + i * 512, hl = p / BHALF, q = p % BHALF;
                int row = q / CPR, ck = q % CPR;
                *(uint4*)(dB + hl * BPL + row * STR + ck * 8) = rgb[i];
            }
        }
        __syncthreads();
        st ^= 1;
    }
}

// ------- 1-term fp16 core (Ah x Bh): cp.async 4-stage ring, KS=32 -------
// A single fp16 plane (threads 0-255 load), B single plane.
template<int NTILE>
__device__ __forceinline__ void mma_core1(
    const bf* __restrict__ Ah, int lda,
    const bf* __restrict__ Bh, int ldb,
    int n0, int k0, int kc, bf* __restrict__ sm, float* acc) {
    constexpr int STR = 40;
    constexpr int APL = 64 * 40;        // 2560 el (single plane)
    constexpr int BST = NTILE * 40;
    constexpr int SST = APL + BST;
    constexpr int NJ  = NTILE / 32;
    const int tid = threadIdx.x;
    const int w = tid >> 5, lane = tid & 31;
    const int mr = (w & 3) << 4;
    const int nc = (w >> 2) * (NTILE / 4);
    const int fr = lane >> 2, fc = (lane & 3) << 1;
    const int aoff = (mr + fr) * STR + fc;
    const int boff = (nc + fr) * STR + fc;
#pragma unroll
    for (int i = 0; i < NJ * 4; i++) acc[i] = 0.f;

    const int arow = tid >> 2;          // threads 0-255: A chunk
    const int ack  = tid & 3;
    const bool doA = tid < 256;
    const bf* Ag = Ah + (size_t)arow * lda + k0 + ack * 8;
    const unsigned adst = (unsigned)(arow * STR + ack * 8);

    const int ns = kc >> 5;
#pragma unroll
    for (int s = 0; s < 3; s++) {
        if (s < ns) {
            bf* base = sm + (s & 3) * SST;
            if (doA) cpa16(base + adst, Ag + s * 32);
#pragma unroll
            for (int i = 0; i < NTILE / 128; i++) {
                int p = tid + i * 512, row = p >> 2, ck = p & 3;
                cpa16(base + APL + row * STR + ck * 8,
                      Bh + (size_t)(n0 + row) * ldb + k0 + s * 32 + ck * 8);
            }
        }
        asm volatile("cp.async.commit_group;" ::: "memory");
    }
    for (int s = 0; s < ns; s++) {
        asm volatile("cp.async.wait_group 2;" ::: "memory");
        __syncthreads();
        if (s + 3 < ns) {
            bf* base = sm + ((s + 3) & 3) * SST;
            if (doA) cpa16(base + adst, Ag + (s + 3) * 32);
#pragma unroll
            for (int i = 0; i < NTILE / 128; i++) {
                int p = tid + i * 512, row = p >> 2, ck = p & 3;
                cpa16(base + APL + row * STR + ck * 8,
                      Bh + (size_t)(n0 + row) * ldb + k0 + (s + 3) * 32 + ck * 8);
            }
        }
        asm volatile("cp.async.commit_group;" ::: "memory");
        const bf* sAs = sm + (s & 3) * SST;
        const bf* sBs = sAs + APL;
#pragma unroll
        for (int win = 0; win < 2; win++) {
            const int ko = win << 4;
            const bf* pah = sAs + aoff + ko;
            unsigned ah0 = *(const unsigned*)(pah);
            unsigned ah1 = *(const unsigned*)(pah + 8 * STR);
            unsigned ah2 = *(const unsigned*)(pah + 8);
            unsigned ah3 = *(const unsigned*)(pah + 8 * STR + 8);
#pragma unroll
            for (int j = 0; j < NJ; j++) {
                const bf* pbh = sBs + boff + ko + j * 8 * STR;
                unsigned bh0 = *(const unsigned*)(pbh);
                unsigned bh1 = *(const unsigned*)(pbh + 8);
                MMAH((acc + j * 4), ah0, ah1, ah2, ah3, bh0, bh1);
            }
        }
    }
    __syncthreads();
}

template<int NTILE, int KS>
__device__ __noinline__ void mma_tile(
    const bf* __restrict__ Ah, const bf* __restrict__ Al, int lda,
    const bf* __restrict__ Bh, const bf* __restrict__ Bl, int ldb,
    float* __restrict__ C, int ldc, int n0, int k0, int kc, bf* sm) {
    float acc[(NTILE / 32) * 4];
    mma_core<NTILE, KS>(Ah, Al, lda, Bh, Bl, ldb, n0, k0, kc, sm, acc);
    const int tid = threadIdx.x;
    const int w = tid >> 5, lane = tid & 31;
    const int mr = (w & 3) << 4;
    const int nc = (w >> 2) * (NTILE / 4);
    const int fr = lane >> 2, fc = (lane & 3) << 1;
#pragma unroll
    for (int j = 0; j < NTILE / 32; j++) {
        int col = n0 + nc + j * 8 + fc;
        float* c0 = C + (size_t)(mr + fr) * ldc + col;
        *(float2*)c0 = make_float2(acc[j*4], acc[j*4+1]);
        *(float2*)(c0 + (size_t)8 * ldc) = make_float2(acc[j*4+2], acc[j*4+3]);
    }
}

template<int NTILE>
__device__ __noinline__ void mma_tile1(
    const hf* __restrict__ Ah, int lda,
    const hf* __restrict__ Bh, int ldb,
    float* __restrict__ C, int ldc, int n0, int k0, int kc, bf* sm) {
    float acc[(NTILE / 32) * 4];
    mma_core1<NTILE>((const bf*)Ah, lda, (const bf*)Bh, ldb, n0, k0, kc, sm, acc);
    const int tid = threadIdx.x;
    const int w = tid >> 5, lane = tid & 31;
    const int mr = (w & 3) << 4;
    const int nc = (w >> 2) * (NTILE / 4);
    const int fr = lane >> 2, fc = (lane & 3) << 1;
#pragma unroll
    for (int j = 0; j < NTILE / 32; j++) {
        int col = n0 + nc + j * 8 + fc;
        float* c0 = C + (size_t)(mr + fr) * ldc + col;
        *(float2*)c0 = make_float2(acc[j*4], acc[j*4+1]);
        *(float2*)(c0 + (size_t)8 * ldc) = make_float2(acc[j*4+2], acc[j*4+3]);
    }
}

// logits 64x256 tile (1-term fp16) -> exp (fexp) into evhf/evlf + row sums g_Zt
__device__ __noinline__ void mma_tile_exp(
    const hf* __restrict__ Ah, const hf* __restrict__ Bh, int n0, bf* sm) {
    float acc[32];
    mma_core1<256>((const bf*)Ah, 512, (const bf*)Bh, 512, n0, 0, 512, sm, acc);
    const int tid = threadIdx.x;
    const int w = tid >> 5, lane = tid & 31;
    const int mr = (w & 3) << 4, nc = (w >> 2) << 6;
    const int fr = lane >> 2, fc = (lane & 3) << 1;
    float rs0 = 0.f, rs1 = 0.f;
#pragma unroll
    for (int j = 0; j < 8; j++) {
#pragma unroll
        for (int q = 0; q < 2; q++) {
            int col = n0 + nc + j * 8 + fc + q;
            float e0 = fexp(acc[j*4+q]);
            float e1 = fexp(acc[j*4+2+q]);
            rs0 += e0; rs1 += e1;
            size_t i0 = (size_t)(mr + fr) * KY + col;
            size_t i1 = i0 + (size_t)8 * KY;
            csplitH(e0, g_evhf[i0], g_evlf[i0]);
            csplitH(e1, g_evhf[i1], g_evlf[i1]);
        }
    }
    rs0 += __shfl_xor_sync(~0u, rs0, 1); rs0 += __shfl_xor_sync(~0u, rs0, 2);
    rs1 += __shfl_xor_sync(~0u, rs1, 1); rs1 += __shfl_xor_sync(~0u, rs1, 2);
    float* srs = (float*)sm;
    if ((lane & 3) == 0) { srs[w * 16 + fr] = rs0; srs[w * 16 + 8 + fr] = rs1; }
    __syncthreads();
    if (tid < 64) {
        int mg = tid >> 4, rr = tid & 15;
        float z = srs[mg * 16 + rr] + srs[(4 + mg) * 16 + rr] +
                  srs[(8 + mg) * 16 + rr] + srs[(12 + mg) * 16 + rr];
        g_Zt[tid * 128 + (n0 >> 8)] = z;
    }
    __syncthreads();
}

// attention energy job j (b = j>>2, 16 rows of e per job)
__device__ void energy_job(int j, const float* __restrict__ bvec,
                           const float* __restrict__ v, float* smf) {
    int b = j >> 2, jg = j & 3;
    int tid = threadIdx.x, lane = tid & 31;
    __syncthreads();
    smf[tid] = g_wsbp[0][b * 512 + tid] + g_wsbp[1][b * 512 + tid] + bvec[tid];
    smf[512 + tid] = v[tid];
    __syncthreads();
    int jr = jg * 16 + (tid >> 5);
    const float* uh = g_Uh + (size_t)(b * 64 + jr) * 512;
    float acc = 0.f;
    for (int c = lane; c < 512; c += 32)
        acc += tanh_fast(smf[c] + uh[c]) * smf[512 + c];
#pragma unroll
    for (int o = 16; o > 0; o >>= 1) acc += __shfl_down_sync(~0u, acc, o);
    if (lane == 0) g_e[b * 64 + jr] = acc;
}

__device__ __forceinline__ float block_sum(float v, float* red) {
#pragma unroll
    for (int o = 16; o > 0; o >>= 1) v += __shfl_down_sync(0xffffffffu, v, o);
    if ((threadIdx.x & 31) == 0) red[threadIdx.x >> 5] = v;
    __syncthreads();
    float r = 0.f;
#pragma unroll
    for (int i = 0; i < 16; i++) r += red[i];
    __syncthreads();
    return r;
}

__device__ void convN(const float* __restrict__ in, size_t n,
                      bf* __restrict__ oh, bf* __restrict__ ol, size_t gth, size_t gs) {
    for (size_t i = gth; i < n; i += gs) csplit(in[i], oh[i], ol[i]);
}

__device__ void ttconv(const float* __restrict__ in, int R, int Cc,
                       bf* __restrict__ oh, bf* __restrict__ ol, float* sm) {
    int ntr = R >> 5, ntc = Cc >> 5;
    int tx = threadIdx.x & 31, ty = threadIdx.x >> 5;
    for (int tile = blockIdx.x; tile < ntr * ntc; tile += NB) {
        int tr = tile / ntc, tc = tile % ntc;
        int r0 = tr << 5, c0 = tc << 5;
        __syncthreads();
        sm[ty * 33 + tx]        = in[(size_t)(r0 + ty) * Cc + c0 + tx];
        sm[(ty + 16) * 33 + tx] = in[(size_t)(r0 + ty + 16) * Cc + c0 + tx];
        __syncthreads();
        size_t o0 = (size_t)(c0 + ty) * R + r0 + tx;
        size_t o1 = (size_t)(c0 + ty + 16) * R + r0 + tx;
        csplit(sm[tx * 33 + ty], oh[o0], ol[o0]);
        csplit(sm[tx * 33 + ty + 16], oh[o1], ol[o1]);
    }
}

__device__ void ttconvh(const float* __restrict__ in, int R, int Cc,
                        hf* __restrict__ oh, float* sm) {
    int ntr = R >> 5, ntc = Cc >> 5;
    int tx = threadIdx.x & 31, ty = threadIdx.x >> 5;
    for (int tile = blockIdx.x; tile < ntr * ntc; tile += NB) {
        int tr = tile / ntc, tc = tile % ntc;
        int r0 = tr << 5, c0 = tc << 5;
        __syncthreads();
        sm[ty * 33 + tx]        = in[(size_t)(r0 + ty) * Cc + c0 + tx];
        sm[(ty + 16) * 33 + tx] = in[(size_t)(r0 + ty + 16) * Cc + c0 + tx];
        __syncthreads();
        size_t o0 = (size_t)(c0 + ty) * R + r0 + tx;
        size_t o1 = (size_t)(c0 + ty + 16) * R + r0 + tx;
        oh[o0] = __float2half_rn(sm[tx * 33 + ty]);
        oh[o1] = __float2half_rn(sm[tx * 33 + ty + 16]);
    }
}

__global__ __launch_bounds__(NT, 1) void dec_kernel(
    const float* __restrict__ x,    const float* __restrict__ Ey_t,
    const float* __restrict__ W,    const float* __restrict__ U,
    const float* __restrict__ bvec, const float* __restrict__ v,
    const float* __restrict__ W_ih, const float* __restrict__ W_hh,
    const float* __restrict__ b_ih, const float* __restrict__ b_hh,
    const float* __restrict__ U_o,  const float* __restrict__ V_o,
    const float* __restrict__ C_o,  const float* __restrict__ W_o,
    float* __restrict__ out) {
    extern __shared__ __align__(16) char sraw[];
    bf* smb = (bf*)sraw;
    float* smf = (float*)sraw;
    float* s_red = smf + 1024;
    const int tid = threadIdx.x, bid = blockIdx.x;
    const size_t gth = (size_t)bid * NT + tid, GS = (size_t)NB * NT;
    const bf z0 = __float2bfloat16(0.f);
    const hf h0 = __float2half_rn(0.f);

    // ---- prep wave 0 ----
    for (size_t i = gth; i < 64 * 1024; i += GS) {
        g_sf[0][i] = 0.f; g_sh[0][i] = z0; g_sl[0][i] = z0;
        g_shf[0][i] = h0;
    }
    for (size_t i = gth; i < 64 * 512; i += GS) g_yEhf[i] = h0;
    convN(x, (size_t)4096 * 512, g_xh, g_xl, gth, GS);
    convN(W_ih, (size_t)3072 * 512, g_Wihh, g_Wihl, gth, GS);
    convN(W_hh, (size_t)3072 * 1024, g_Whhh, g_Whhl, gth, GS);
    ttconv(W, 1024, 512, g_Wph, g_Wpl, smf);
    ttconv(U, 512, 512, g_Uph, g_Upl, smf);
    ttconvh(U_o, 1024, 1024, g_Uopf, smf);
    ttconvh(V_o, 512, 1024, g_Vopf, smf);
    ttconvh(C_o, 512, 1024, g_Copf, smf);
    ttconvh(W_o, 512, KY, g_Wopf, smf);
    ttconvh(Ey_t, KY, 512, g_Eypf, smf);
    gsync();

    // ---- prep wave 1: U_h (128 jobs) + Wsb(s0) (8 jobs) ----
    for (int j = bid; j < 136; j += NB) {
        if (j < 128) {
            int mt = j >> 1, nt = j & 1;
            mma_tile<256, 32>(g_xh + (size_t)mt * 64 * 512, g_xl + (size_t)mt * 64 * 512, 512,
                              g_Uph, g_Upl, 512,
                              g_Uh + (size_t)mt * 64 * 512, 512, nt * 256, 0, 512, smb);
        } else {
            int q = j - 128, ch = q >> 2, nt = q & 3;
            mma_tile<128, 64>(g_sh[0], g_sl[0], 1024, g_Wph, g_Wpl, 1024,
                              g_wsbp[ch], 512, nt * 128, ch * 512, 512, smb);
        }
    }
    gsync();

    // ---- prep wave 2: energies for t=0 ----
    for (int j = bid; j < 256; j += NB) energy_job(j, bvec, v, smf);
    gsync();

    for (int t = 0; t < 64; t++) {
        const int cur = t & 1, nxt = cur ^ 1;

        // ---- B2: softmax+ctx (bid<64) / yE reduce+scale (bid>=64) ----
        if (bid < 64) {
            int b = bid;
            if (tid < 64) smf[tid] = g_e[b * 64 + tid];
            __syncthreads();
            float mx = -1e30f;
#pragma unroll
            for (int j = 0; j < 64; j++) mx = fmaxf(mx, smf[j]);
            float ex = (tid < 64) ? __expf(smf[tid] - mx) : 0.f;
            __syncthreads();
            if (tid < 64) smf[64 + tid] = ex;
            __syncthreads();
            float Z = 0.f;
#pragma unroll
            for (int j = 0; j < 64; j++) Z += smf[64 + j];
            float inv = 1.f / Z;
            const float* xb = x + (size_t)b * 64 * 512;
            float ca = 0.f;
            for (int j = 0; j < 64; j++) ca += smf[64 + j] * xb[j * 512 + tid];
            float cv = ca * inv;
            csplit(cv, g_ctxh[b * 512 + tid], g_ctxl[b * 512 + tid]);
            g_ctxhf[b * 512 + tid] = __float2half_rn(cv);
        } else if (t > 0) {
            for (size_t i = (size_t)(bid - 64) * NT + tid; i < 64 * 512; i += (size_t)84 * NT) {
                int b = (int)(i >> 9);
                float s = 0.f;
#pragma unroll
                for (int p = 0; p < 25; p++) s += g_yep[p][i];
                g_yEhf[i] = __float2half_rn(s * g_Zinv[b]);
            }
        }
        gsync();

        // ---- C: gi (48 jobs) + gh (96 jobs), 3-term bf16 ----
        for (int j = bid; j < 144; j += NB) {
            if (j < 48) {
                int ch = j / 24, nt = j % 24;
                mma_tile<128, 64>(g_ctxh, g_ctxl, 512, g_Wihh, g_Wihl, 512,
                                  g_gip[ch], 3072, nt * 128, ch * 256, 256, smb);
            } else {
                int q = j - 48, ch = q / 24, nt = q % 24;
                mma_tile<128, 64>(g_sh[cur], g_sl[cur], 1024, g_Whhh, g_Whhl, 1024,
                                  g_ghp[ch], 3072, nt * 128, ch * 256, 256, smb);
            }
        }
        gsync();

        // ---- D: V_o/C_o MMA (blocks 0-31, 1-term fp16) | gate combine (32-147) ----
        if (bid < 32) {
            if (bid < 16) {
                int ch = bid >> 3, nt = bid & 7;
                mma_tile1<128>(g_yEhf, 512, g_Vopf, 512,
                               g_tp[4 + ch], 1024, nt * 128, ch * 256, 256, smb);
            } else {
                int q = bid - 16, ch = q >> 3, nt = q & 7;
                mma_tile1<128>(g_ctxhf, 512, g_Copf, 512,
                               g_tp[6 + ch], 1024, nt * 128, ch * 256, 256, smb);
            }
        } else {
            for (size_t i = (size_t)(bid - 32) * NT + tid; i < 64 * 1024; i += (size_t)116 * NT) {
                int b = (int)(i >> 10), h = (int)(i & 1023);
                size_t bs = (size_t)b * 3072;
                float gr = b_ih[h], gz = b_ih[1024 + h], gn = b_ih[2048 + h];
                float hr = b_hh[h], hz = b_hh[1024 + h], hn = b_hh[2048 + h];
#pragma unroll
                for (int p = 0; p < 2; p++) {
                    gr += g_gip[p][bs + h];
                    gz += g_gip[p][bs + 1024 + h];
                    gn += g_gip[p][bs + 2048 + h];
                }
#pragma unroll
                for (int p = 0; p < 4; p++) {
                    hr += g_ghp[p][bs + h];
                    hz += g_ghp[p][bs + 1024 + h];
                    hn += g_ghp[p][bs + 2048 + h];
                }
                float r = 1.f / (1.f + __expf(-(gr + hr)));
                float zz = 1.f / (1.f + __expf(-(gz + hz)));
                float n = tanhf(gn + r * hn);
                float sn = (1.f - zz) * n + zz * g_sf[cur][i];
                g_sf[nxt][i] = sn;
                csplit(sn, g_sh[nxt][i], g_sl[nxt][i]);
                g_shf[nxt][i] = __float2half_rn(sn);
            }
        }
        gsync();

        // ---- E: U_o partials (32 jobs, 1-term fp16) ----
        for (int j = bid; j < 32; j += NB) {
            int ch = j >> 3, nt = j & 7;
            mma_tile1<128>(g_shf[nxt], 1024, g_Uopf, 1024,
                           g_tp[ch], 1024, nt * 128, ch * 256, 256, smb);
        }
        gsync();

        // ---- F: maxout ----
        for (size_t i = gth; i < 64 * 512; i += GS) {
            int b = (int)(i >> 9), d = (int)(i & 511);
            size_t base = (size_t)b * 1024 + 2 * d;
            float t0 = 0.f, t1 = 0.f;
#pragma unroll
            for (int p = 0; p < 8; p++) { t0 += g_tp[p][base]; t1 += g_tp[p][base + 1]; }
            g_tmhf[i] = __float2half_rn(fmaxf(t0, t1));
        }
        gsync();

        // ---- G: logits+exp+Zt (125 jobs, 1-term fp16) + Wsb t+1 (8 jobs) ----
        for (int j = bid; j < 133; j += NB) {
            if (j < 125) {
                mma_tile_exp(g_tmhf, g_Wopf, j * 256, smb);
            } else {
                int q = j - 125, ch = q >> 2, nt = q & 3;
                mma_tile<128, 64>(g_sh[nxt], g_sl[nxt], 1024, g_Wph, g_Wpl, 1024,
                                  g_wsbp[ch], 512, nt * 128, ch * 512, 512, smb);
            }
        }
        gsync();

        // ---- I': yE MMA 50 jobs kc=1280 (blocks 0-49, 1-term) |
        //      scale+Z + next energies (blocks 50-147) ----
        {
            float* po = out + (size_t)t * 64 * KY;
            if (bid < 50) {
                if (t < 63) {
                    int ch = bid >> 1, nt = bid & 1;
                    mma_tile1<256>(g_evhf, KY, g_Eypf, KY,
                                   g_yep[ch], 512, nt * 256, ch * 1280, 1280, smb);
                }
            } else {
                for (int b = bid - 50; b < 64; b += 98) {
                    float z = (tid < 125) ? g_Zt[b * 128 + tid] : 0.f;
                    z = block_sum(z, s_red);
                    float inv = 1.f / z;
                    if (tid == 0) g_Zinv[b] = inv;
                    const hf* eh = g_evhf + (size_t)b * KY;
                    const hf* el = g_evlf + (size_t)b * KY;
                    float* pb = po + (size_t)b * KY;
                    for (int k = tid; k < KY; k += NT)
                        pb[k] = (__half2float(eh[k]) + __half2float(el[k])) * inv;
                    __syncthreads();
                }
                if (t < 63)
                    for (int j = bid - 50; j < 256; j += 98) energy_job(j, bvec, v, smf);
            }
        }
        gsync();
    }
}

extern "C" void kernel_launch(void* const* d_in, const int* in_sizes, int n_in,
                              void* d_out, int out_size) {
    const float* x    = (const float*)d_in[0];
    const float* Ey_t = (const float*)d_in[1];
    const float* W    = (const float*)d_in[2];
    const float* U    = (const float*)d_in[3];
    const float* bvec = (const float*)d_in[4];
    const float* v    = (const float*)d_in[5];
    const float* W_ih = (const float*)d_in[6];
    const float* W_hh = (const float*)d_in[7];
    const float* b_ih = (const float*)d_in[8];
    const float* b_hh = (const float*)d_in[9];
    const float* U_o  = (const float*)d_in[10];
    const float* V_o  = (const float*)d_in[11];
    const float* C_o  = (const float*)d_in[12];
    const float* W_o  = (const float*)d_in[13];
    float* out = (float*)d_out;

    // arena: max(3-term KS=64: 110592B, 1-term ring NTILE=256: 4*25600 = 102400B)
    cudaFuncSetAttribute(dec_kernel, cudaFuncAttributeMaxDynamicSharedMemorySize, 114688);
    dec_kernel<<<NB, NT, 110592>>>(x, Ey_t, W, U, bvec, v, W_ih, W_hh, b_ih, b_hh,
                                   U_o, V_o, C_o, W_o, out);
}